// round 3
// baseline (speedup 1.0000x reference)
#include <cuda_runtime.h>
#include <cuda_bf16.h>
#include <cstdint>

// ============================================================================
// KTMutualAttention — fp32 implementation
//   B=8, T=512, S=1024, TL=64, D=1024, H=16, hd=64
// Stages:
//   1) 5 projection GEMMs (A @ W^T + b, optional *0.125)
//   2) weights kernel: masked-mean of target mutual attention (algebraically
//      collapsed to tq . (mask @ tk) / sum(mask))
//   3) fused flash attention with per-key-column weight scaling
//   4) output projection GEMM into d_out
// ============================================================================

#define B_   8
#define T_   512
#define S_   1024
#define TL_  64
#define D_   1024
#define H_   16
#define HD_  64
#define SCALING_ 0.125f

// ---------------------------------------------------------------------------
// scratch (device globals; no allocations allowed)
// ---------------------------------------------------------------------------
__device__ float g_q  [B_ * T_ * D_];    // 16 MB
__device__ float g_k  [B_ * S_ * D_];    // 32 MB
__device__ float g_v  [B_ * S_ * D_];    // 32 MB
__device__ float g_tq [B_ * S_ * D_];    // 32 MB
__device__ float g_tk [B_ * TL_ * D_];   //  2 MB
__device__ float g_w  [B_ * H_ * S_];    // 0.5 MB
__device__ float g_ctx[B_ * T_ * D_];    // 16 MB

// ---------------------------------------------------------------------------
// SGEMM: C[M,N] = scale * (A[M,K] @ W[N,K]^T + bias[N])
// 128x128 tile, BK=8, 256 threads, 8x8 microtile. M,N mult of 128, K mult of 8.
// ---------------------------------------------------------------------------
__global__ __launch_bounds__(256, 2)
void sgemm_bias_kernel(const float* __restrict__ A, const float* __restrict__ W,
                       const float* __restrict__ bias, float* __restrict__ C,
                       int M, int N, int K, float scale)
{
    __shared__ float As[8][128];
    __shared__ float Bs[8][128];

    const int tid = threadIdx.x;
    const int bm = blockIdx.y * 128;
    const int bn = blockIdx.x * 128;

    const int lr = tid >> 1;          // 0..127
    const int lk = (tid & 1) << 2;    // 0 or 4

    const float* Ap = A + (size_t)(bm + lr) * K + lk;
    const float* Wp = W + (size_t)(bn + lr) * K + lk;

    const int ty = tid >> 4;   // 0..15
    const int tx = tid & 15;   // 0..15

    float acc[8][8];
#pragma unroll
    for (int i = 0; i < 8; i++)
#pragma unroll
        for (int j = 0; j < 8; j++) acc[i][j] = 0.f;

    float4 a4 = *reinterpret_cast<const float4*>(Ap);
    float4 b4 = *reinterpret_cast<const float4*>(Wp);

    for (int k0 = 0; k0 < K; k0 += 8) {
        As[lk + 0][lr] = a4.x; As[lk + 1][lr] = a4.y;
        As[lk + 2][lr] = a4.z; As[lk + 3][lr] = a4.w;
        Bs[lk + 0][lr] = b4.x; Bs[lk + 1][lr] = b4.y;
        Bs[lk + 2][lr] = b4.z; Bs[lk + 3][lr] = b4.w;
        __syncthreads();

        if (k0 + 8 < K) {
            a4 = *reinterpret_cast<const float4*>(Ap + k0 + 8);
            b4 = *reinterpret_cast<const float4*>(Wp + k0 + 8);
        }

#pragma unroll
        for (int kk = 0; kk < 8; kk++) {
            float4 af0 = *reinterpret_cast<const float4*>(&As[kk][ty * 8]);
            float4 af1 = *reinterpret_cast<const float4*>(&As[kk][ty * 8 + 4]);
            float4 bf0 = *reinterpret_cast<const float4*>(&Bs[kk][tx * 8]);
            float4 bf1 = *reinterpret_cast<const float4*>(&Bs[kk][tx * 8 + 4]);
            float a[8] = {af0.x, af0.y, af0.z, af0.w, af1.x, af1.y, af1.z, af1.w};
            float b[8] = {bf0.x, bf0.y, bf0.z, bf0.w, bf1.x, bf1.y, bf1.z, bf1.w};
#pragma unroll
            for (int i = 0; i < 8; i++)
#pragma unroll
                for (int j = 0; j < 8; j++)
                    acc[i][j] = fmaf(a[i], b[j], acc[i][j]);
        }
        __syncthreads();
    }

    float bb[8];
#pragma unroll
    for (int j = 0; j < 8; j++) bb[j] = bias[bn + tx * 8 + j];

#pragma unroll
    for (int i = 0; i < 8; i++) {
        const int row = bm + ty * 8 + i;
        float* Cp = C + (size_t)row * N + bn + tx * 8;
        float4 o0, o1;
        o0.x = scale * (acc[i][0] + bb[0]);
        o0.y = scale * (acc[i][1] + bb[1]);
        o0.z = scale * (acc[i][2] + bb[2]);
        o0.w = scale * (acc[i][3] + bb[3]);
        o1.x = scale * (acc[i][4] + bb[4]);
        o1.y = scale * (acc[i][5] + bb[5]);
        o1.z = scale * (acc[i][6] + bb[6]);
        o1.w = scale * (acc[i][7] + bb[7]);
        *reinterpret_cast<float4*>(Cp)     = o0;
        *reinterpret_cast<float4*>(Cp + 4) = o1;
    }
}

// ---------------------------------------------------------------------------
// weights[b,h,s] = (tq[b,s,h*64:] . sum_t(mask[b,s,t]*tk[b,t,h*64:])) / sum_t mask
// grid = B*H blocks of 256 threads (8 warps); one warp per s, strided.
// ---------------------------------------------------------------------------
__global__ __launch_bounds__(256)
void weights_kernel(const float* __restrict__ tq, const float* __restrict__ tk,
                    const float* __restrict__ mask, float* __restrict__ wgt)
{
    const int bh = blockIdx.x;
    const int b = bh >> 4;
    const int h = bh & 15;

    __shared__ float tks[TL_][HD_];   // [t][d]

    const int tid = threadIdx.x;
    for (int idx = tid; idx < TL_ * HD_; idx += 256) {
        const int t = idx >> 6, d = idx & 63;
        tks[t][d] = tk[((size_t)b * TL_ + t) * D_ + h * HD_ + d];
    }
    __syncthreads();

    const int warp = tid >> 5, lane = tid & 31;

    for (int s = warp; s < S_; s += 8) {
        const size_t tqo = ((size_t)b * S_ + s) * D_ + h * HD_;
        const float tq0 = __ldg(&tq[tqo + lane]);
        const float tq1 = __ldg(&tq[tqo + lane + 32]);
        const float* mrow = mask + ((size_t)b * S_ + s) * TL_;

        float mk0 = 0.f, mk1 = 0.f, cnt = 0.f;
#pragma unroll
        for (int t = 0; t < TL_; t++) {
            const float m = __ldg(&mrow[t]);   // broadcast across warp
            cnt += m;
            mk0 = fmaf(m, tks[t][lane], mk0);
            mk1 = fmaf(m, tks[t][lane + 32], mk1);
        }
        float dotv = tq0 * mk0 + tq1 * mk1;
#pragma unroll
        for (int off = 16; off; off >>= 1)
            dotv += __shfl_xor_sync(0xffffffffu, dotv, off);

        if (lane == 0)
            wgt[(size_t)bh * S_ + s] = dotv / cnt;
    }
}

// ---------------------------------------------------------------------------
// fast exp on the FMA pipe (no MUFU). Accurate ~1e-8 rel for x <= 0.
// ---------------------------------------------------------------------------
__device__ __forceinline__ float fast_exp(float x)
{
    const float y = x * 1.44269504088896341f;
    const float n = rintf(y);
    const float t = (y - n) * 0.69314718055994531f;
    float p = 1.9841269841e-4f;            // 1/5040
    p = fmaf(p, t, 1.38888888889e-3f);     // 1/720
    p = fmaf(p, t, 8.33333333333e-3f);     // 1/120
    p = fmaf(p, t, 4.16666666667e-2f);     // 1/24
    p = fmaf(p, t, 1.66666666667e-1f);     // 1/6
    p = fmaf(p, t, 0.5f);
    p = fmaf(p, t, 1.0f);
    p = fmaf(p, t, 1.0f);
    int e = (int)n;                        // saturates on huge-negative
    e = e < -126 ? -126 : e;
    const float s = __int_as_float((e + 127) << 23);
    return p * s;
}

// ---------------------------------------------------------------------------
// Fused attention: per (b,h,q-tile of 64 rows)
//   S = q @ k^T  (contraction hd=64), scaled per key column by weights[b,h,s],
//   online softmax over S=1024, O = P @ v, written to ctx[b,t,h*64+d].
// grid = (T/64, B*H), 256 threads. Dynamic smem (4 tiles of 64x68 + 64).
// ---------------------------------------------------------------------------
#define APAD 68
#define ATT_SMEM_FLOATS (4 * 64 * APAD + 64)

__global__ __launch_bounds__(256)
void attn_kernel(const float* __restrict__ q, const float* __restrict__ k,
                 const float* __restrict__ v, const float* __restrict__ wgt,
                 float* __restrict__ ctx)
{
    extern __shared__ float smem[];
    float* qT = smem;                  // [d][r]  64 x APAD
    float* kT = qT + 64 * APAD;        // [d][c]
    float* vs = kT + 64 * APAD;        // [s][d]
    float* ps = vs + 64 * APAD;        // [r][c]
    float* ws = ps + 64 * APAD;        // [64]

    const int qt = blockIdx.x;
    const int bh = blockIdx.y;
    const int b = bh >> 4;
    const int h = bh & 15;

    const int tid = threadIdx.x;
    const int ty = tid >> 4;     // q-row group
    const int tx = tid & 15;     // col group

    // load q tile transposed
    const size_t qbase = ((size_t)b * T_ + qt * 64) * D_ + h * HD_;
    for (int idx = tid; idx < 64 * 64; idx += 256) {
        const int r = idx >> 6, d = idx & 63;
        qT[d * APAD + r] = q[qbase + (size_t)r * D_ + d];
    }

    float o[4][4];
    float m_i[4], l_i[4];
#pragma unroll
    for (int i = 0; i < 4; i++) {
        m_i[i] = -1e30f;
        l_i[i] = 0.f;
#pragma unroll
        for (int j = 0; j < 4; j++) o[i][j] = 0.f;
    }

    const size_t kvbase = ((size_t)b * S_) * D_ + h * HD_;
    const float* wrow = wgt + (size_t)bh * S_;

    for (int sc = 0; sc < S_ / 64; sc++) {
        __syncthreads();   // previous chunk's P@V done; q tile visible on sc==0
        const size_t koff = kvbase + (size_t)sc * 64 * D_;
        for (int idx = tid; idx < 64 * 64; idx += 256) {
            const int c = idx >> 6, d = idx & 63;
            kT[d * APAD + c] = k[koff + (size_t)c * D_ + d];
            vs[c * APAD + d] = v[koff + (size_t)c * D_ + d];
        }
        if (tid < 64) ws[tid] = wrow[sc * 64 + tid];
        __syncthreads();

        // ---- scores: s[i][j] = sum_d q[r_i][d] * k[c_j][d]
        float sv[4][4];
#pragma unroll
        for (int i = 0; i < 4; i++)
#pragma unroll
            for (int j = 0; j < 4; j++) sv[i][j] = 0.f;

#pragma unroll 16
        for (int d = 0; d < 64; d++) {
            const float4 a4 = *reinterpret_cast<const float4*>(&qT[d * APAD + ty * 4]);
            const float4 b4 = *reinterpret_cast<const float4*>(&kT[d * APAD + tx * 4]);
            const float a[4] = {a4.x, a4.y, a4.z, a4.w};
            const float bb[4] = {b4.x, b4.y, b4.z, b4.w};
#pragma unroll
            for (int i = 0; i < 4; i++)
#pragma unroll
                for (int j = 0; j < 4; j++)
                    sv[i][j] = fmaf(a[i], bb[j], sv[i][j]);
        }

        // per-key-column weight scaling
        const float w0 = ws[tx * 4 + 0], w1 = ws[tx * 4 + 1];
        const float w2 = ws[tx * 4 + 2], w3 = ws[tx * 4 + 3];
#pragma unroll
        for (int i = 0; i < 4; i++) {
            sv[i][0] *= w0; sv[i][1] *= w1; sv[i][2] *= w2; sv[i][3] *= w3;
        }

        // ---- online softmax stats (reduce over the 16 tx lanes of each row)
        float rm[4], rs[4], alpha[4];
#pragma unroll
        for (int i = 0; i < 4; i++) {
            float mx = fmaxf(fmaxf(sv[i][0], sv[i][1]), fmaxf(sv[i][2], sv[i][3]));
#pragma unroll
            for (int off = 1; off < 16; off <<= 1)
                mx = fmaxf(mx, __shfl_xor_sync(0xffffffffu, mx, off));
            rm[i] = mx;
        }
#pragma unroll
        for (int i = 0; i < 4; i++) {
            const float m_new = fmaxf(m_i[i], rm[i]);
            alpha[i] = fast_exp(m_i[i] - m_new);
            m_i[i] = m_new;
            float r = 0.f;
#pragma unroll
            for (int j = 0; j < 4; j++) {
                sv[i][j] = fast_exp(sv[i][j] - m_new);
                r += sv[i][j];
            }
            rs[i] = r;
        }
#pragma unroll
        for (int i = 0; i < 4; i++) {
#pragma unroll
            for (int off = 1; off < 16; off <<= 1)
                rs[i] += __shfl_xor_sync(0xffffffffu, rs[i], off);
            l_i[i] = l_i[i] * alpha[i] + rs[i];
#pragma unroll
            for (int j = 0; j < 4; j++) o[i][j] *= alpha[i];
        }

        // ---- write P tile (row-major, float4 per row-fragment)
#pragma unroll
        for (int i = 0; i < 4; i++) {
            float4 pv = make_float4(sv[i][0], sv[i][1], sv[i][2], sv[i][3]);
            *reinterpret_cast<float4*>(&ps[(ty * 4 + i) * APAD + tx * 4]) = pv;
        }
        __syncthreads();

        // ---- O += P @ V  (contraction over s within chunk)
#pragma unroll 16
        for (int ss = 0; ss < 64; ss++) {
            const float4 vv = *reinterpret_cast<const float4*>(&vs[ss * APAD + tx * 4]);
            const float vb[4] = {vv.x, vv.y, vv.z, vv.w};
            float pa[4];
#pragma unroll
            for (int i = 0; i < 4; i++) pa[i] = ps[(ty * 4 + i) * APAD + ss];
#pragma unroll
            for (int i = 0; i < 4; i++)
#pragma unroll
                for (int j = 0; j < 4; j++)
                    o[i][j] = fmaf(pa[i], vb[j], o[i][j]);
        }
    }

    // ---- epilogue: ctx[b, t, h*64+d] = o / l
#pragma unroll
    for (int i = 0; i < 4; i++) {
        const float inv = 1.0f / l_i[i];
        const int row = qt * 64 + ty * 4 + i;
        float4 ov = make_float4(o[i][0] * inv, o[i][1] * inv,
                                o[i][2] * inv, o[i][3] * inv);
        *reinterpret_cast<float4*>(
            &ctx[((size_t)b * T_ + row) * D_ + h * HD_ + tx * 4]) = ov;
    }
}

// ---------------------------------------------------------------------------
// launch
// ---------------------------------------------------------------------------
extern "C" void kernel_launch(void* const* d_in, const int* in_sizes, int n_in,
                              void* d_out, int out_size)
{
    const float* hidden = (const float*)d_in[0];
    const float* kv     = (const float*)d_in[1];
    const float* target = (const float*)d_in[2];
    const float* mask   = (const float*)d_in[3];
    const float* Wq  = (const float*)d_in[4];
    const float* bq  = (const float*)d_in[5];
    const float* Wk  = (const float*)d_in[6];
    const float* bk  = (const float*)d_in[7];
    const float* Wv  = (const float*)d_in[8];
    const float* bv  = (const float*)d_in[9];
    const float* Wwq = (const float*)d_in[10];
    const float* bwq = (const float*)d_in[11];
    const float* Wwk = (const float*)d_in[12];
    const float* bwk = (const float*)d_in[13];
    const float* Wo  = (const float*)d_in[14];
    const float* bo  = (const float*)d_in[15];
    float* out = (float*)d_out;

    float *q, *k, *v, *tq, *tk, *w, *ctx;
    cudaGetSymbolAddress((void**)&q,   g_q);
    cudaGetSymbolAddress((void**)&k,   g_k);
    cudaGetSymbolAddress((void**)&v,   g_v);
    cudaGetSymbolAddress((void**)&tq,  g_tq);
    cudaGetSymbolAddress((void**)&tk,  g_tk);
    cudaGetSymbolAddress((void**)&w,   g_w);
    cudaGetSymbolAddress((void**)&ctx, g_ctx);

    const dim3 blk(256);

    // projections (C = scale*(A @ W^T + b))
    sgemm_bias_kernel<<<dim3(D_ / 128, (B_ * T_) / 128), blk>>>(
        hidden, Wq, bq, q, B_ * T_, D_, D_, SCALING_);
    sgemm_bias_kernel<<<dim3(D_ / 128, (B_ * S_) / 128), blk>>>(
        kv, Wk, bk, k, B_ * S_, D_, D_, 1.0f);
    sgemm_bias_kernel<<<dim3(D_ / 128, (B_ * S_) / 128), blk>>>(
        kv, Wv, bv, v, B_ * S_, D_, D_, 1.0f);
    sgemm_bias_kernel<<<dim3(D_ / 128, (B_ * S_) / 128), blk>>>(
        kv, Wwq, bwq, tq, B_ * S_, D_, D_, SCALING_);
    sgemm_bias_kernel<<<dim3(D_ / 128, (B_ * TL_) / 128), blk>>>(
        target, Wwk, bwk, tk, B_ * TL_, D_, D_, 1.0f);

    // masked-mean weights
    weights_kernel<<<B_ * H_, 256>>>(tq, tk, mask, w);

    // fused attention
    const int att_smem = ATT_SMEM_FLOATS * (int)sizeof(float);
    cudaFuncSetAttribute(attn_kernel,
                         cudaFuncAttributeMaxDynamicSharedMemorySize, att_smem);
    attn_kernel<<<dim3(T_ / 64, B_ * H_), 256, att_smem>>>(q, k, v, w, ctx);

    // output projection
    sgemm_bias_kernel<<<dim3(D_ / 128, (B_ * T_) / 128), blk>>>(
        ctx, Wo, bo, out, B_ * T_, D_, D_, 1.0f);
}

// round 6
// speedup vs baseline: 1.4173x; 1.4173x over previous
#include <cuda_runtime.h>
#include <cuda_bf16.h>
#include <cstdint>

// ============================================================================
// KTMutualAttention — mma.sync (bf16) 3-term split GEMMs + fused fp32 attn
//   B=8, T=512, S=1024, TL=64, D=1024, H=16, hd=64
// GEMMs: x = hi + lo (bf16 each). Single GEMM over K'=3072 computes
//   hi*hi + hi*lo + lo*hi  (A segments: hi,hi,lo ; W segments: hi,lo,hi)
// dropping only lo*lo (~2^-18 rel). Buffers stay [hi|lo] 2048-wide; the
// loader remaps segments per chunk.
// ============================================================================

#define B_   8
#define T_   512
#define S_   1024
#define TL_  64
#define D_   1024
#define H_   16
#define HD_  64
#define SCALING_ 0.125f
#define K2_  2048          // stored split width ([hi|lo])

// ---------------------------------------------------------------------------
// scratch (device globals; no allocations allowed)
// ---------------------------------------------------------------------------
__device__ __align__(256) float g_q  [B_ * T_ * D_];
__device__ __align__(256) float g_k  [B_ * S_ * D_];
__device__ __align__(256) float g_v  [B_ * S_ * D_];
__device__ __align__(256) float g_tq [B_ * S_ * D_];
__device__ __align__(256) float g_tk [B_ * TL_ * D_];
__device__ __align__(256) float g_w  [B_ * H_ * S_];
__device__ __align__(256) float g_ctx[B_ * T_ * D_];

// bf16 split operands  [rows, 2048] = [hi(1024) | lo(1024)]
__device__ __align__(256) __nv_bfloat16 g_hA  [(size_t)B_ * T_  * K2_];
__device__ __align__(256) __nv_bfloat16 g_kvA [(size_t)B_ * S_  * K2_];
__device__ __align__(256) __nv_bfloat16 g_tA  [(size_t)B_ * TL_ * K2_];
__device__ __align__(256) __nv_bfloat16 g_ctxA[(size_t)B_ * T_  * K2_];
__device__ __align__(256) __nv_bfloat16 g_Wq2 [(size_t)D_ * K2_];
__device__ __align__(256) __nv_bfloat16 g_Wk2 [(size_t)D_ * K2_];
__device__ __align__(256) __nv_bfloat16 g_Wv2 [(size_t)D_ * K2_];
__device__ __align__(256) __nv_bfloat16 g_Wwq2[(size_t)D_ * K2_];
__device__ __align__(256) __nv_bfloat16 g_Wwk2[(size_t)D_ * K2_];
__device__ __align__(256) __nv_bfloat16 g_Wo2 [(size_t)D_ * K2_];

// ---------------------------------------------------------------------------
// PTX helpers (all portable: sm_80+)
// ---------------------------------------------------------------------------
__device__ __forceinline__ uint32_t smem_u32(const void* p) {
    uint32_t a;
    asm("{ .reg .u64 t; cvta.to.shared.u64 t, %1; cvt.u32.u64 %0, t; }"
        : "=r"(a) : "l"(p));
    return a;
}

#define CP_ASYNC16(dst_u32, src_ptr) \
    asm volatile("cp.async.cg.shared.global [%0], [%1], 16;" \
                 :: "r"(dst_u32), "l"(src_ptr) : "memory")
#define CP_COMMIT() asm volatile("cp.async.commit_group;" ::: "memory")
#define CP_WAIT1()  asm volatile("cp.async.wait_group 1;" ::: "memory")
#define CP_WAIT0()  asm volatile("cp.async.wait_group 0;" ::: "memory")

__device__ __forceinline__ void ldmatrix_x4(uint32_t& r0, uint32_t& r1,
                                            uint32_t& r2, uint32_t& r3,
                                            uint32_t addr)
{
    asm volatile("ldmatrix.sync.aligned.m8n8.x4.shared.b16 {%0,%1,%2,%3}, [%4];"
                 : "=r"(r0), "=r"(r1), "=r"(r2), "=r"(r3) : "r"(addr));
}

__device__ __forceinline__ void mma_bf16(float* c, uint32_t a0, uint32_t a1,
                                         uint32_t a2, uint32_t a3,
                                         uint32_t b0, uint32_t b1)
{
    asm volatile(
        "mma.sync.aligned.m16n8k16.row.col.f32.bf16.bf16.f32 "
        "{%0,%1,%2,%3}, {%4,%5,%6,%7}, {%8,%9}, {%0,%1,%2,%3};"
        : "+f"(c[0]), "+f"(c[1]), "+f"(c[2]), "+f"(c[3])
        : "r"(a0), "r"(a1), "r"(a2), "r"(a3), "r"(b0), "r"(b1));
}

// ---------------------------------------------------------------------------
// fp32 -> bf16 hi|lo split:  y[row, 0:1024]=hi, y[row, 1024:2048]=lo
// ---------------------------------------------------------------------------
__global__ __launch_bounds__(256)
void split_kernel(const float* __restrict__ x, __nv_bfloat16* __restrict__ y)
{
    const int idx = blockIdx.x * 256 + threadIdx.x;
    const int row = idx >> 8;
    const int c4  = (idx & 255) * 4;
    const float4 v = *reinterpret_cast<const float4*>(x + ((size_t)row << 10) + c4);

    __nv_bfloat16 hx = __float2bfloat16_rn(v.x);
    __nv_bfloat16 hy = __float2bfloat16_rn(v.y);
    __nv_bfloat16 hz = __float2bfloat16_rn(v.z);
    __nv_bfloat16 hw = __float2bfloat16_rn(v.w);
    __nv_bfloat16 lx = __float2bfloat16_rn(v.x - __bfloat162float(hx));
    __nv_bfloat16 ly = __float2bfloat16_rn(v.y - __bfloat162float(hy));
    __nv_bfloat16 lz = __float2bfloat16_rn(v.z - __bfloat162float(hz));
    __nv_bfloat16 lw = __float2bfloat16_rn(v.w - __bfloat162float(hw));

    __nv_bfloat162* dh = reinterpret_cast<__nv_bfloat162*>(
        y + (size_t)row * K2_ + c4);
    dh[0] = __nv_bfloat162(hx, hy);
    dh[1] = __nv_bfloat162(hz, hw);
    __nv_bfloat162* dl = reinterpret_cast<__nv_bfloat162*>(
        y + (size_t)row * K2_ + 1024 + c4);
    dl[0] = __nv_bfloat162(lx, ly);
    dl[1] = __nv_bfloat162(lz, lw);
}

// ---------------------------------------------------------------------------
// mma.sync GEMM: C[M,1024] = scale * ((Ahi+Alo)@(Whi+Wlo)^T + bias), 3-term
//   CTA 128x128, 256 thr, warps 4(M)x2(N) -> 32x64 warp tile.
//   BK=32 chunks over virtual K'=3072: chunk c -> A seg {hi,hi,lo}[c/32],
//   W seg {hi,lo,hi}[c/32], column (c%32)*32 within the 1024-wide segment.
// grid = (8, M/128)
// ---------------------------------------------------------------------------
#define BK 32
#define SROW 40                 // padded row stride (bf16 elems): 80 bytes
#define N_CHUNK 96              // 3 segments x 32 chunks

__global__ __launch_bounds__(256, 2)
void mma_gemm_kernel(const __nv_bfloat16* __restrict__ A,
                     const __nv_bfloat16* __restrict__ W,
                     const float* __restrict__ bias,
                     float* __restrict__ C, float scale)
{
    __shared__ __nv_bfloat16 sA[2][128 * SROW];
    __shared__ __nv_bfloat16 sB[2][128 * SROW];
    __shared__ float biasS[128];

    const int tid = threadIdx.x;
    const int wid = tid >> 5, lane = tid & 31;
    const int wm = wid & 3;          // 0..3  (M)
    const int wn = wid >> 2;         // 0..1  (N)
    const int bm = blockIdx.y * 128;
    const int bn = blockIdx.x * 128;

    if (tid < 128) biasS[tid] = bias[bn + tid];

    const __nv_bfloat16* Ag = A + (size_t)bm * K2_;
    const __nv_bfloat16* Wg = W + (size_t)bn * K2_;

    // staging: thread -> (row = tid>>1, 32 bytes at element offset (tid&1)*16)
    const int ldrow = tid >> 1;
    const int ldoff = (tid & 1) * 16;

    const uint32_t sA0 = smem_u32(sA[0]);
    const uint32_t sA1 = smem_u32(sA[1]);
    const uint32_t sB0 = smem_u32(sB[0]);
    const uint32_t sB1 = smem_u32(sB[1]);

    // 3-term segment maps (byte-free, element offsets into the 2048 width)
    auto stage = [&](int c, int buf) {
        const int seg = c >> 5;                 // 0,1,2
        const int col = (c & 31) * BK;          // 0..992
        const int gA = ((seg == 2) ? 1024 : 0) + col;   // A: hi,hi,lo
        const int gW = ((seg == 1) ? 1024 : 0) + col;   // W: hi,lo,hi
        const size_t ga = (size_t)ldrow * K2_ + gA + ldoff;
        const size_t gw = (size_t)ldrow * K2_ + gW + ldoff;
        const uint32_t sa = (buf ? sA1 : sA0) + ldrow * (SROW * 2) + ldoff * 2;
        const uint32_t sb = (buf ? sB1 : sB0) + ldrow * (SROW * 2) + ldoff * 2;
        CP_ASYNC16(sa,      Ag + ga);
        CP_ASYNC16(sa + 16, Ag + ga + 8);
        CP_ASYNC16(sb,      Wg + gw);
        CP_ASYNC16(sb + 16, Wg + gw + 8);
    };

    float acc[2][8][4];
#pragma unroll
    for (int mt = 0; mt < 2; mt++)
#pragma unroll
        for (int nf = 0; nf < 8; nf++)
#pragma unroll
            for (int r = 0; r < 4; r++) acc[mt][nf][r] = 0.f;

    stage(0, 0);
    CP_COMMIT();

    // ldmatrix lane addressing: row = (lane&15), col-bytes = (lane>>4)*16
    const int lrow = lane & 15;
    const int lcol = (lane >> 4) * 16;           // bytes

    for (int c = 0; c < N_CHUNK; ++c) {
        const int buf = c & 1;
        if (c + 1 < N_CHUNK) {
            stage(c + 1, buf ^ 1);
            CP_COMMIT();
            CP_WAIT1();
        } else {
            CP_WAIT0();
        }
        __syncthreads();

        const uint32_t aBase = (buf ? sA1 : sA0);
        const uint32_t bBase = (buf ? sB1 : sB0);

#pragma unroll
        for (int kk = 0; kk < 2; kk++) {          // two k16 steps
            const int kbyte = kk * 32 + lcol;

            uint32_t a[2][4];
#pragma unroll
            for (int mt = 0; mt < 2; mt++) {
                const int row = wm * 32 + mt * 16 + lrow;
                ldmatrix_x4(a[mt][0], a[mt][1], a[mt][2], a[mt][3],
                            aBase + row * (SROW * 2) + kbyte);
            }
            uint32_t b[4][4];
#pragma unroll
            for (int nb = 0; nb < 4; nb++) {
                const int row = wn * 64 + nb * 16 + lrow;
                ldmatrix_x4(b[nb][0], b[nb][1], b[nb][2], b[nb][3],
                            bBase + row * (SROW * 2) + kbyte);
            }
#pragma unroll
            for (int mt = 0; mt < 2; mt++)
#pragma unroll
                for (int nf = 0; nf < 8; nf++) {
                    const int nb = nf >> 1;
                    const uint32_t b0 = (nf & 1) ? b[nb][1] : b[nb][0];
                    const uint32_t b1 = (nf & 1) ? b[nb][3] : b[nb][2];
                    mma_bf16(acc[mt][nf], a[mt][0], a[mt][1], a[mt][2], a[mt][3],
                             b0, b1);
                }
        }
        __syncthreads();
    }

    // epilogue
    const int g_  = lane >> 2;
    const int tig = lane & 3;
#pragma unroll
    for (int mt = 0; mt < 2; mt++) {
        const int row0 = bm + wm * 32 + mt * 16 + g_;
#pragma unroll
        for (int nf = 0; nf < 8; nf++) {
            const int col = wn * 64 + nf * 8 + tig * 2;
            const float b0 = biasS[col], b1 = biasS[col + 1];
            float2 o0, o1;
            o0.x = scale * (acc[mt][nf][0] + b0);
            o0.y = scale * (acc[mt][nf][1] + b1);
            o1.x = scale * (acc[mt][nf][2] + b0);
            o1.y = scale * (acc[mt][nf][3] + b1);
            *reinterpret_cast<float2*>(C + (size_t)row0 * 1024 + bn + col) = o0;
            *reinterpret_cast<float2*>(C + (size_t)(row0 + 8) * 1024 + bn + col) = o1;
        }
    }
}

// ---------------------------------------------------------------------------
// weights[b,h,s] = (tq . (mask @ tk)) / sum(mask)
// ---------------------------------------------------------------------------
__global__ __launch_bounds__(256)
void weights_kernel(const float* __restrict__ tq, const float* __restrict__ tk,
                    const float* __restrict__ mask, float* __restrict__ wgt)
{
    const int bh = blockIdx.x;
    const int b = bh >> 4;
    const int h = bh & 15;

    __shared__ float tks[TL_][HD_];

    const int tid = threadIdx.x;
    for (int idx = tid; idx < TL_ * HD_; idx += 256) {
        const int t = idx >> 6, d = idx & 63;
        tks[t][d] = tk[((size_t)b * TL_ + t) * D_ + h * HD_ + d];
    }
    __syncthreads();

    const int warp = tid >> 5, lane = tid & 31;

    for (int s = warp; s < S_; s += 8) {
        const size_t tqo = ((size_t)b * S_ + s) * D_ + h * HD_;
        const float tq0 = __ldg(&tq[tqo + lane]);
        const float tq1 = __ldg(&tq[tqo + lane + 32]);
        const float* mrow = mask + ((size_t)b * S_ + s) * TL_;

        float mk0 = 0.f, mk1 = 0.f, cnt = 0.f;
#pragma unroll
        for (int t = 0; t < TL_; t++) {
            const float m = __ldg(&mrow[t]);
            cnt += m;
            mk0 = fmaf(m, tks[t][lane], mk0);
            mk1 = fmaf(m, tks[t][lane + 32], mk1);
        }
        float dotv = tq0 * mk0 + tq1 * mk1;
#pragma unroll
        for (int off = 16; off; off >>= 1)
            dotv += __shfl_xor_sync(0xffffffffu, dotv, off);

        if (lane == 0)
            wgt[(size_t)bh * S_ + s] = dotv / cnt;
    }
}

// ---------------------------------------------------------------------------
// fast exp on FMA pipe
// ---------------------------------------------------------------------------
__device__ __forceinline__ float fast_exp(float x)
{
    const float y = x * 1.44269504088896341f;
    const float n = rintf(y);
    const float t = (y - n) * 0.69314718055994531f;
    float p = 1.9841269841e-4f;
    p = fmaf(p, t, 1.38888888889e-3f);
    p = fmaf(p, t, 8.33333333333e-3f);
    p = fmaf(p, t, 4.16666666667e-2f);
    p = fmaf(p, t, 1.66666666667e-1f);
    p = fmaf(p, t, 0.5f);
    p = fmaf(p, t, 1.0f);
    p = fmaf(p, t, 1.0f);
    int e = (int)n;
    e = e < -126 ? -126 : e;
    const float s = __int_as_float((e + 127) << 23);
    return p * s;
}

// ---------------------------------------------------------------------------
// fused attention
// ---------------------------------------------------------------------------
#define APAD 68
#define ATT_SMEM_FLOATS (4 * 64 * APAD + 64)

__global__ __launch_bounds__(256)
void attn_kernel(const float* __restrict__ q, const float* __restrict__ k,
                 const float* __restrict__ v, const float* __restrict__ wgt,
                 float* __restrict__ ctx)
{
    extern __shared__ float smem[];
    float* qT = smem;
    float* kT = qT + 64 * APAD;
    float* vs = kT + 64 * APAD;
    float* ps = vs + 64 * APAD;
    float* ws = ps + 64 * APAD;

    const int qt = blockIdx.x;
    const int bh = blockIdx.y;
    const int b = bh >> 4;
    const int h = bh & 15;

    const int tid = threadIdx.x;
    const int ty = tid >> 4;
    const int tx = tid & 15;

    const size_t qbase = ((size_t)b * T_ + qt * 64) * D_ + h * HD_;
    for (int idx = tid; idx < 64 * 64; idx += 256) {
        const int r = idx >> 6, d = idx & 63;
        qT[d * APAD + r] = q[qbase + (size_t)r * D_ + d];
    }

    float o[4][4];
    float m_i[4], l_i[4];
#pragma unroll
    for (int i = 0; i < 4; i++) {
        m_i[i] = -1e30f;
        l_i[i] = 0.f;
#pragma unroll
        for (int j = 0; j < 4; j++) o[i][j] = 0.f;
    }

    const size_t kvbase = ((size_t)b * S_) * D_ + h * HD_;
    const float* wrow = wgt + (size_t)bh * S_;

    for (int sc = 0; sc < S_ / 64; sc++) {
        __syncthreads();
        const size_t koff = kvbase + (size_t)sc * 64 * D_;
        for (int idx = tid; idx < 64 * 64; idx += 256) {
            const int c = idx >> 6, d = idx & 63;
            kT[d * APAD + c] = k[koff + (size_t)c * D_ + d];
            vs[c * APAD + d] = v[koff + (size_t)c * D_ + d];
        }
        if (tid < 64) ws[tid] = wrow[sc * 64 + tid];
        __syncthreads();

        float sv[4][4];
#pragma unroll
        for (int i = 0; i < 4; i++)
#pragma unroll
            for (int j = 0; j < 4; j++) sv[i][j] = 0.f;

#pragma unroll 16
        for (int d = 0; d < 64; d++) {
            const float4 a4 = *reinterpret_cast<const float4*>(&qT[d * APAD + ty * 4]);
            const float4 b4 = *reinterpret_cast<const float4*>(&kT[d * APAD + tx * 4]);
            const float a[4] = {a4.x, a4.y, a4.z, a4.w};
            const float bb[4] = {b4.x, b4.y, b4.z, b4.w};
#pragma unroll
            for (int i = 0; i < 4; i++)
#pragma unroll
                for (int j = 0; j < 4; j++)
                    sv[i][j] = fmaf(a[i], bb[j], sv[i][j]);
        }

        const float w0 = ws[tx * 4 + 0], w1 = ws[tx * 4 + 1];
        const float w2 = ws[tx * 4 + 2], w3 = ws[tx * 4 + 3];
#pragma unroll
        for (int i = 0; i < 4; i++) {
            sv[i][0] *= w0; sv[i][1] *= w1; sv[i][2] *= w2; sv[i][3] *= w3;
        }

        float rm[4], rs[4], alpha[4];
#pragma unroll
        for (int i = 0; i < 4; i++) {
            float mx = fmaxf(fmaxf(sv[i][0], sv[i][1]), fmaxf(sv[i][2], sv[i][3]));
#pragma unroll
            for (int off = 1; off < 16; off <<= 1)
                mx = fmaxf(mx, __shfl_xor_sync(0xffffffffu, mx, off));
            rm[i] = mx;
        }
#pragma unroll
        for (int i = 0; i < 4; i++) {
            const float m_new = fmaxf(m_i[i], rm[i]);
            alpha[i] = fast_exp(m_i[i] - m_new);
            m_i[i] = m_new;
            float r = 0.f;
#pragma unroll
            for (int j = 0; j < 4; j++) {
                sv[i][j] = fast_exp(sv[i][j] - m_new);
                r += sv[i][j];
            }
            rs[i] = r;
        }
#pragma unroll
        for (int i = 0; i < 4; i++) {
#pragma unroll
            for (int off = 1; off < 16; off <<= 1)
                rs[i] += __shfl_xor_sync(0xffffffffu, rs[i], off);
            l_i[i] = l_i[i] * alpha[i] + rs[i];
#pragma unroll
            for (int j = 0; j < 4; j++) o[i][j] *= alpha[i];
        }

#pragma unroll
        for (int i = 0; i < 4; i++) {
            float4 pv = make_float4(sv[i][0], sv[i][1], sv[i][2], sv[i][3]);
            *reinterpret_cast<float4*>(&ps[(ty * 4 + i) * APAD + tx * 4]) = pv;
        }
        __syncthreads();

#pragma unroll 16
        for (int ss = 0; ss < 64; ss++) {
            const float4 vv = *reinterpret_cast<const float4*>(&vs[ss * APAD + tx * 4]);
            const float vb[4] = {vv.x, vv.y, vv.z, vv.w};
            float pa[4];
#pragma unroll
            for (int i = 0; i < 4; i++) pa[i] = ps[(ty * 4 + i) * APAD + ss];
#pragma unroll
            for (int i = 0; i < 4; i++)
#pragma unroll
                for (int j = 0; j < 4; j++)
                    o[i][j] = fmaf(pa[i], vb[j], o[i][j]);
        }
    }

#pragma unroll
    for (int i = 0; i < 4; i++) {
        const float inv = 1.0f / l_i[i];
        const int row = qt * 64 + ty * 4 + i;
        float4 ov = make_float4(o[i][0] * inv, o[i][1] * inv,
                                o[i][2] * inv, o[i][3] * inv);
        *reinterpret_cast<float4*>(
            &ctx[((size_t)b * T_ + row) * D_ + h * HD_ + tx * 4]) = ov;
    }
}

// ---------------------------------------------------------------------------
// launch
// ---------------------------------------------------------------------------
extern "C" void kernel_launch(void* const* d_in, const int* in_sizes, int n_in,
                              void* d_out, int out_size)
{
    const float* hidden = (const float*)d_in[0];
    const float* kv     = (const float*)d_in[1];
    const float* target = (const float*)d_in[2];
    const float* mask   = (const float*)d_in[3];
    const float* Wq  = (const float*)d_in[4];
    const float* bq  = (const float*)d_in[5];
    const float* Wk  = (const float*)d_in[6];
    const float* bk  = (const float*)d_in[7];
    const float* Wv  = (const float*)d_in[8];
    const float* bv  = (const float*)d_in[9];
    const float* Wwq = (const float*)d_in[10];
    const float* bwq = (const float*)d_in[11];
    const float* Wwk = (const float*)d_in[12];
    const float* bwk = (const float*)d_in[13];
    const float* Wo  = (const float*)d_in[14];
    const float* bo  = (const float*)d_in[15];
    float* out = (float*)d_out;

    float *q, *k, *v, *tq, *tk, *w, *ctx;
    cudaGetSymbolAddress((void**)&q,   g_q);
    cudaGetSymbolAddress((void**)&k,   g_k);
    cudaGetSymbolAddress((void**)&v,   g_v);
    cudaGetSymbolAddress((void**)&tq,  g_tq);
    cudaGetSymbolAddress((void**)&tk,  g_tk);
    cudaGetSymbolAddress((void**)&w,   g_w);
    cudaGetSymbolAddress((void**)&ctx, g_ctx);

    __nv_bfloat16 *hA, *kvA, *tA, *ctxA, *Wq2, *Wk2, *Wv2, *Wwq2, *Wwk2, *Wo2;
    cudaGetSymbolAddress((void**)&hA,   g_hA);
    cudaGetSymbolAddress((void**)&kvA,  g_kvA);
    cudaGetSymbolAddress((void**)&tA,   g_tA);
    cudaGetSymbolAddress((void**)&ctxA, g_ctxA);
    cudaGetSymbolAddress((void**)&Wq2,  g_Wq2);
    cudaGetSymbolAddress((void**)&Wk2,  g_Wk2);
    cudaGetSymbolAddress((void**)&Wv2,  g_Wv2);
    cudaGetSymbolAddress((void**)&Wwq2, g_Wwq2);
    cudaGetSymbolAddress((void**)&Wwk2, g_Wwk2);
    cudaGetSymbolAddress((void**)&Wo2,  g_Wo2);

    // 1) fp32 -> bf16 hi|lo splits
    split_kernel<<<B_ * T_,  256>>>(hidden, hA);
    split_kernel<<<B_ * S_,  256>>>(kv,     kvA);
    split_kernel<<<B_ * TL_, 256>>>(target, tA);
    split_kernel<<<D_, 256>>>(Wq,  Wq2);
    split_kernel<<<D_, 256>>>(Wk,  Wk2);
    split_kernel<<<D_, 256>>>(Wv,  Wv2);
    split_kernel<<<D_, 256>>>(Wwq, Wwq2);
    split_kernel<<<D_, 256>>>(Wwk, Wwk2);
    split_kernel<<<D_, 256>>>(Wo,  Wo2);

    // 2) tensor-core projections (mma.sync, 3-term split)
    mma_gemm_kernel<<<dim3(8, (B_ * T_) / 128), 256>>>(hA, Wq2, bq, q, SCALING_);
    mma_gemm_kernel<<<dim3(8, (B_ * S_) / 128), 256>>>(kvA, Wk2, bk, k, 1.0f);
    mma_gemm_kernel<<<dim3(8, (B_ * S_) / 128), 256>>>(kvA, Wv2, bv, v, 1.0f);
    mma_gemm_kernel<<<dim3(8, (B_ * S_) / 128), 256>>>(kvA, Wwq2, bwq, tq, SCALING_);
    mma_gemm_kernel<<<dim3(8, (B_ * TL_) / 128), 256>>>(tA, Wwk2, bwk, tk, 1.0f);

    // 3) masked-mean weights
    weights_kernel<<<B_ * H_, 256>>>(tq, tk, mask, w);

    // 4) fused attention
    const int att_smem = ATT_SMEM_FLOATS * (int)sizeof(float);
    cudaFuncSetAttribute(attn_kernel,
                         cudaFuncAttributeMaxDynamicSharedMemorySize, att_smem);
    attn_kernel<<<dim3(T_ / 64, B_ * H_), 256, att_smem>>>(q, k, v, w, ctx);

    // 5) output projection (mma.sync, 3-term split)
    split_kernel<<<B_ * T_, 256>>>(ctx, ctxA);
    mma_gemm_kernel<<<dim3(8, (B_ * T_) / 128), 256>>>(ctxA, Wo2, bo, out, 1.0f);
}

// round 7
// speedup vs baseline: 1.6640x; 1.1740x over previous
#include <cuda_runtime.h>
#include <cuda_bf16.h>
#include <cstdint>

// ============================================================================
// KTMutualAttention — mma.sync (bf16) 3-term split GEMMs
//                   + mma.sync tensor-core flash attention
//   B=8, T=512, S=1024, TL=64, D=1024, H=16, hd=64
// GEMMs: K'=3072 virtual (hi*hi + hi*lo + lo*hi), rel ~2^-18.
// Attention: QK single bf16 (softmax shift-invariant, logits tiny);
//            PV 3-term hi/lo split (averaging cancellation needs it).
// ============================================================================

#define B_   8
#define T_   512
#define S_   1024
#define TL_  64
#define D_   1024
#define H_   16
#define HD_  64
#define SCALING_ 0.125f
#define K2_  2048          // stored split width ([hi|lo])

// ---------------------------------------------------------------------------
// scratch (device globals; no allocations allowed)
// ---------------------------------------------------------------------------
__device__ __align__(256) float g_q  [B_ * T_ * D_];
__device__ __align__(256) float g_k  [B_ * S_ * D_];
__device__ __align__(256) float g_v  [B_ * S_ * D_];
__device__ __align__(256) float g_tq [B_ * S_ * D_];
__device__ __align__(256) float g_tk [B_ * TL_ * D_];
__device__ __align__(256) float g_w  [B_ * H_ * S_];
__device__ __align__(256) float g_ctx[B_ * T_ * D_];

// bf16 split operands  [rows, 2048] = [hi(1024) | lo(1024)]
__device__ __align__(256) __nv_bfloat16 g_hA  [(size_t)B_ * T_  * K2_];
__device__ __align__(256) __nv_bfloat16 g_kvA [(size_t)B_ * S_  * K2_];
__device__ __align__(256) __nv_bfloat16 g_tA  [(size_t)B_ * TL_ * K2_];
__device__ __align__(256) __nv_bfloat16 g_ctxA[(size_t)B_ * T_  * K2_];
__device__ __align__(256) __nv_bfloat16 g_Wq2 [(size_t)D_ * K2_];
__device__ __align__(256) __nv_bfloat16 g_Wk2 [(size_t)D_ * K2_];
__device__ __align__(256) __nv_bfloat16 g_Wv2 [(size_t)D_ * K2_];
__device__ __align__(256) __nv_bfloat16 g_Wwq2[(size_t)D_ * K2_];
__device__ __align__(256) __nv_bfloat16 g_Wwk2[(size_t)D_ * K2_];
__device__ __align__(256) __nv_bfloat16 g_Wo2 [(size_t)D_ * K2_];

// ---------------------------------------------------------------------------
// PTX helpers (all portable: sm_80+)
// ---------------------------------------------------------------------------
__device__ __forceinline__ uint32_t smem_u32(const void* p) {
    uint32_t a;
    asm("{ .reg .u64 t; cvta.to.shared.u64 t, %1; cvt.u32.u64 %0, t; }"
        : "=r"(a) : "l"(p));
    return a;
}

#define CP_ASYNC16(dst_u32, src_ptr) \
    asm volatile("cp.async.cg.shared.global [%0], [%1], 16;" \
                 :: "r"(dst_u32), "l"(src_ptr) : "memory")
#define CP_COMMIT() asm volatile("cp.async.commit_group;" ::: "memory")
#define CP_WAIT1()  asm volatile("cp.async.wait_group 1;" ::: "memory")
#define CP_WAIT0()  asm volatile("cp.async.wait_group 0;" ::: "memory")

__device__ __forceinline__ void ldmatrix_x4(uint32_t& r0, uint32_t& r1,
                                            uint32_t& r2, uint32_t& r3,
                                            uint32_t addr)
{
    asm volatile("ldmatrix.sync.aligned.m8n8.x4.shared.b16 {%0,%1,%2,%3}, [%4];"
                 : "=r"(r0), "=r"(r1), "=r"(r2), "=r"(r3) : "r"(addr));
}

__device__ __forceinline__ void mma_bf16(float* c, uint32_t a0, uint32_t a1,
                                         uint32_t a2, uint32_t a3,
                                         uint32_t b0, uint32_t b1)
{
    asm volatile(
        "mma.sync.aligned.m16n8k16.row.col.f32.bf16.bf16.f32 "
        "{%0,%1,%2,%3}, {%4,%5,%6,%7}, {%8,%9}, {%0,%1,%2,%3};"
        : "+f"(c[0]), "+f"(c[1]), "+f"(c[2]), "+f"(c[3])
        : "r"(a0), "r"(a1), "r"(a2), "r"(a3), "r"(b0), "r"(b1));
}

__device__ __forceinline__ uint32_t pack_bf162(float x, float y)
{
    __nv_bfloat162 t = __floats2bfloat162_rn(x, y);   // low = x, high = y
    return *reinterpret_cast<uint32_t*>(&t);
}

// hi/lo split of a float pair into two bf16x2 regs
__device__ __forceinline__ void split_pair(float x, float y,
                                           uint32_t& hi, uint32_t& lo)
{
    __nv_bfloat16 hx = __float2bfloat16_rn(x);
    __nv_bfloat16 hy = __float2bfloat16_rn(y);
    __nv_bfloat162 th(hx, hy);
    hi = *reinterpret_cast<uint32_t*>(&th);
    __nv_bfloat162 tl(__float2bfloat16_rn(x - __bfloat162float(hx)),
                      __float2bfloat16_rn(y - __bfloat162float(hy)));
    lo = *reinterpret_cast<uint32_t*>(&tl);
}

// ---------------------------------------------------------------------------
// fp32 -> bf16 hi|lo split:  y[row, 0:1024]=hi, y[row, 1024:2048]=lo
// ---------------------------------------------------------------------------
__global__ __launch_bounds__(256)
void split_kernel(const float* __restrict__ x, __nv_bfloat16* __restrict__ y)
{
    const int idx = blockIdx.x * 256 + threadIdx.x;
    const int row = idx >> 8;
    const int c4  = (idx & 255) * 4;
    const float4 v = *reinterpret_cast<const float4*>(x + ((size_t)row << 10) + c4);

    __nv_bfloat16 hx = __float2bfloat16_rn(v.x);
    __nv_bfloat16 hy = __float2bfloat16_rn(v.y);
    __nv_bfloat16 hz = __float2bfloat16_rn(v.z);
    __nv_bfloat16 hw = __float2bfloat16_rn(v.w);
    __nv_bfloat16 lx = __float2bfloat16_rn(v.x - __bfloat162float(hx));
    __nv_bfloat16 ly = __float2bfloat16_rn(v.y - __bfloat162float(hy));
    __nv_bfloat16 lz = __float2bfloat16_rn(v.z - __bfloat162float(hz));
    __nv_bfloat16 lw = __float2bfloat16_rn(v.w - __bfloat162float(hw));

    __nv_bfloat162* dh = reinterpret_cast<__nv_bfloat162*>(
        y + (size_t)row * K2_ + c4);
    dh[0] = __nv_bfloat162(hx, hy);
    dh[1] = __nv_bfloat162(hz, hw);
    __nv_bfloat162* dl = reinterpret_cast<__nv_bfloat162*>(
        y + (size_t)row * K2_ + 1024 + c4);
    dl[0] = __nv_bfloat162(lx, ly);
    dl[1] = __nv_bfloat162(lz, lw);
}

// ---------------------------------------------------------------------------
// mma.sync GEMM (3-term split), unchanged from R6 (validated)
// ---------------------------------------------------------------------------
#define BK 32
#define SROW 40
#define N_CHUNK 96

__global__ __launch_bounds__(256, 2)
void mma_gemm_kernel(const __nv_bfloat16* __restrict__ A,
                     const __nv_bfloat16* __restrict__ W,
                     const float* __restrict__ bias,
                     float* __restrict__ C, float scale)
{
    __shared__ __nv_bfloat16 sA[2][128 * SROW];
    __shared__ __nv_bfloat16 sB[2][128 * SROW];
    __shared__ float biasS[128];

    const int tid = threadIdx.x;
    const int wid = tid >> 5, lane = tid & 31;
    const int wm = wid & 3;
    const int wn = wid >> 2;
    const int bm = blockIdx.y * 128;
    const int bn = blockIdx.x * 128;

    if (tid < 128) biasS[tid] = bias[bn + tid];

    const __nv_bfloat16* Ag = A + (size_t)bm * K2_;
    const __nv_bfloat16* Wg = W + (size_t)bn * K2_;

    const int ldrow = tid >> 1;
    const int ldoff = (tid & 1) * 16;

    const uint32_t sA0 = smem_u32(sA[0]);
    const uint32_t sA1 = smem_u32(sA[1]);
    const uint32_t sB0 = smem_u32(sB[0]);
    const uint32_t sB1 = smem_u32(sB[1]);

    auto stage = [&](int c, int buf) {
        const int seg = c >> 5;
        const int col = (c & 31) * BK;
        const int gA = ((seg == 2) ? 1024 : 0) + col;   // A: hi,hi,lo
        const int gW = ((seg == 1) ? 1024 : 0) + col;   // W: hi,lo,hi
        const size_t ga = (size_t)ldrow * K2_ + gA + ldoff;
        const size_t gw = (size_t)ldrow * K2_ + gW + ldoff;
        const uint32_t sa = (buf ? sA1 : sA0) + ldrow * (SROW * 2) + ldoff * 2;
        const uint32_t sb = (buf ? sB1 : sB0) + ldrow * (SROW * 2) + ldoff * 2;
        CP_ASYNC16(sa,      Ag + ga);
        CP_ASYNC16(sa + 16, Ag + ga + 8);
        CP_ASYNC16(sb,      Wg + gw);
        CP_ASYNC16(sb + 16, Wg + gw + 8);
    };

    float acc[2][8][4];
#pragma unroll
    for (int mt = 0; mt < 2; mt++)
#pragma unroll
        for (int nf = 0; nf < 8; nf++)
#pragma unroll
            for (int r = 0; r < 4; r++) acc[mt][nf][r] = 0.f;

    stage(0, 0);
    CP_COMMIT();

    const int lrow = lane & 15;
    const int lcol = (lane >> 4) * 16;

    for (int c = 0; c < N_CHUNK; ++c) {
        const int buf = c & 1;
        if (c + 1 < N_CHUNK) {
            stage(c + 1, buf ^ 1);
            CP_COMMIT();
            CP_WAIT1();
        } else {
            CP_WAIT0();
        }
        __syncthreads();

        const uint32_t aBase = (buf ? sA1 : sA0);
        const uint32_t bBase = (buf ? sB1 : sB0);

#pragma unroll
        for (int kk = 0; kk < 2; kk++) {
            const int kbyte = kk * 32 + lcol;

            uint32_t a[2][4];
#pragma unroll
            for (int mt = 0; mt < 2; mt++) {
                const int row = wm * 32 + mt * 16 + lrow;
                ldmatrix_x4(a[mt][0], a[mt][1], a[mt][2], a[mt][3],
                            aBase + row * (SROW * 2) + kbyte);
            }
            uint32_t b[4][4];
#pragma unroll
            for (int nb = 0; nb < 4; nb++) {
                const int row = wn * 64 + nb * 16 + lrow;
                ldmatrix_x4(b[nb][0], b[nb][1], b[nb][2], b[nb][3],
                            bBase + row * (SROW * 2) + kbyte);
            }
#pragma unroll
            for (int mt = 0; mt < 2; mt++)
#pragma unroll
                for (int nf = 0; nf < 8; nf++) {
                    const int nb = nf >> 1;
                    const uint32_t b0 = (nf & 1) ? b[nb][1] : b[nb][0];
                    const uint32_t b1 = (nf & 1) ? b[nb][3] : b[nb][2];
                    mma_bf16(acc[mt][nf], a[mt][0], a[mt][1], a[mt][2], a[mt][3],
                             b0, b1);
                }
        }
        __syncthreads();
    }

    const int g_  = lane >> 2;
    const int tig = lane & 3;
#pragma unroll
    for (int mt = 0; mt < 2; mt++) {
        const int row0 = bm + wm * 32 + mt * 16 + g_;
#pragma unroll
        for (int nf = 0; nf < 8; nf++) {
            const int col = wn * 64 + nf * 8 + tig * 2;
            const float b0 = biasS[col], b1 = biasS[col + 1];
            float2 o0, o1;
            o0.x = scale * (acc[mt][nf][0] + b0);
            o0.y = scale * (acc[mt][nf][1] + b1);
            o1.x = scale * (acc[mt][nf][2] + b0);
            o1.y = scale * (acc[mt][nf][3] + b1);
            *reinterpret_cast<float2*>(C + (size_t)row0 * 1024 + bn + col) = o0;
            *reinterpret_cast<float2*>(C + (size_t)(row0 + 8) * 1024 + bn + col) = o1;
        }
    }
}

// ---------------------------------------------------------------------------
// weights[b,h,s] = (tq . (mask @ tk)) / sum(mask)
// ---------------------------------------------------------------------------
__global__ __launch_bounds__(256)
void weights_kernel(const float* __restrict__ tq, const float* __restrict__ tk,
                    const float* __restrict__ mask, float* __restrict__ wgt)
{
    const int bh = blockIdx.x;
    const int b = bh >> 4;
    const int h = bh & 15;

    __shared__ float tks[TL_][HD_];

    const int tid = threadIdx.x;
    for (int idx = tid; idx < TL_ * HD_; idx += 256) {
        const int t = idx >> 6, d = idx & 63;
        tks[t][d] = tk[((size_t)b * TL_ + t) * D_ + h * HD_ + d];
    }
    __syncthreads();

    const int warp = tid >> 5, lane = tid & 31;

    for (int s = warp; s < S_; s += 8) {
        const size_t tqo = ((size_t)b * S_ + s) * D_ + h * HD_;
        const float tq0 = __ldg(&tq[tqo + lane]);
        const float tq1 = __ldg(&tq[tqo + lane + 32]);
        const float* mrow = mask + ((size_t)b * S_ + s) * TL_;

        float mk0 = 0.f, mk1 = 0.f, cnt = 0.f;
#pragma unroll
        for (int t = 0; t < TL_; t++) {
            const float m = __ldg(&mrow[t]);
            cnt += m;
            mk0 = fmaf(m, tks[t][lane], mk0);
            mk1 = fmaf(m, tks[t][lane + 32], mk1);
        }
        float dotv = tq0 * mk0 + tq1 * mk1;
#pragma unroll
        for (int off = 16; off; off >>= 1)
            dotv += __shfl_xor_sync(0xffffffffu, dotv, off);

        if (lane == 0)
            wgt[(size_t)bh * S_ + s] = dotv / cnt;
    }
}

// ---------------------------------------------------------------------------
// fast exp on FMA pipe
// ---------------------------------------------------------------------------
__device__ __forceinline__ float fast_exp(float x)
{
    const float y = x * 1.44269504088896341f;
    const float n = rintf(y);
    const float t = (y - n) * 0.69314718055994531f;
    float p = 1.9841269841e-4f;
    p = fmaf(p, t, 1.38888888889e-3f);
    p = fmaf(p, t, 8.33333333333e-3f);
    p = fmaf(p, t, 4.16666666667e-2f);
    p = fmaf(p, t, 1.66666666667e-1f);
    p = fmaf(p, t, 0.5f);
    p = fmaf(p, t, 1.0f);
    p = fmaf(p, t, 1.0f);
    int e = (int)n;
    e = e < -126 ? -126 : e;
    const float s = __int_as_float((e + 127) << 23);
    return p * s;
}

// ---------------------------------------------------------------------------
// Tensor-core flash attention.
//   grid = (T/64, B*H), 128 threads (4 warps x 16 q-rows).
//   QK: single bf16. PV: 3-term hi/lo split. P stays in registers
//   (C-frag -> A-frag reinterpretation). V transposed to [d][s] in smem.
// ---------------------------------------------------------------------------
#define VPAD 72

__global__ __launch_bounds__(128)
void attn_tc_kernel(const float* __restrict__ q, const float* __restrict__ k,
                    const float* __restrict__ v, const float* __restrict__ wgt,
                    float* __restrict__ ctx)
{
    __shared__ __nv_bfloat16 sQ [64 * VPAD];
    __shared__ __nv_bfloat16 sK [64 * VPAD];
    __shared__ __nv_bfloat16 sVh[64 * VPAD];
    __shared__ __nv_bfloat16 sVl[64 * VPAD];
    __shared__ float ws[64];

    const int qt = blockIdx.x, bh = blockIdx.y;
    const int b = bh >> 4, h = bh & 15;
    const int tid = threadIdx.x, wid = tid >> 5, lane = tid & 31;
    const int g = lane >> 2, tig = lane & 3;
    const int lrow = lane & 15, lcolb = (lane >> 4) * 16;

    // load Q tile once -> bf16
    const size_t qbase = ((size_t)b * T_ + qt * 64) * D_ + h * HD_;
#pragma unroll
    for (int it = 0; it < 8; ++it) {
        const int idx = it * 128 + tid;
        const int r = idx >> 4, c4 = (idx & 15) * 4;
        const float4 vq = *reinterpret_cast<const float4*>(q + qbase + (size_t)r * D_ + c4);
        __nv_bfloat162* dq = reinterpret_cast<__nv_bfloat162*>(&sQ[r * VPAD + c4]);
        dq[0] = __floats2bfloat162_rn(vq.x, vq.y);
        dq[1] = __floats2bfloat162_rn(vq.z, vq.w);
    }

    float o[8][4];
#pragma unroll
    for (int nf = 0; nf < 8; nf++)
#pragma unroll
        for (int r = 0; r < 4; r++) o[nf][r] = 0.f;
    float m0 = -1e30f, m1 = -1e30f, l0 = 0.f, l1 = 0.f;

    const uint32_t sQb = smem_u32(sQ), sKb = smem_u32(sK);
    const uint32_t sVhb = smem_u32(sVh), sVlb = smem_u32(sVl);

    const size_t kvbase = ((size_t)b * S_) * D_ + h * HD_;
    const float* wrow = wgt + (size_t)bh * S_;

    for (int sc = 0; sc < S_ / 64; ++sc) {
        __syncthreads();
        const size_t koff = kvbase + (size_t)sc * 64 * D_;
#pragma unroll
        for (int it = 0; it < 8; ++it) {
            const int idx = it * 128 + tid;
            const int r = idx >> 4, c4 = (idx & 15) * 4;
            const float4 kk = *reinterpret_cast<const float4*>(k + koff + (size_t)r * D_ + c4);
            __nv_bfloat162* dk = reinterpret_cast<__nv_bfloat162*>(&sK[r * VPAD + c4]);
            dk[0] = __floats2bfloat162_rn(kk.x, kk.y);
            dk[1] = __floats2bfloat162_rn(kk.z, kk.w);
            const float4 vv = *reinterpret_cast<const float4*>(v + koff + (size_t)r * D_ + c4);
            const float vals[4] = {vv.x, vv.y, vv.z, vv.w};
#pragma unroll
            for (int i = 0; i < 4; ++i) {
                const __nv_bfloat16 hi = __float2bfloat16_rn(vals[i]);
                const __nv_bfloat16 lo =
                    __float2bfloat16_rn(vals[i] - __bfloat162float(hi));
                sVh[(c4 + i) * VPAD + r] = hi;     // transposed: [d][s]
                sVl[(c4 + i) * VPAD + r] = lo;
            }
        }
        if (tid < 64) ws[tid] = wrow[sc * 64 + tid];
        __syncthreads();

        // ---- S = Q @ K^T (bf16 mma)
        float sv[8][4];
#pragma unroll
        for (int nf = 0; nf < 8; nf++)
#pragma unroll
            for (int r = 0; r < 4; r++) sv[nf][r] = 0.f;

#pragma unroll
        for (int kk = 0; kk < 4; kk++) {
            const int kb = kk * 32 + lcolb;
            uint32_t a0, a1, a2, a3;
            ldmatrix_x4(a0, a1, a2, a3,
                        sQb + (wid * 16 + lrow) * (VPAD * 2) + kb);
#pragma unroll
            for (int nb = 0; nb < 4; nb++) {
                uint32_t b0, b1, b2, b3;
                ldmatrix_x4(b0, b1, b2, b3,
                            sKb + (nb * 16 + lrow) * (VPAD * 2) + kb);
                mma_bf16(sv[2 * nb],     a0, a1, a2, a3, b0, b2);
                mma_bf16(sv[2 * nb + 1], a0, a1, a2, a3, b1, b3);
            }
        }

        // ---- per-key-column weight scaling
#pragma unroll
        for (int nf = 0; nf < 8; nf++) {
            const int col = nf * 8 + tig * 2;
            const float w0 = ws[col], w1 = ws[col + 1];
            sv[nf][0] *= w0; sv[nf][1] *= w1;
            sv[nf][2] *= w0; sv[nf][3] *= w1;
        }

        // ---- online softmax (rows g and g+8)
        float mx0 = -1e30f, mx1 = -1e30f;
#pragma unroll
        for (int nf = 0; nf < 8; nf++) {
            mx0 = fmaxf(mx0, fmaxf(sv[nf][0], sv[nf][1]));
            mx1 = fmaxf(mx1, fmaxf(sv[nf][2], sv[nf][3]));
        }
        mx0 = fmaxf(mx0, __shfl_xor_sync(0xffffffffu, mx0, 1));
        mx0 = fmaxf(mx0, __shfl_xor_sync(0xffffffffu, mx0, 2));
        mx1 = fmaxf(mx1, __shfl_xor_sync(0xffffffffu, mx1, 1));
        mx1 = fmaxf(mx1, __shfl_xor_sync(0xffffffffu, mx1, 2));

        const float mn0 = fmaxf(m0, mx0), mn1 = fmaxf(m1, mx1);
        const float al0 = fast_exp(m0 - mn0), al1 = fast_exp(m1 - mn1);
        m0 = mn0; m1 = mn1;

        float s0 = 0.f, s1 = 0.f;
#pragma unroll
        for (int nf = 0; nf < 8; nf++) {
            sv[nf][0] = fast_exp(sv[nf][0] - mn0);
            sv[nf][1] = fast_exp(sv[nf][1] - mn0);
            sv[nf][2] = fast_exp(sv[nf][2] - mn1);
            sv[nf][3] = fast_exp(sv[nf][3] - mn1);
            s0 += sv[nf][0] + sv[nf][1];
            s1 += sv[nf][2] + sv[nf][3];
        }
        s0 += __shfl_xor_sync(0xffffffffu, s0, 1);
        s0 += __shfl_xor_sync(0xffffffffu, s0, 2);
        s1 += __shfl_xor_sync(0xffffffffu, s1, 1);
        s1 += __shfl_xor_sync(0xffffffffu, s1, 2);
        l0 = l0 * al0 + s0;
        l1 = l1 * al1 + s1;

#pragma unroll
        for (int nf = 0; nf < 8; nf++) {
            o[nf][0] *= al0; o[nf][1] *= al0;
            o[nf][2] *= al1; o[nf][3] *= al1;
        }

        // ---- O += P @ V  (3-term hi/lo; P regs reused as A frags)
#pragma unroll
        for (int j = 0; j < 4; j++) {
            uint32_t ph[4], pl[4];
            split_pair(sv[2 * j][0],     sv[2 * j][1],     ph[0], pl[0]);
            split_pair(sv[2 * j][2],     sv[2 * j][3],     ph[1], pl[1]);
            split_pair(sv[2 * j + 1][0], sv[2 * j + 1][1], ph[2], pl[2]);
            split_pair(sv[2 * j + 1][2], sv[2 * j + 1][3], ph[3], pl[3]);

            const int kb = j * 32 + lcolb;
#pragma unroll
            for (int nb = 0; nb < 4; nb++) {
                uint32_t h0, h1, h2, h3, q0, q1, q2, q3;
                ldmatrix_x4(h0, h1, h2, h3,
                            sVhb + (nb * 16 + lrow) * (VPAD * 2) + kb);
                ldmatrix_x4(q0, q1, q2, q3,
                            sVlb + (nb * 16 + lrow) * (VPAD * 2) + kb);
                mma_bf16(o[2 * nb],     ph[0], ph[1], ph[2], ph[3], h0, h2);
                mma_bf16(o[2 * nb + 1], ph[0], ph[1], ph[2], ph[3], h1, h3);
                mma_bf16(o[2 * nb],     ph[0], ph[1], ph[2], ph[3], q0, q2);
                mma_bf16(o[2 * nb + 1], ph[0], ph[1], ph[2], ph[3], q1, q3);
                mma_bf16(o[2 * nb],     pl[0], pl[1], pl[2], pl[3], h0, h2);
                mma_bf16(o[2 * nb + 1], pl[0], pl[1], pl[2], pl[3], h1, h3);
            }
        }
    }

    // ---- epilogue
    const float inv0 = 1.0f / l0, inv1 = 1.0f / l1;
    const int row0 = qt * 64 + wid * 16 + g;
#pragma unroll
    for (int nf = 0; nf < 8; nf++) {
        const int col = h * HD_ + nf * 8 + tig * 2;
        float2 w0, w1;
        w0.x = o[nf][0] * inv0; w0.y = o[nf][1] * inv0;
        w1.x = o[nf][2] * inv1; w1.y = o[nf][3] * inv1;
        *reinterpret_cast<float2*>(&ctx[((size_t)b * T_ + row0) * D_ + col]) = w0;
        *reinterpret_cast<float2*>(&ctx[((size_t)b * T_ + row0 + 8) * D_ + col]) = w1;
    }
}

// ---------------------------------------------------------------------------
// launch
// ---------------------------------------------------------------------------
extern "C" void kernel_launch(void* const* d_in, const int* in_sizes, int n_in,
                              void* d_out, int out_size)
{
    const float* hidden = (const float*)d_in[0];
    const float* kv     = (const float*)d_in[1];
    const float* target = (const float*)d_in[2];
    const float* mask   = (const float*)d_in[3];
    const float* Wq  = (const float*)d_in[4];
    const float* bq  = (const float*)d_in[5];
    const float* Wk  = (const float*)d_in[6];
    const float* bk  = (const float*)d_in[7];
    const float* Wv  = (const float*)d_in[8];
    const float* bv  = (const float*)d_in[9];
    const float* Wwq = (const float*)d_in[10];
    const float* bwq = (const float*)d_in[11];
    const float* Wwk = (const float*)d_in[12];
    const float* bwk = (const float*)d_in[13];
    const float* Wo  = (const float*)d_in[14];
    const float* bo  = (const float*)d_in[15];
    float* out = (float*)d_out;

    float *q, *k, *v, *tq, *tk, *w, *ctx;
    cudaGetSymbolAddress((void**)&q,   g_q);
    cudaGetSymbolAddress((void**)&k,   g_k);
    cudaGetSymbolAddress((void**)&v,   g_v);
    cudaGetSymbolAddress((void**)&tq,  g_tq);
    cudaGetSymbolAddress((void**)&tk,  g_tk);
    cudaGetSymbolAddress((void**)&w,   g_w);
    cudaGetSymbolAddress((void**)&ctx, g_ctx);

    __nv_bfloat16 *hA, *kvA, *tA, *ctxA, *Wq2, *Wk2, *Wv2, *Wwq2, *Wwk2, *Wo2;
    cudaGetSymbolAddress((void**)&hA,   g_hA);
    cudaGetSymbolAddress((void**)&kvA,  g_kvA);
    cudaGetSymbolAddress((void**)&tA,   g_tA);
    cudaGetSymbolAddress((void**)&ctxA, g_ctxA);
    cudaGetSymbolAddress((void**)&Wq2,  g_Wq2);
    cudaGetSymbolAddress((void**)&Wk2,  g_Wk2);
    cudaGetSymbolAddress((void**)&Wv2,  g_Wv2);
    cudaGetSymbolAddress((void**)&Wwq2, g_Wwq2);
    cudaGetSymbolAddress((void**)&Wwk2, g_Wwk2);
    cudaGetSymbolAddress((void**)&Wo2,  g_Wo2);

    // 1) fp32 -> bf16 hi|lo splits
    split_kernel<<<B_ * T_,  256>>>(hidden, hA);
    split_kernel<<<B_ * S_,  256>>>(kv,     kvA);
    split_kernel<<<B_ * TL_, 256>>>(target, tA);
    split_kernel<<<D_, 256>>>(Wq,  Wq2);
    split_kernel<<<D_, 256>>>(Wk,  Wk2);
    split_kernel<<<D_, 256>>>(Wv,  Wv2);
    split_kernel<<<D_, 256>>>(Wwq, Wwq2);
    split_kernel<<<D_, 256>>>(Wwk, Wwk2);
    split_kernel<<<D_, 256>>>(Wo,  Wo2);

    // 2) tensor-core projections (mma.sync, 3-term split)
    mma_gemm_kernel<<<dim3(8, (B_ * T_) / 128), 256>>>(hA, Wq2, bq, q, SCALING_);
    mma_gemm_kernel<<<dim3(8, (B_ * S_) / 128), 256>>>(kvA, Wk2, bk, k, 1.0f);
    mma_gemm_kernel<<<dim3(8, (B_ * S_) / 128), 256>>>(kvA, Wv2, bv, v, 1.0f);
    mma_gemm_kernel<<<dim3(8, (B_ * S_) / 128), 256>>>(kvA, Wwq2, bwq, tq, SCALING_);
    mma_gemm_kernel<<<dim3(8, (B_ * TL_) / 128), 256>>>(tA, Wwk2, bwk, tk, 1.0f);

    // 3) masked-mean weights
    weights_kernel<<<B_ * H_, 256>>>(tq, tk, mask, w);

    // 4) tensor-core flash attention
    attn_tc_kernel<<<dim3(T_ / 64, B_ * H_), 128>>>(q, k, v, w, ctx);

    // 5) output projection (mma.sync, 3-term split)
    split_kernel<<<B_ * T_, 256>>>(ctx, ctxA);
    mma_gemm_kernel<<<dim3(8, (B_ * T_) / 128), 256>>>(ctxA, Wo2, bo, out, 1.0f);
}

// round 8
// speedup vs baseline: 1.7515x; 1.0526x over previous
#include <cuda_runtime.h>
#include <cuda_bf16.h>
#include <cstdint>

// ============================================================================
// KTMutualAttention — mma.sync (bf16) 3-term split GEMMs (4-stage pipeline)
//                   + mma.sync flash attention (128-row q tiles, trans-V)
//   B=8, T=512, S=1024, TL=64, D=1024, H=16, hd=64
// ============================================================================

#define B_   8
#define T_   512
#define S_   1024
#define TL_  64
#define D_   1024
#define H_   16
#define HD_  64
#define SCALING_ 0.125f
#define K2_  2048          // stored split width ([hi|lo])

// ---------------------------------------------------------------------------
// scratch (device globals; no allocations allowed)
// ---------------------------------------------------------------------------
__device__ __align__(256) float g_q  [B_ * T_ * D_];
__device__ __align__(256) float g_k  [B_ * S_ * D_];
__device__ __align__(256) float g_v  [B_ * S_ * D_];
__device__ __align__(256) float g_tq [B_ * S_ * D_];
__device__ __align__(256) float g_tk [B_ * TL_ * D_];
__device__ __align__(256) float g_w  [B_ * H_ * S_];
__device__ __align__(256) float g_ctx[B_ * T_ * D_];

__device__ __align__(256) __nv_bfloat16 g_hA  [(size_t)B_ * T_  * K2_];
__device__ __align__(256) __nv_bfloat16 g_kvA [(size_t)B_ * S_  * K2_];
__device__ __align__(256) __nv_bfloat16 g_tA  [(size_t)B_ * TL_ * K2_];
__device__ __align__(256) __nv_bfloat16 g_ctxA[(size_t)B_ * T_  * K2_];
__device__ __align__(256) __nv_bfloat16 g_Wq2 [(size_t)D_ * K2_];
__device__ __align__(256) __nv_bfloat16 g_Wk2 [(size_t)D_ * K2_];
__device__ __align__(256) __nv_bfloat16 g_Wv2 [(size_t)D_ * K2_];
__device__ __align__(256) __nv_bfloat16 g_Wwq2[(size_t)D_ * K2_];
__device__ __align__(256) __nv_bfloat16 g_Wwk2[(size_t)D_ * K2_];
__device__ __align__(256) __nv_bfloat16 g_Wo2 [(size_t)D_ * K2_];

// ---------------------------------------------------------------------------
// PTX helpers (portable sm_80+)
// ---------------------------------------------------------------------------
__device__ __forceinline__ uint32_t smem_u32(const void* p) {
    uint32_t a;
    asm("{ .reg .u64 t; cvta.to.shared.u64 t, %1; cvt.u32.u64 %0, t; }"
        : "=r"(a) : "l"(p));
    return a;
}

#define CP_ASYNC16(dst_u32, src_ptr) \
    asm volatile("cp.async.cg.shared.global [%0], [%1], 16;" \
                 :: "r"(dst_u32), "l"(src_ptr) : "memory")
#define CP_COMMIT() asm volatile("cp.async.commit_group;" ::: "memory")
#define CP_WAIT2()  asm volatile("cp.async.wait_group 2;" ::: "memory")
#define CP_WAIT0()  asm volatile("cp.async.wait_group 0;" ::: "memory")

__device__ __forceinline__ void ldmatrix_x4(uint32_t& r0, uint32_t& r1,
                                            uint32_t& r2, uint32_t& r3,
                                            uint32_t addr)
{
    asm volatile("ldmatrix.sync.aligned.m8n8.x4.shared.b16 {%0,%1,%2,%3}, [%4];"
                 : "=r"(r0), "=r"(r1), "=r"(r2), "=r"(r3) : "r"(addr));
}

__device__ __forceinline__ void ldmatrix_x4_trans(uint32_t& r0, uint32_t& r1,
                                                  uint32_t& r2, uint32_t& r3,
                                                  uint32_t addr)
{
    asm volatile("ldmatrix.sync.aligned.m8n8.x4.trans.shared.b16 {%0,%1,%2,%3}, [%4];"
                 : "=r"(r0), "=r"(r1), "=r"(r2), "=r"(r3) : "r"(addr));
}

__device__ __forceinline__ void mma_bf16(float* c, uint32_t a0, uint32_t a1,
                                         uint32_t a2, uint32_t a3,
                                         uint32_t b0, uint32_t b1)
{
    asm volatile(
        "mma.sync.aligned.m16n8k16.row.col.f32.bf16.bf16.f32 "
        "{%0,%1,%2,%3}, {%4,%5,%6,%7}, {%8,%9}, {%0,%1,%2,%3};"
        : "+f"(c[0]), "+f"(c[1]), "+f"(c[2]), "+f"(c[3])
        : "r"(a0), "r"(a1), "r"(a2), "r"(a3), "r"(b0), "r"(b1));
}

__device__ __forceinline__ void split_pair(float x, float y,
                                           uint32_t& hi, uint32_t& lo)
{
    __nv_bfloat16 hx = __float2bfloat16_rn(x);
    __nv_bfloat16 hy = __float2bfloat16_rn(y);
    __nv_bfloat162 th(hx, hy);
    hi = *reinterpret_cast<uint32_t*>(&th);
    __nv_bfloat162 tl(__float2bfloat16_rn(x - __bfloat162float(hx)),
                      __float2bfloat16_rn(y - __bfloat162float(hy)));
    lo = *reinterpret_cast<uint32_t*>(&tl);
}

// ---------------------------------------------------------------------------
// fp32 -> bf16 hi|lo split
// ---------------------------------------------------------------------------
__global__ __launch_bounds__(256)
void split_kernel(const float* __restrict__ x, __nv_bfloat16* __restrict__ y)
{
    const int idx = blockIdx.x * 256 + threadIdx.x;
    const int row = idx >> 8;
    const int c4  = (idx & 255) * 4;
    const float4 v = *reinterpret_cast<const float4*>(x + ((size_t)row << 10) + c4);

    __nv_bfloat16 hx = __float2bfloat16_rn(v.x);
    __nv_bfloat16 hy = __float2bfloat16_rn(v.y);
    __nv_bfloat16 hz = __float2bfloat16_rn(v.z);
    __nv_bfloat16 hw = __float2bfloat16_rn(v.w);
    __nv_bfloat16 lx = __float2bfloat16_rn(v.x - __bfloat162float(hx));
    __nv_bfloat16 ly = __float2bfloat16_rn(v.y - __bfloat162float(hy));
    __nv_bfloat16 lz = __float2bfloat16_rn(v.z - __bfloat162float(hz));
    __nv_bfloat16 lw = __float2bfloat16_rn(v.w - __bfloat162float(hw));

    __nv_bfloat162* dh = reinterpret_cast<__nv_bfloat162*>(y + (size_t)row * K2_ + c4);
    dh[0] = __nv_bfloat162(hx, hy);
    dh[1] = __nv_bfloat162(hz, hw);
    __nv_bfloat162* dl = reinterpret_cast<__nv_bfloat162*>(y + (size_t)row * K2_ + 1024 + c4);
    dl[0] = __nv_bfloat162(lx, ly);
    dl[1] = __nv_bfloat162(lz, lw);
}

// ---------------------------------------------------------------------------
// mma.sync GEMM, 3-term split, 4-stage cp.async ring, 1 barrier per chunk
// grid = (8, M/128), 256 threads
// ---------------------------------------------------------------------------
#define BK 32
#define SROW 40
#define N_CHUNK 96
#define STAGES 4
#define STAGE_ELEMS (128 * SROW)
#define GEMM_SMEM_BYTES (STAGES * STAGE_ELEMS * 2 * 2)

__global__ __launch_bounds__(256, 2)
void mma_gemm_kernel(const __nv_bfloat16* __restrict__ A,
                     const __nv_bfloat16* __restrict__ W,
                     const float* __restrict__ bias,
                     float* __restrict__ C, float scale)
{
    extern __shared__ __nv_bfloat16 smem[];
    __nv_bfloat16* sA = smem;                          // [STAGES][STAGE_ELEMS]
    __nv_bfloat16* sB = smem + STAGES * STAGE_ELEMS;
    __shared__ float biasS[128];

    const int tid = threadIdx.x;
    const int wid = tid >> 5, lane = tid & 31;
    const int wm = wid & 3;
    const int wn = wid >> 2;
    const int bm = blockIdx.y * 128;
    const int bn = blockIdx.x * 128;

    if (tid < 128) biasS[tid] = bias[bn + tid];

    const __nv_bfloat16* Ag = A + (size_t)bm * K2_;
    const __nv_bfloat16* Wg = W + (size_t)bn * K2_;

    const int ldrow = tid >> 1;
    const int ldoff = (tid & 1) * 16;

    const uint32_t sAu = smem_u32(sA);
    const uint32_t sBu = smem_u32(sB);

    auto stage = [&](int c) {
        const int slot = c & (STAGES - 1);
        const int seg = c >> 5;
        const int col = (c & 31) * BK;
        const int gA = ((seg == 2) ? 1024 : 0) + col;   // A: hi,hi,lo
        const int gW = ((seg == 1) ? 1024 : 0) + col;   // W: hi,lo,hi
        const size_t ga = (size_t)ldrow * K2_ + gA + ldoff;
        const size_t gw = (size_t)ldrow * K2_ + gW + ldoff;
        const uint32_t sa = sAu + (slot * STAGE_ELEMS + ldrow * SROW + ldoff) * 2;
        const uint32_t sb = sBu + (slot * STAGE_ELEMS + ldrow * SROW + ldoff) * 2;
        CP_ASYNC16(sa,      Ag + ga);
        CP_ASYNC16(sa + 16, Ag + ga + 8);
        CP_ASYNC16(sb,      Wg + gw);
        CP_ASYNC16(sb + 16, Wg + gw + 8);
    };

    float acc[2][8][4];
#pragma unroll
    for (int mt = 0; mt < 2; mt++)
#pragma unroll
        for (int nf = 0; nf < 8; nf++)
#pragma unroll
            for (int r = 0; r < 4; r++) acc[mt][nf][r] = 0.f;

    stage(0); CP_COMMIT();
    stage(1); CP_COMMIT();
    stage(2); CP_COMMIT();

    const int lrow = lane & 15;
    const int lcol = (lane >> 4) * 16;

    for (int c = 0; c < N_CHUNK; ++c) {
        CP_WAIT2();
        __syncthreads();

        if (c + 3 < N_CHUNK) { stage(c + 3); CP_COMMIT(); }

        const int slot = c & (STAGES - 1);
        const uint32_t aBase = sAu + slot * STAGE_ELEMS * 2;
        const uint32_t bBase = sBu + slot * STAGE_ELEMS * 2;

#pragma unroll
        for (int kk = 0; kk < 2; kk++) {
            const int kbyte = kk * 32 + lcol;

            uint32_t a[2][4];
#pragma unroll
            for (int mt = 0; mt < 2; mt++) {
                const int row = wm * 32 + mt * 16 + lrow;
                ldmatrix_x4(a[mt][0], a[mt][1], a[mt][2], a[mt][3],
                            aBase + row * (SROW * 2) + kbyte);
            }
            uint32_t b[4][4];
#pragma unroll
            for (int nb = 0; nb < 4; nb++) {
                const int row = wn * 64 + nb * 16 + lrow;
                ldmatrix_x4(b[nb][0], b[nb][1], b[nb][2], b[nb][3],
                            bBase + row * (SROW * 2) + kbyte);
            }
#pragma unroll
            for (int mt = 0; mt < 2; mt++)
#pragma unroll
                for (int nf = 0; nf < 8; nf++) {
                    const int nb = nf >> 1;
                    const uint32_t b0 = (nf & 1) ? b[nb][1] : b[nb][0];
                    const uint32_t b1 = (nf & 1) ? b[nb][3] : b[nb][2];
                    mma_bf16(acc[mt][nf], a[mt][0], a[mt][1], a[mt][2], a[mt][3],
                             b0, b1);
                }
        }
    }

    const int g_  = lane >> 2;
    const int tig = lane & 3;
#pragma unroll
    for (int mt = 0; mt < 2; mt++) {
        const int row0 = bm + wm * 32 + mt * 16 + g_;
#pragma unroll
        for (int nf = 0; nf < 8; nf++) {
            const int col = wn * 64 + nf * 8 + tig * 2;
            const float b0 = biasS[col], b1 = biasS[col + 1];
            float2 o0, o1;
            o0.x = scale * (acc[mt][nf][0] + b0);
            o0.y = scale * (acc[mt][nf][1] + b1);
            o1.x = scale * (acc[mt][nf][2] + b0);
            o1.y = scale * (acc[mt][nf][3] + b1);
            *reinterpret_cast<float2*>(C + (size_t)row0 * 1024 + bn + col) = o0;
            *reinterpret_cast<float2*>(C + (size_t)(row0 + 8) * 1024 + bn + col) = o1;
        }
    }
}

// ---------------------------------------------------------------------------
// weights[b,h,s] = (tq . (mask @ tk)) / sum(mask)
// ---------------------------------------------------------------------------
__global__ __launch_bounds__(256)
void weights_kernel(const float* __restrict__ tq, const float* __restrict__ tk,
                    const float* __restrict__ mask, float* __restrict__ wgt)
{
    const int bh = blockIdx.x;
    const int b = bh >> 4;
    const int h = bh & 15;

    __shared__ float tks[TL_][HD_];

    const int tid = threadIdx.x;
    for (int idx = tid; idx < TL_ * HD_; idx += 256) {
        const int t = idx >> 6, d = idx & 63;
        tks[t][d] = tk[((size_t)b * TL_ + t) * D_ + h * HD_ + d];
    }
    __syncthreads();

    const int warp = tid >> 5, lane = tid & 31;

    for (int s = warp; s < S_; s += 8) {
        const size_t tqo = ((size_t)b * S_ + s) * D_ + h * HD_;
        const float tq0 = __ldg(&tq[tqo + lane]);
        const float tq1 = __ldg(&tq[tqo + lane + 32]);
        const float* mrow = mask + ((size_t)b * S_ + s) * TL_;

        float mk0 = 0.f, mk1 = 0.f, cnt = 0.f;
#pragma unroll
        for (int t = 0; t < TL_; t++) {
            const float m = __ldg(&mrow[t]);
            cnt += m;
            mk0 = fmaf(m, tks[t][lane], mk0);
            mk1 = fmaf(m, tks[t][lane + 32], mk1);
        }
        float dotv = tq0 * mk0 + tq1 * mk1;
#pragma unroll
        for (int off = 16; off; off >>= 1)
            dotv += __shfl_xor_sync(0xffffffffu, dotv, off);

        if (lane == 0)
            wgt[(size_t)bh * S_ + s] = dotv / cnt;
    }
}

// ---------------------------------------------------------------------------
// fast exp on FMA pipe
// ---------------------------------------------------------------------------
__device__ __forceinline__ float fast_exp(float x)
{
    const float y = x * 1.44269504088896341f;
    const float n = rintf(y);
    const float t = (y - n) * 0.69314718055994531f;
    float p = 1.9841269841e-4f;
    p = fmaf(p, t, 1.38888888889e-3f);
    p = fmaf(p, t, 8.33333333333e-3f);
    p = fmaf(p, t, 4.16666666667e-2f);
    p = fmaf(p, t, 1.66666666667e-1f);
    p = fmaf(p, t, 0.5f);
    p = fmaf(p, t, 1.0f);
    p = fmaf(p, t, 1.0f);
    int e = (int)n;
    e = e < -126 ? -126 : e;
    const float s = __int_as_float((e + 127) << 23);
    return p * s;
}

// ---------------------------------------------------------------------------
// Tensor-core flash attention, 128-row q tiles, row-major V + ldmatrix.trans.
//   grid = (T/128, B*H), 256 threads (8 warps x 16 q-rows).
// ---------------------------------------------------------------------------
#define VPAD 72

__global__ __launch_bounds__(256)
void attn_tc_kernel(const float* __restrict__ q, const float* __restrict__ k,
                    const float* __restrict__ v, const float* __restrict__ wgt,
                    float* __restrict__ ctx)
{
    __shared__ __nv_bfloat16 sQ [128 * VPAD];
    __shared__ __nv_bfloat16 sK [64 * VPAD];
    __shared__ __nv_bfloat16 sVh[64 * VPAD];   // row-major [s][d]
    __shared__ __nv_bfloat16 sVl[64 * VPAD];
    __shared__ float ws[64];

    const int qt = blockIdx.x, bh = blockIdx.y;
    const int b = bh >> 4, h = bh & 15;
    const int tid = threadIdx.x, wid = tid >> 5, lane = tid & 31;
    const int g = lane >> 2, tig = lane & 3;
    const int lrow = lane & 15, lcolb = (lane >> 4) * 16;

    // trans-ldmatrix lane addressing for PV: row = k-sub, col = n-sub
    const int trow = ((lane >> 3) & 1) * 8 + (lane & 7);
    const int tcol = (lane >> 4) * 8;

    // load Q tile (128 x 64) -> bf16
    const size_t qbase = ((size_t)b * T_ + qt * 128) * D_ + h * HD_;
#pragma unroll
    for (int it = 0; it < 8; ++it) {
        const int idx = it * 256 + tid;
        const int r = idx >> 4, c4 = (idx & 15) * 4;
        const float4 vq = *reinterpret_cast<const float4*>(q + qbase + (size_t)r * D_ + c4);
        __nv_bfloat162* dq = reinterpret_cast<__nv_bfloat162*>(&sQ[r * VPAD + c4]);
        dq[0] = __floats2bfloat162_rn(vq.x, vq.y);
        dq[1] = __floats2bfloat162_rn(vq.z, vq.w);
    }

    float o[8][4];
#pragma unroll
    for (int nf = 0; nf < 8; nf++)
#pragma unroll
        for (int r = 0; r < 4; r++) o[nf][r] = 0.f;
    float m0 = -1e30f, m1 = -1e30f, l0 = 0.f, l1 = 0.f;

    const uint32_t sQb = smem_u32(sQ), sKb = smem_u32(sK);
    const uint32_t sVhb = smem_u32(sVh), sVlb = smem_u32(sVl);

    const size_t kvbase = ((size_t)b * S_) * D_ + h * HD_;
    const float* wrow = wgt + (size_t)bh * S_;

    for (int sc = 0; sc < S_ / 64; ++sc) {
        __syncthreads();
        const size_t koff = kvbase + (size_t)sc * 64 * D_;
#pragma unroll
        for (int it = 0; it < 4; ++it) {
            const int idx = it * 256 + tid;
            const int r = idx >> 4, c4 = (idx & 15) * 4;
            const float4 kk = *reinterpret_cast<const float4*>(k + koff + (size_t)r * D_ + c4);
            __nv_bfloat162* dk = reinterpret_cast<__nv_bfloat162*>(&sK[r * VPAD + c4]);
            dk[0] = __floats2bfloat162_rn(kk.x, kk.y);
            dk[1] = __floats2bfloat162_rn(kk.z, kk.w);

            const float4 vv = *reinterpret_cast<const float4*>(v + koff + (size_t)r * D_ + c4);
            uint32_t h0, l0r, h1, l1r;
            split_pair(vv.x, vv.y, h0, l0r);
            split_pair(vv.z, vv.w, h1, l1r);
            uint32_t* dvh = reinterpret_cast<uint32_t*>(&sVh[r * VPAD + c4]);
            dvh[0] = h0; dvh[1] = h1;
            uint32_t* dvl = reinterpret_cast<uint32_t*>(&sVl[r * VPAD + c4]);
            dvl[0] = l0r; dvl[1] = l1r;
        }
        if (tid < 64) ws[tid] = wrow[sc * 64 + tid];
        __syncthreads();

        // ---- S = Q @ K^T (bf16 mma)
        float sv[8][4];
#pragma unroll
        for (int nf = 0; nf < 8; nf++)
#pragma unroll
            for (int r = 0; r < 4; r++) sv[nf][r] = 0.f;

#pragma unroll
        for (int kk = 0; kk < 4; kk++) {
            const int kb = kk * 32 + lcolb;
            uint32_t a0, a1, a2, a3;
            ldmatrix_x4(a0, a1, a2, a3,
                        sQb + (wid * 16 + lrow) * (VPAD * 2) + kb);
#pragma unroll
            for (int nb = 0; nb < 4; nb++) {
                uint32_t b0, b1, b2, b3;
                ldmatrix_x4(b0, b1, b2, b3,
                            sKb + (nb * 16 + lrow) * (VPAD * 2) + kb);
                mma_bf16(sv[2 * nb],     a0, a1, a2, a3, b0, b2);
                mma_bf16(sv[2 * nb + 1], a0, a1, a2, a3, b1, b3);
            }
        }

        // ---- per-key-column weight scaling
#pragma unroll
        for (int nf = 0; nf < 8; nf++) {
            const int col = nf * 8 + tig * 2;
            const float w0 = ws[col], w1 = ws[col + 1];
            sv[nf][0] *= w0; sv[nf][1] *= w1;
            sv[nf][2] *= w0; sv[nf][3] *= w1;
        }

        // ---- online softmax
        float mx0 = -1e30f, mx1 = -1e30f;
#pragma unroll
        for (int nf = 0; nf < 8; nf++) {
            mx0 = fmaxf(mx0, fmaxf(sv[nf][0], sv[nf][1]));
            mx1 = fmaxf(mx1, fmaxf(sv[nf][2], sv[nf][3]));
        }
        mx0 = fmaxf(mx0, __shfl_xor_sync(0xffffffffu, mx0, 1));
        mx0 = fmaxf(mx0, __shfl_xor_sync(0xffffffffu, mx0, 2));
        mx1 = fmaxf(mx1, __shfl_xor_sync(0xffffffffu, mx1, 1));
        mx1 = fmaxf(mx1, __shfl_xor_sync(0xffffffffu, mx1, 2));

        const float mn0 = fmaxf(m0, mx0), mn1 = fmaxf(m1, mx1);
        const float al0 = fast_exp(m0 - mn0), al1 = fast_exp(m1 - mn1);
        m0 = mn0; m1 = mn1;

        float s0 = 0.f, s1 = 0.f;
#pragma unroll
        for (int nf = 0; nf < 8; nf++) {
            sv[nf][0] = fast_exp(sv[nf][0] - mn0);
            sv[nf][1] = fast_exp(sv[nf][1] - mn0);
            sv[nf][2] = fast_exp(sv[nf][2] - mn1);
            sv[nf][3] = fast_exp(sv[nf][3] - mn1);
            s0 += sv[nf][0] + sv[nf][1];
            s1 += sv[nf][2] + sv[nf][3];
        }
        s0 += __shfl_xor_sync(0xffffffffu, s0, 1);
        s0 += __shfl_xor_sync(0xffffffffu, s0, 2);
        s1 += __shfl_xor_sync(0xffffffffu, s1, 1);
        s1 += __shfl_xor_sync(0xffffffffu, s1, 2);
        l0 = l0 * al0 + s0;
        l1 = l1 * al1 + s1;

#pragma unroll
        for (int nf = 0; nf < 8; nf++) {
            o[nf][0] *= al0; o[nf][1] *= al0;
            o[nf][2] *= al1; o[nf][3] *= al1;
        }

        // ---- O += P @ V  (3-term hi/lo; V row-major + ldmatrix.trans)
#pragma unroll
        for (int j = 0; j < 4; j++) {          // k16 groups over s
            uint32_t ph[4], pl[4];
            split_pair(sv[2 * j][0],     sv[2 * j][1],     ph[0], pl[0]);
            split_pair(sv[2 * j][2],     sv[2 * j][3],     ph[1], pl[1]);
            split_pair(sv[2 * j + 1][0], sv[2 * j + 1][1], ph[2], pl[2]);
            split_pair(sv[2 * j + 1][2], sv[2 * j + 1][3], ph[3], pl[3]);

            const uint32_t vrow = (j * 16 + trow) * (VPAD * 2);
#pragma unroll
            for (int nb = 0; nb < 4; nb++) {
                const uint32_t vaddr = vrow + (nb * 16 + tcol) * 2;
                uint32_t h0, h1, h2, h3, q0, q1, q2, q3;
                ldmatrix_x4_trans(h0, h1, h2, h3, sVhb + vaddr);
                ldmatrix_x4_trans(q0, q1, q2, q3, sVlb + vaddr);
                mma_bf16(o[2 * nb],     ph[0], ph[1], ph[2], ph[3], h0, h1);
                mma_bf16(o[2 * nb + 1], ph[0], ph[1], ph[2], ph[3], h2, h3);
                mma_bf16(o[2 * nb],     ph[0], ph[1], ph[2], ph[3], q0, q1);
                mma_bf16(o[2 * nb + 1], ph[0], ph[1], ph[2], ph[3], q2, q3);
                mma_bf16(o[2 * nb],     pl[0], pl[1], pl[2], pl[3], h0, h1);
                mma_bf16(o[2 * nb + 1], pl[0], pl[1], pl[2], pl[3], h2, h3);
            }
        }
    }

    // ---- epilogue
    const float inv0 = 1.0f / l0, inv1 = 1.0f / l1;
    const int row0 = qt * 128 + wid * 16 + g;
#pragma unroll
    for (int nf = 0; nf < 8; nf++) {
        const int col = h * HD_ + nf * 8 + tig * 2;
        float2 w0, w1;
        w0.x = o[nf][0] * inv0; w0.y = o[nf][1] * inv0;
        w1.x = o[nf][2] * inv1; w1.y = o[nf][3] * inv1;
        *reinterpret_cast<float2*>(&ctx[((size_t)b * T_ + row0) * D_ + col]) = w0;
        *reinterpret_cast<float2*>(&ctx[((size_t)b * T_ + row0 + 8) * D_ + col]) = w1;
    }
}

// ---------------------------------------------------------------------------
// launch
// ---------------------------------------------------------------------------
extern "C" void kernel_launch(void* const* d_in, const int* in_sizes, int n_in,
                              void* d_out, int out_size)
{
    const float* hidden = (const float*)d_in[0];
    const float* kv     = (const float*)d_in[1];
    const float* target = (const float*)d_in[2];
    const float* mask   = (const float*)d_in[3];
    const float* Wq  = (const float*)d_in[4];
    const float* bq  = (const float*)d_in[5];
    const float* Wk  = (const float*)d_in[6];
    const float* bk  = (const float*)d_in[7];
    const float* Wv  = (const float*)d_in[8];
    const float* bv  = (const float*)d_in[9];
    const float* Wwq = (const float*)d_in[10];
    const float* bwq = (const float*)d_in[11];
    const float* Wwk = (const float*)d_in[12];
    const float* bwk = (const float*)d_in[13];
    const float* Wo  = (const float*)d_in[14];
    const float* bo  = (const float*)d_in[15];
    float* out = (float*)d_out;

    float *q, *k, *v, *tq, *tk, *w, *ctx;
    cudaGetSymbolAddress((void**)&q,   g_q);
    cudaGetSymbolAddress((void**)&k,   g_k);
    cudaGetSymbolAddress((void**)&v,   g_v);
    cudaGetSymbolAddress((void**)&tq,  g_tq);
    cudaGetSymbolAddress((void**)&tk,  g_tk);
    cudaGetSymbolAddress((void**)&w,   g_w);
    cudaGetSymbolAddress((void**)&ctx, g_ctx);

    __nv_bfloat16 *hA, *kvA, *tA, *ctxA, *Wq2, *Wk2, *Wv2, *Wwq2, *Wwk2, *Wo2;
    cudaGetSymbolAddress((void**)&hA,   g_hA);
    cudaGetSymbolAddress((void**)&kvA,  g_kvA);
    cudaGetSymbolAddress((void**)&tA,   g_tA);
    cudaGetSymbolAddress((void**)&ctxA, g_ctxA);
    cudaGetSymbolAddress((void**)&Wq2,  g_Wq2);
    cudaGetSymbolAddress((void**)&Wk2,  g_Wk2);
    cudaGetSymbolAddress((void**)&Wv2,  g_Wv2);
    cudaGetSymbolAddress((void**)&Wwq2, g_Wwq2);
    cudaGetSymbolAddress((void**)&Wwk2, g_Wwk2);
    cudaGetSymbolAddress((void**)&Wo2,  g_Wo2);

    // 1) fp32 -> bf16 hi|lo splits
    split_kernel<<<B_ * T_,  256>>>(hidden, hA);
    split_kernel<<<B_ * S_,  256>>>(kv,     kvA);
    split_kernel<<<B_ * TL_, 256>>>(target, tA);
    split_kernel<<<D_, 256>>>(Wq,  Wq2);
    split_kernel<<<D_, 256>>>(Wk,  Wk2);
    split_kernel<<<D_, 256>>>(Wv,  Wv2);
    split_kernel<<<D_, 256>>>(Wwq, Wwq2);
    split_kernel<<<D_, 256>>>(Wwk, Wwk2);
    split_kernel<<<D_, 256>>>(Wo,  Wo2);

    // 2) tensor-core projections (mma.sync, 3-term split, 4-stage)
    cudaFuncSetAttribute(mma_gemm_kernel,
                         cudaFuncAttributeMaxDynamicSharedMemorySize, GEMM_SMEM_BYTES);
    mma_gemm_kernel<<<dim3(8, (B_ * T_) / 128), 256, GEMM_SMEM_BYTES>>>(hA, Wq2, bq, q, SCALING_);
    mma_gemm_kernel<<<dim3(8, (B_ * S_) / 128), 256, GEMM_SMEM_BYTES>>>(kvA, Wk2, bk, k, 1.0f);
    mma_gemm_kernel<<<dim3(8, (B_ * S_) / 128), 256, GEMM_SMEM_BYTES>>>(kvA, Wv2, bv, v, 1.0f);
    mma_gemm_kernel<<<dim3(8, (B_ * S_) / 128), 256, GEMM_SMEM_BYTES>>>(kvA, Wwq2, bwq, tq, SCALING_);
    mma_gemm_kernel<<<dim3(8, (B_ * TL_) / 128), 256, GEMM_SMEM_BYTES>>>(tA, Wwk2, bwk, tk, 1.0f);

    // 3) masked-mean weights
    weights_kernel<<<B_ * H_, 256>>>(tq, tk, mask, w);

    // 4) tensor-core flash attention (128-row q tiles)
    attn_tc_kernel<<<dim3(T_ / 128, B_ * H_), 256>>>(q, k, v, w, ctx);

    // 5) output projection
    split_kernel<<<B_ * T_, 256>>>(ctx, ctxA);
    mma_gemm_kernel<<<dim3(8, (B_ * T_) / 128), 256, GEMM_SMEM_BYTES>>>(ctxA, Wo2, bo, out, 1.0f);
}

// round 9
// speedup vs baseline: 1.8739x; 1.0698x over previous
#include <cuda_runtime.h>
#include <cuda_bf16.h>
#include <cstdint>

// ============================================================================
// KTMutualAttention — mma.sync (bf16) 3-term split GEMMs (4-stage pipeline,
//   fused k/v/tq launch) + mma.sync flash attention (128-row q tiles, trans-V)
//   B=8, T=512, S=1024, TL=64, D=1024, H=16, hd=64
// Launch order places a GEMM at index 5 so ncu (-s 5 -c 1) profiles it.
// ============================================================================

#define B_   8
#define T_   512
#define S_   1024
#define TL_  64
#define D_   1024
#define H_   16
#define HD_  64
#define SCALING_ 0.125f
#define K2_  2048          // stored split width ([hi|lo])

// ---------------------------------------------------------------------------
// scratch (device globals; no allocations allowed)
// ---------------------------------------------------------------------------
__device__ __align__(256) float g_q  [B_ * T_ * D_];
__device__ __align__(256) float g_k  [B_ * S_ * D_];
__device__ __align__(256) float g_v  [B_ * S_ * D_];
__device__ __align__(256) float g_tq [B_ * S_ * D_];
__device__ __align__(256) float g_tk [B_ * TL_ * D_];
__device__ __align__(256) float g_w  [B_ * H_ * S_];
__device__ __align__(256) float g_ctx[B_ * T_ * D_];

__device__ __align__(256) __nv_bfloat16 g_hA  [(size_t)B_ * T_  * K2_];
__device__ __align__(256) __nv_bfloat16 g_kvA [(size_t)B_ * S_  * K2_];
__device__ __align__(256) __nv_bfloat16 g_tA  [(size_t)B_ * TL_ * K2_];
__device__ __align__(256) __nv_bfloat16 g_ctxA[(size_t)B_ * T_  * K2_];
__device__ __align__(256) __nv_bfloat16 g_Wq2 [(size_t)D_ * K2_];
__device__ __align__(256) __nv_bfloat16 g_Wk2 [(size_t)D_ * K2_];
__device__ __align__(256) __nv_bfloat16 g_Wv2 [(size_t)D_ * K2_];
__device__ __align__(256) __nv_bfloat16 g_Wwq2[(size_t)D_ * K2_];
__device__ __align__(256) __nv_bfloat16 g_Wwk2[(size_t)D_ * K2_];
__device__ __align__(256) __nv_bfloat16 g_Wo2 [(size_t)D_ * K2_];

// ---------------------------------------------------------------------------
// PTX helpers (portable sm_80+)
// ---------------------------------------------------------------------------
__device__ __forceinline__ uint32_t smem_u32(const void* p) {
    uint32_t a;
    asm("{ .reg .u64 t; cvta.to.shared.u64 t, %1; cvt.u32.u64 %0, t; }"
        : "=r"(a) : "l"(p));
    return a;
}

#define CP_ASYNC16(dst_u32, src_ptr) \
    asm volatile("cp.async.cg.shared.global [%0], [%1], 16;" \
                 :: "r"(dst_u32), "l"(src_ptr) : "memory")
#define CP_COMMIT() asm volatile("cp.async.commit_group;" ::: "memory")
#define CP_WAIT2()  asm volatile("cp.async.wait_group 2;" ::: "memory")

__device__ __forceinline__ void ldmatrix_x4(uint32_t& r0, uint32_t& r1,
                                            uint32_t& r2, uint32_t& r3,
                                            uint32_t addr)
{
    asm volatile("ldmatrix.sync.aligned.m8n8.x4.shared.b16 {%0,%1,%2,%3}, [%4];"
                 : "=r"(r0), "=r"(r1), "=r"(r2), "=r"(r3) : "r"(addr));
}

__device__ __forceinline__ void ldmatrix_x4_trans(uint32_t& r0, uint32_t& r1,
                                                  uint32_t& r2, uint32_t& r3,
                                                  uint32_t addr)
{
    asm volatile("ldmatrix.sync.aligned.m8n8.x4.trans.shared.b16 {%0,%1,%2,%3}, [%4];"
                 : "=r"(r0), "=r"(r1), "=r"(r2), "=r"(r3) : "r"(addr));
}

__device__ __forceinline__ void mma_bf16(float* c, uint32_t a0, uint32_t a1,
                                         uint32_t a2, uint32_t a3,
                                         uint32_t b0, uint32_t b1)
{
    asm volatile(
        "mma.sync.aligned.m16n8k16.row.col.f32.bf16.bf16.f32 "
        "{%0,%1,%2,%3}, {%4,%5,%6,%7}, {%8,%9}, {%0,%1,%2,%3};"
        : "+f"(c[0]), "+f"(c[1]), "+f"(c[2]), "+f"(c[3])
        : "r"(a0), "r"(a1), "r"(a2), "r"(a3), "r"(b0), "r"(b1));
}

__device__ __forceinline__ void split_pair(float x, float y,
                                           uint32_t& hi, uint32_t& lo)
{
    __nv_bfloat16 hx = __float2bfloat16_rn(x);
    __nv_bfloat16 hy = __float2bfloat16_rn(y);
    __nv_bfloat162 th(hx, hy);
    hi = *reinterpret_cast<uint32_t*>(&th);
    __nv_bfloat162 tl(__float2bfloat16_rn(x - __bfloat162float(hx)),
                      __float2bfloat16_rn(y - __bfloat162float(hy)));
    lo = *reinterpret_cast<uint32_t*>(&tl);
}

// ---------------------------------------------------------------------------
// fp32 -> bf16 hi|lo split
// ---------------------------------------------------------------------------
__global__ __launch_bounds__(256)
void split_kernel(const float* __restrict__ x, __nv_bfloat16* __restrict__ y)
{
    const int idx = blockIdx.x * 256 + threadIdx.x;
    const int row = idx >> 8;
    const int c4  = (idx & 255) * 4;
    const float4 v = *reinterpret_cast<const float4*>(x + ((size_t)row << 10) + c4);

    __nv_bfloat16 hx = __float2bfloat16_rn(v.x);
    __nv_bfloat16 hy = __float2bfloat16_rn(v.y);
    __nv_bfloat16 hz = __float2bfloat16_rn(v.z);
    __nv_bfloat16 hw = __float2bfloat16_rn(v.w);
    __nv_bfloat16 lx = __float2bfloat16_rn(v.x - __bfloat162float(hx));
    __nv_bfloat16 ly = __float2bfloat16_rn(v.y - __bfloat162float(hy));
    __nv_bfloat16 lz = __float2bfloat16_rn(v.z - __bfloat162float(hz));
    __nv_bfloat16 lw = __float2bfloat16_rn(v.w - __bfloat162float(hw));

    __nv_bfloat162* dh = reinterpret_cast<__nv_bfloat162*>(y + (size_t)row * K2_ + c4);
    dh[0] = __nv_bfloat162(hx, hy);
    dh[1] = __nv_bfloat162(hz, hw);
    __nv_bfloat162* dl = reinterpret_cast<__nv_bfloat162*>(y + (size_t)row * K2_ + 1024 + c4);
    dl[0] = __nv_bfloat162(lx, ly);
    dl[1] = __nv_bfloat162(lz, lw);
}

// ---------------------------------------------------------------------------
// GEMM core: C[bm:+128, bn:+128] = scale*(A@W^T + bias), 3-term split,
// 4-stage cp.async ring, 1 barrier per chunk. 256 threads.
// ---------------------------------------------------------------------------
#define BK 32
#define SROW 40
#define N_CHUNK 96
#define STAGES 4
#define STAGE_ELEMS (128 * SROW)
#define GEMM_SMEM_BYTES (STAGES * STAGE_ELEMS * 2 * 2)

__device__ __forceinline__
void gemm_core(const __nv_bfloat16* __restrict__ A,
               const __nv_bfloat16* __restrict__ W,
               const float* __restrict__ bias,
               float* __restrict__ C, float scale,
               int bm, int bn, __nv_bfloat16* smem)
{
    __nv_bfloat16* sA = smem;
    __nv_bfloat16* sB = smem + STAGES * STAGE_ELEMS;
    __shared__ float biasS[128];

    const int tid = threadIdx.x;
    const int wid = tid >> 5, lane = tid & 31;
    const int wm = wid & 3;
    const int wn = wid >> 2;

    if (tid < 128) biasS[tid] = bias[bn + tid];

    const __nv_bfloat16* Ag = A + (size_t)bm * K2_;
    const __nv_bfloat16* Wg = W + (size_t)bn * K2_;

    const int ldrow = tid >> 1;
    const int ldoff = (tid & 1) * 16;

    const uint32_t sAu = smem_u32(sA);
    const uint32_t sBu = smem_u32(sB);

    auto stage = [&](int c) {
        const int slot = c & (STAGES - 1);
        const int seg = c >> 5;
        const int col = (c & 31) * BK;
        const int gA = ((seg == 2) ? 1024 : 0) + col;   // A: hi,hi,lo
        const int gW = ((seg == 1) ? 1024 : 0) + col;   // W: hi,lo,hi
        const size_t ga = (size_t)ldrow * K2_ + gA + ldoff;
        const size_t gw = (size_t)ldrow * K2_ + gW + ldoff;
        const uint32_t sa = sAu + (slot * STAGE_ELEMS + ldrow * SROW + ldoff) * 2;
        const uint32_t sb = sBu + (slot * STAGE_ELEMS + ldrow * SROW + ldoff) * 2;
        CP_ASYNC16(sa,      Ag + ga);
        CP_ASYNC16(sa + 16, Ag + ga + 8);
        CP_ASYNC16(sb,      Wg + gw);
        CP_ASYNC16(sb + 16, Wg + gw + 8);
    };

    float acc[2][8][4];
#pragma unroll
    for (int mt = 0; mt < 2; mt++)
#pragma unroll
        for (int nf = 0; nf < 8; nf++)
#pragma unroll
            for (int r = 0; r < 4; r++) acc[mt][nf][r] = 0.f;

    stage(0); CP_COMMIT();
    stage(1); CP_COMMIT();
    stage(2); CP_COMMIT();

    const int lrow = lane & 15;
    const int lcol = (lane >> 4) * 16;

    for (int c = 0; c < N_CHUNK; ++c) {
        CP_WAIT2();
        __syncthreads();

        if (c + 3 < N_CHUNK) { stage(c + 3); CP_COMMIT(); }

        const int slot = c & (STAGES - 1);
        const uint32_t aBase = sAu + slot * STAGE_ELEMS * 2;
        const uint32_t bBase = sBu + slot * STAGE_ELEMS * 2;

#pragma unroll
        for (int kk = 0; kk < 2; kk++) {
            const int kbyte = kk * 32 + lcol;

            uint32_t a[2][4];
#pragma unroll
            for (int mt = 0; mt < 2; mt++) {
                const int row = wm * 32 + mt * 16 + lrow;
                ldmatrix_x4(a[mt][0], a[mt][1], a[mt][2], a[mt][3],
                            aBase + row * (SROW * 2) + kbyte);
            }
            uint32_t b[4][4];
#pragma unroll
            for (int nb = 0; nb < 4; nb++) {
                const int row = wn * 64 + nb * 16 + lrow;
                ldmatrix_x4(b[nb][0], b[nb][1], b[nb][2], b[nb][3],
                            bBase + row * (SROW * 2) + kbyte);
            }
#pragma unroll
            for (int mt = 0; mt < 2; mt++)
#pragma unroll
                for (int nf = 0; nf < 8; nf++) {
                    const int nb = nf >> 1;
                    const uint32_t b0 = (nf & 1) ? b[nb][1] : b[nb][0];
                    const uint32_t b1 = (nf & 1) ? b[nb][3] : b[nb][2];
                    mma_bf16(acc[mt][nf], a[mt][0], a[mt][1], a[mt][2], a[mt][3],
                             b0, b1);
                }
        }
    }

    const int g_  = lane >> 2;
    const int tig = lane & 3;
#pragma unroll
    for (int mt = 0; mt < 2; mt++) {
        const int row0 = bm + wm * 32 + mt * 16 + g_;
#pragma unroll
        for (int nf = 0; nf < 8; nf++) {
            const int col = wn * 64 + nf * 8 + tig * 2;
            const float b0 = biasS[col], b1 = biasS[col + 1];
            float2 o0, o1;
            o0.x = scale * (acc[mt][nf][0] + b0);
            o0.y = scale * (acc[mt][nf][1] + b1);
            o1.x = scale * (acc[mt][nf][2] + b0);
            o1.y = scale * (acc[mt][nf][3] + b1);
            *reinterpret_cast<float2*>(C + (size_t)row0 * 1024 + bn + col) = o0;
            *reinterpret_cast<float2*>(C + (size_t)(row0 + 8) * 1024 + bn + col) = o1;
        }
    }
}

__global__ __launch_bounds__(256, 2)
void mma_gemm_kernel(const __nv_bfloat16* __restrict__ A,
                     const __nv_bfloat16* __restrict__ W,
                     const float* __restrict__ bias,
                     float* __restrict__ C, float scale)
{
    extern __shared__ __nv_bfloat16 smem[];
    gemm_core(A, W, bias, C, scale, blockIdx.y * 128, blockIdx.x * 128, smem);
}

// fused k / v / tq (same A): blockIdx.z selects output
__global__ __launch_bounds__(256, 2)
void mma_gemm3_kernel(const __nv_bfloat16* __restrict__ A,
                      const __nv_bfloat16* __restrict__ W0,
                      const float* __restrict__ b0, float* __restrict__ C0,
                      const __nv_bfloat16* __restrict__ W1,
                      const float* __restrict__ b1, float* __restrict__ C1,
                      const __nv_bfloat16* __restrict__ W2,
                      const float* __restrict__ b2, float* __restrict__ C2,
                      float scale2)
{
    extern __shared__ __nv_bfloat16 smem[];
    const int z = blockIdx.z;
    const __nv_bfloat16* W = (z == 0) ? W0 : (z == 1) ? W1 : W2;
    const float* bias      = (z == 0) ? b0 : (z == 1) ? b1 : b2;
    float* C               = (z == 0) ? C0 : (z == 1) ? C1 : C2;
    const float scale      = (z == 2) ? scale2 : 1.0f;
    gemm_core(A, W, bias, C, scale, blockIdx.y * 128, blockIdx.x * 128, smem);
}

// ---------------------------------------------------------------------------
// weights[b,h,s] = (tq . (mask @ tk)) / sum(mask)
// ---------------------------------------------------------------------------
__global__ __launch_bounds__(256)
void weights_kernel(const float* __restrict__ tq, const float* __restrict__ tk,
                    const float* __restrict__ mask, float* __restrict__ wgt)
{
    const int bh = blockIdx.x;
    const int b = bh >> 4;
    const int h = bh & 15;

    __shared__ float tks[TL_][HD_];

    const int tid = threadIdx.x;
    for (int idx = tid; idx < TL_ * HD_; idx += 256) {
        const int t = idx >> 6, d = idx & 63;
        tks[t][d] = tk[((size_t)b * TL_ + t) * D_ + h * HD_ + d];
    }
    __syncthreads();

    const int warp = tid >> 5, lane = tid & 31;

    for (int s = warp; s < S_; s += 8) {
        const size_t tqo = ((size_t)b * S_ + s) * D_ + h * HD_;
        const float tq0 = __ldg(&tq[tqo + lane]);
        const float tq1 = __ldg(&tq[tqo + lane + 32]);
        const float* mrow = mask + ((size_t)b * S_ + s) * TL_;

        float mk0 = 0.f, mk1 = 0.f, cnt = 0.f;
#pragma unroll
        for (int t = 0; t < TL_; t++) {
            const float m = __ldg(&mrow[t]);
            cnt += m;
            mk0 = fmaf(m, tks[t][lane], mk0);
            mk1 = fmaf(m, tks[t][lane + 32], mk1);
        }
        float dotv = tq0 * mk0 + tq1 * mk1;
#pragma unroll
        for (int off = 16; off; off >>= 1)
            dotv += __shfl_xor_sync(0xffffffffu, dotv, off);

        if (lane == 0)
            wgt[(size_t)bh * S_ + s] = dotv / cnt;
    }
}

// ---------------------------------------------------------------------------
// fast exp on FMA pipe
// ---------------------------------------------------------------------------
__device__ __forceinline__ float fast_exp(float x)
{
    const float y = x * 1.44269504088896341f;
    const float n = rintf(y);
    const float t = (y - n) * 0.69314718055994531f;
    float p = 1.9841269841e-4f;
    p = fmaf(p, t, 1.38888888889e-3f);
    p = fmaf(p, t, 8.33333333333e-3f);
    p = fmaf(p, t, 4.16666666667e-2f);
    p = fmaf(p, t, 1.66666666667e-1f);
    p = fmaf(p, t, 0.5f);
    p = fmaf(p, t, 1.0f);
    p = fmaf(p, t, 1.0f);
    int e = (int)n;
    e = e < -126 ? -126 : e;
    const float s = __int_as_float((e + 127) << 23);
    return p * s;
}

// ---------------------------------------------------------------------------
// Tensor-core flash attention, 128-row q tiles, row-major V + ldmatrix.trans.
// ---------------------------------------------------------------------------
#define VPAD 72

__global__ __launch_bounds__(256)
void attn_tc_kernel(const float* __restrict__ q, const float* __restrict__ k,
                    const float* __restrict__ v, const float* __restrict__ wgt,
                    float* __restrict__ ctx)
{
    __shared__ __nv_bfloat16 sQ [128 * VPAD];
    __shared__ __nv_bfloat16 sK [64 * VPAD];
    __shared__ __nv_bfloat16 sVh[64 * VPAD];
    __shared__ __nv_bfloat16 sVl[64 * VPAD];
    __shared__ float ws[64];

    const int qt = blockIdx.x, bh = blockIdx.y;
    const int b = bh >> 4, h = bh & 15;
    const int tid = threadIdx.x, wid = tid >> 5, lane = tid & 31;
    const int g = lane >> 2, tig = lane & 3;
    const int lrow = lane & 15, lcolb = (lane >> 4) * 16;

    const int trow = ((lane >> 3) & 1) * 8 + (lane & 7);
    const int tcol = (lane >> 4) * 8;

    const size_t qbase = ((size_t)b * T_ + qt * 128) * D_ + h * HD_;
#pragma unroll
    for (int it = 0; it < 8; ++it) {
        const int idx = it * 256 + tid;
        const int r = idx >> 4, c4 = (idx & 15) * 4;
        const float4 vq = *reinterpret_cast<const float4*>(q + qbase + (size_t)r * D_ + c4);
        __nv_bfloat162* dq = reinterpret_cast<__nv_bfloat162*>(&sQ[r * VPAD + c4]);
        dq[0] = __floats2bfloat162_rn(vq.x, vq.y);
        dq[1] = __floats2bfloat162_rn(vq.z, vq.w);
    }

    float o[8][4];
#pragma unroll
    for (int nf = 0; nf < 8; nf++)
#pragma unroll
        for (int r = 0; r < 4; r++) o[nf][r] = 0.f;
    float m0 = -1e30f, m1 = -1e30f, l0 = 0.f, l1 = 0.f;

    const uint32_t sQb = smem_u32(sQ), sKb = smem_u32(sK);
    const uint32_t sVhb = smem_u32(sVh), sVlb = smem_u32(sVl);

    const size_t kvbase = ((size_t)b * S_) * D_ + h * HD_;
    const float* wrow = wgt + (size_t)bh * S_;

    for (int sc = 0; sc < S_ / 64; ++sc) {
        __syncthreads();
        const size_t koff = kvbase + (size_t)sc * 64 * D_;
#pragma unroll
        for (int it = 0; it < 4; ++it) {
            const int idx = it * 256 + tid;
            const int r = idx >> 4, c4 = (idx & 15) * 4;
            const float4 kk = *reinterpret_cast<const float4*>(k + koff + (size_t)r * D_ + c4);
            __nv_bfloat162* dk = reinterpret_cast<__nv_bfloat162*>(&sK[r * VPAD + c4]);
            dk[0] = __floats2bfloat162_rn(kk.x, kk.y);
            dk[1] = __floats2bfloat162_rn(kk.z, kk.w);

            const float4 vv = *reinterpret_cast<const float4*>(v + koff + (size_t)r * D_ + c4);
            uint32_t h0, l0r, h1, l1r;
            split_pair(vv.x, vv.y, h0, l0r);
            split_pair(vv.z, vv.w, h1, l1r);
            uint32_t* dvh = reinterpret_cast<uint32_t*>(&sVh[r * VPAD + c4]);
            dvh[0] = h0; dvh[1] = h1;
            uint32_t* dvl = reinterpret_cast<uint32_t*>(&sVl[r * VPAD + c4]);
            dvl[0] = l0r; dvl[1] = l1r;
        }
        if (tid < 64) ws[tid] = wrow[sc * 64 + tid];
        __syncthreads();

        float sv[8][4];
#pragma unroll
        for (int nf = 0; nf < 8; nf++)
#pragma unroll
            for (int r = 0; r < 4; r++) sv[nf][r] = 0.f;

#pragma unroll
        for (int kk = 0; kk < 4; kk++) {
            const int kb = kk * 32 + lcolb;
            uint32_t a0, a1, a2, a3;
            ldmatrix_x4(a0, a1, a2, a3,
                        sQb + (wid * 16 + lrow) * (VPAD * 2) + kb);
#pragma unroll
            for (int nb = 0; nb < 4; nb++) {
                uint32_t b0, b1, b2, b3;
                ldmatrix_x4(b0, b1, b2, b3,
                            sKb + (nb * 16 + lrow) * (VPAD * 2) + kb);
                mma_bf16(sv[2 * nb],     a0, a1, a2, a3, b0, b2);
                mma_bf16(sv[2 * nb + 1], a0, a1, a2, a3, b1, b3);
            }
        }

#pragma unroll
        for (int nf = 0; nf < 8; nf++) {
            const int col = nf * 8 + tig * 2;
            const float w0 = ws[col], w1 = ws[col + 1];
            sv[nf][0] *= w0; sv[nf][1] *= w1;
            sv[nf][2] *= w0; sv[nf][3] *= w1;
        }

        float mx0 = -1e30f, mx1 = -1e30f;
#pragma unroll
        for (int nf = 0; nf < 8; nf++) {
            mx0 = fmaxf(mx0, fmaxf(sv[nf][0], sv[nf][1]));
            mx1 = fmaxf(mx1, fmaxf(sv[nf][2], sv[nf][3]));
        }
        mx0 = fmaxf(mx0, __shfl_xor_sync(0xffffffffu, mx0, 1));
        mx0 = fmaxf(mx0, __shfl_xor_sync(0xffffffffu, mx0, 2));
        mx1 = fmaxf(mx1, __shfl_xor_sync(0xffffffffu, mx1, 1));
        mx1 = fmaxf(mx1, __shfl_xor_sync(0xffffffffu, mx1, 2));

        const float mn0 = fmaxf(m0, mx0), mn1 = fmaxf(m1, mx1);
        const float al0 = fast_exp(m0 - mn0), al1 = fast_exp(m1 - mn1);
        m0 = mn0; m1 = mn1;

        float s0 = 0.f, s1 = 0.f;
#pragma unroll
        for (int nf = 0; nf < 8; nf++) {
            sv[nf][0] = fast_exp(sv[nf][0] - mn0);
            sv[nf][1] = fast_exp(sv[nf][1] - mn0);
            sv[nf][2] = fast_exp(sv[nf][2] - mn1);
            sv[nf][3] = fast_exp(sv[nf][3] - mn1);
            s0 += sv[nf][0] + sv[nf][1];
            s1 += sv[nf][2] + sv[nf][3];
        }
        s0 += __shfl_xor_sync(0xffffffffu, s0, 1);
        s0 += __shfl_xor_sync(0xffffffffu, s0, 2);
        s1 += __shfl_xor_sync(0xffffffffu, s1, 1);
        s1 += __shfl_xor_sync(0xffffffffu, s1, 2);
        l0 = l0 * al0 + s0;
        l1 = l1 * al1 + s1;

#pragma unroll
        for (int nf = 0; nf < 8; nf++) {
            o[nf][0] *= al0; o[nf][1] *= al0;
            o[nf][2] *= al1; o[nf][3] *= al1;
        }

#pragma unroll
        for (int j = 0; j < 4; j++) {
            uint32_t ph[4], pl[4];
            split_pair(sv[2 * j][0],     sv[2 * j][1],     ph[0], pl[0]);
            split_pair(sv[2 * j][2],     sv[2 * j][3],     ph[1], pl[1]);
            split_pair(sv[2 * j + 1][0], sv[2 * j + 1][1], ph[2], pl[2]);
            split_pair(sv[2 * j + 1][2], sv[2 * j + 1][3], ph[3], pl[3]);

            const uint32_t vrow = (j * 16 + trow) * (VPAD * 2);
#pragma unroll
            for (int nb = 0; nb < 4; nb++) {
                const uint32_t vaddr = vrow + (nb * 16 + tcol) * 2;
                uint32_t h0, h1, h2, h3, q0, q1, q2, q3;
                ldmatrix_x4_trans(h0, h1, h2, h3, sVhb + vaddr);
                ldmatrix_x4_trans(q0, q1, q2, q3, sVlb + vaddr);
                mma_bf16(o[2 * nb],     ph[0], ph[1], ph[2], ph[3], h0, h1);
                mma_bf16(o[2 * nb + 1], ph[0], ph[1], ph[2], ph[3], h2, h3);
                mma_bf16(o[2 * nb],     ph[0], ph[1], ph[2], ph[3], q0, q1);
                mma_bf16(o[2 * nb + 1], ph[0], ph[1], ph[2], ph[3], q2, q3);
                mma_bf16(o[2 * nb],     pl[0], pl[1], pl[2], pl[3], h0, h1);
                mma_bf16(o[2 * nb + 1], pl[0], pl[1], pl[2], pl[3], h2, h3);
            }
        }
    }

    const float inv0 = 1.0f / l0, inv1 = 1.0f / l1;
    const int row0 = qt * 128 + wid * 16 + g;
#pragma unroll
    for (int nf = 0; nf < 8; nf++) {
        const int col = h * HD_ + nf * 8 + tig * 2;
        float2 w0, w1;
        w0.x = o[nf][0] * inv0; w0.y = o[nf][1] * inv0;
        w1.x = o[nf][2] * inv1; w1.y = o[nf][3] * inv1;
        *reinterpret_cast<float2*>(&ctx[((size_t)b * T_ + row0) * D_ + col]) = w0;
        *reinterpret_cast<float2*>(&ctx[((size_t)b * T_ + row0 + 8) * D_ + col]) = w1;
    }
}

// ---------------------------------------------------------------------------
// launch — order chosen so launch index 5 (0-based) is mma_gemm_kernel,
// which the ncu capture (-s 5 -c 1) will profile.
// ---------------------------------------------------------------------------
extern "C" void kernel_launch(void* const* d_in, const int* in_sizes, int n_in,
                              void* d_out, int out_size)
{
    const float* hidden = (const float*)d_in[0];
    const float* kv     = (const float*)d_in[1];
    const float* target = (const float*)d_in[2];
    const float* mask   = (const float*)d_in[3];
    const float* Wq  = (const float*)d_in[4];
    const float* bq  = (const float*)d_in[5];
    const float* Wk  = (const float*)d_in[6];
    const float* bk  = (const float*)d_in[7];
    const float* Wv  = (const float*)d_in[8];
    const float* bv  = (const float*)d_in[9];
    const float* Wwq = (const float*)d_in[10];
    const float* bwq = (const float*)d_in[11];
    const float* Wwk = (const float*)d_in[12];
    const float* bwk = (const float*)d_in[13];
    const float* Wo  = (const float*)d_in[14];
    const float* bo  = (const float*)d_in[15];
    float* out = (float*)d_out;

    float *q, *k, *v, *tq, *tk, *w, *ctx;
    cudaGetSymbolAddress((void**)&q,   g_q);
    cudaGetSymbolAddress((void**)&k,   g_k);
    cudaGetSymbolAddress((void**)&v,   g_v);
    cudaGetSymbolAddress((void**)&tq,  g_tq);
    cudaGetSymbolAddress((void**)&tk,  g_tk);
    cudaGetSymbolAddress((void**)&w,   g_w);
    cudaGetSymbolAddress((void**)&ctx, g_ctx);

    __nv_bfloat16 *hA, *kvA, *tA, *ctxA, *Wq2, *Wk2, *Wv2, *Wwq2, *Wwk2, *Wo2;
    cudaGetSymbolAddress((void**)&hA,   g_hA);
    cudaGetSymbolAddress((void**)&kvA,  g_kvA);
    cudaGetSymbolAddress((void**)&tA,   g_tA);
    cudaGetSymbolAddress((void**)&ctxA, g_ctxA);
    cudaGetSymbolAddress((void**)&Wq2,  g_Wq2);
    cudaGetSymbolAddress((void**)&Wk2,  g_Wk2);
    cudaGetSymbolAddress((void**)&Wv2,  g_Wv2);
    cudaGetSymbolAddress((void**)&Wwq2, g_Wwq2);
    cudaGetSymbolAddress((void**)&Wwk2, g_Wwk2);
    cudaGetSymbolAddress((void**)&Wo2,  g_Wo2);

    cudaFuncSetAttribute(mma_gemm_kernel,
                         cudaFuncAttributeMaxDynamicSharedMemorySize, GEMM_SMEM_BYTES);
    cudaFuncSetAttribute(mma_gemm3_kernel,
                         cudaFuncAttributeMaxDynamicSharedMemorySize, GEMM_SMEM_BYTES);

    // launches 0..4: splits needed by gemm-q
    split_kernel<<<B_ * T_,  256>>>(hidden, hA);    // 0
    split_kernel<<<B_ * S_,  256>>>(kv,     kvA);   // 1
    split_kernel<<<B_ * TL_, 256>>>(target, tA);    // 2
    split_kernel<<<D_, 256>>>(Wq,  Wq2);            // 3
    split_kernel<<<D_, 256>>>(Wk,  Wk2);            // 4

    // launch 5: PROFILED by ncu
    mma_gemm_kernel<<<dim3(8, (B_ * T_) / 128), 256, GEMM_SMEM_BYTES>>>(
        hA, Wq2, bq, q, SCALING_);                  // 5

    // remaining splits
    split_kernel<<<D_, 256>>>(Wv,  Wv2);            // 6
    split_kernel<<<D_, 256>>>(Wwq, Wwq2);           // 7
    split_kernel<<<D_, 256>>>(Wwk, Wwk2);           // 8
    split_kernel<<<D_, 256>>>(Wo,  Wo2);            // 9

    // fused k / v / tq GEMMs (one launch, 3x grid.z)
    mma_gemm3_kernel<<<dim3(8, (B_ * S_) / 128, 3), 256, GEMM_SMEM_BYTES>>>(
        kvA, Wk2, bk, k, Wv2, bv, v, Wwq2, bwq, tq, SCALING_);

    // tk projection
    mma_gemm_kernel<<<dim3(8, (B_ * TL_) / 128), 256, GEMM_SMEM_BYTES>>>(
        tA, Wwk2, bwk, tk, 1.0f);

    // masked-mean weights
    weights_kernel<<<B_ * H_, 256>>>(tq, tk, mask, w);

    // tensor-core flash attention
    attn_tc_kernel<<<dim3(T_ / 128, B_ * H_), 256>>>(q, k, v, w, ctx);

    // output projection
    split_kernel<<<B_ * T_, 256>>>(ctx, ctxA);
    mma_gemm_kernel<<<dim3(8, (B_ * T_) / 128), 256, GEMM_SMEM_BYTES>>>(
        ctxA, Wo2, bo, out, 1.0f);
}

// round 10
// speedup vs baseline: 1.9337x; 1.0319x over previous
#include <cuda_runtime.h>
#include <cuda_bf16.h>
#include <cstdint>

// ============================================================================
// KTMutualAttention — mma.sync bf16 3-term split GEMMs with format-fused
//   epilogues (q/k bf16, v bf16 hi|lo), flash attention writes ctx hi|lo
//   directly, merged q+tk launch.
//   B=8, T=512, S=1024, TL=64, D=1024, H=16, hd=64
// ============================================================================

#define B_   8
#define T_   512
#define S_   1024
#define TL_  64
#define D_   1024
#define H_   16
#define HD_  64
#define SCALING_ 0.125f
#define K2_  2048          // [hi|lo] split width

#define MODE_F32   0
#define MODE_BF16  1
#define MODE_SPLIT 2

// ---------------------------------------------------------------------------
// scratch (device globals)
// ---------------------------------------------------------------------------
__device__ __align__(256) float g_tq [B_ * S_ * D_];
__device__ __align__(256) float g_tk [B_ * TL_ * D_];
__device__ __align__(256) float g_w  [B_ * H_ * S_];

__device__ __align__(256) __nv_bfloat16 g_qb  [(size_t)B_ * T_ * D_];    // q bf16
__device__ __align__(256) __nv_bfloat16 g_kb  [(size_t)B_ * S_ * D_];    // k bf16
__device__ __align__(256) __nv_bfloat16 g_v2  [(size_t)B_ * S_ * K2_];   // v hi|lo

__device__ __align__(256) __nv_bfloat16 g_hA  [(size_t)B_ * T_  * K2_];
__device__ __align__(256) __nv_bfloat16 g_kvA [(size_t)B_ * S_  * K2_];
__device__ __align__(256) __nv_bfloat16 g_tA  [(size_t)B_ * TL_ * K2_];
__device__ __align__(256) __nv_bfloat16 g_ctxA[(size_t)B_ * T_  * K2_];
__device__ __align__(256) __nv_bfloat16 g_Wq2 [(size_t)D_ * K2_];
__device__ __align__(256) __nv_bfloat16 g_Wk2 [(size_t)D_ * K2_];
__device__ __align__(256) __nv_bfloat16 g_Wv2 [(size_t)D_ * K2_];
__device__ __align__(256) __nv_bfloat16 g_Wwq2[(size_t)D_ * K2_];
__device__ __align__(256) __nv_bfloat16 g_Wwk2[(size_t)D_ * K2_];
__device__ __align__(256) __nv_bfloat16 g_Wo2 [(size_t)D_ * K2_];

// ---------------------------------------------------------------------------
// PTX helpers (portable sm_80+)
// ---------------------------------------------------------------------------
__device__ __forceinline__ uint32_t smem_u32(const void* p) {
    uint32_t a;
    asm("{ .reg .u64 t; cvta.to.shared.u64 t, %1; cvt.u32.u64 %0, t; }"
        : "=r"(a) : "l"(p));
    return a;
}

#define CP_ASYNC16(dst_u32, src_ptr) \
    asm volatile("cp.async.cg.shared.global [%0], [%1], 16;" \
                 :: "r"(dst_u32), "l"(src_ptr) : "memory")
#define CP_COMMIT() asm volatile("cp.async.commit_group;" ::: "memory")
#define CP_WAIT2()  asm volatile("cp.async.wait_group 2;" ::: "memory")

__device__ __forceinline__ void ldmatrix_x4(uint32_t& r0, uint32_t& r1,
                                            uint32_t& r2, uint32_t& r3,
                                            uint32_t addr)
{
    asm volatile("ldmatrix.sync.aligned.m8n8.x4.shared.b16 {%0,%1,%2,%3}, [%4];"
                 : "=r"(r0), "=r"(r1), "=r"(r2), "=r"(r3) : "r"(addr));
}

__device__ __forceinline__ void ldmatrix_x4_trans(uint32_t& r0, uint32_t& r1,
                                                  uint32_t& r2, uint32_t& r3,
                                                  uint32_t addr)
{
    asm volatile("ldmatrix.sync.aligned.m8n8.x4.trans.shared.b16 {%0,%1,%2,%3}, [%4];"
                 : "=r"(r0), "=r"(r1), "=r"(r2), "=r"(r3) : "r"(addr));
}

__device__ __forceinline__ void mma_bf16(float* c, uint32_t a0, uint32_t a1,
                                         uint32_t a2, uint32_t a3,
                                         uint32_t b0, uint32_t b1)
{
    asm volatile(
        "mma.sync.aligned.m16n8k16.row.col.f32.bf16.bf16.f32 "
        "{%0,%1,%2,%3}, {%4,%5,%6,%7}, {%8,%9}, {%0,%1,%2,%3};"
        : "+f"(c[0]), "+f"(c[1]), "+f"(c[2]), "+f"(c[3])
        : "r"(a0), "r"(a1), "r"(a2), "r"(a3), "r"(b0), "r"(b1));
}

__device__ __forceinline__ uint32_t pack_bf162(float x, float y)
{
    __nv_bfloat162 t = __floats2bfloat162_rn(x, y);
    return *reinterpret_cast<uint32_t*>(&t);
}

__device__ __forceinline__ void split_pair(float x, float y,
                                           uint32_t& hi, uint32_t& lo)
{
    __nv_bfloat16 hx = __float2bfloat16_rn(x);
    __nv_bfloat16 hy = __float2bfloat16_rn(y);
    __nv_bfloat162 th(hx, hy);
    hi = *reinterpret_cast<uint32_t*>(&th);
    __nv_bfloat162 tl(__float2bfloat16_rn(x - __bfloat162float(hx)),
                      __float2bfloat16_rn(y - __bfloat162float(hy)));
    lo = *reinterpret_cast<uint32_t*>(&tl);
}

// ---------------------------------------------------------------------------
// fp32 -> bf16 hi|lo split kernel (inputs / weights)
// ---------------------------------------------------------------------------
__global__ __launch_bounds__(256)
void split_kernel(const float* __restrict__ x, __nv_bfloat16* __restrict__ y)
{
    const int idx = blockIdx.x * 256 + threadIdx.x;
    const int row = idx >> 8;
    const int c4  = (idx & 255) * 4;
    const float4 v = *reinterpret_cast<const float4*>(x + ((size_t)row << 10) + c4);

    uint32_t h0, l0, h1, l1;
    split_pair(v.x, v.y, h0, l0);
    split_pair(v.z, v.w, h1, l1);
    uint32_t* dh = reinterpret_cast<uint32_t*>(y + (size_t)row * K2_ + c4);
    dh[0] = h0; dh[1] = h1;
    uint32_t* dl = reinterpret_cast<uint32_t*>(y + (size_t)row * K2_ + 1024 + c4);
    dl[0] = l0; dl[1] = l1;
}

// ---------------------------------------------------------------------------
// GEMM core: out[bm:+128, bn:+128] = scale*(A@W^T + bias)
//   3-term split (A: hi,hi,lo; W: hi,lo,hi), 4-stage cp.async ring.
//   mode: 0 fp32 (stride 1024), 1 bf16 (stride 1024), 2 bf16 hi|lo (stride 2048)
// ---------------------------------------------------------------------------
#define BK 32
#define SROW 40
#define N_CHUNK 96
#define STAGES 4
#define STAGE_ELEMS (128 * SROW)
#define GEMM_SMEM_BYTES (STAGES * STAGE_ELEMS * 2 * 2)

__device__ __forceinline__
void gemm_core(const __nv_bfloat16* __restrict__ A,
               const __nv_bfloat16* __restrict__ W,
               const float* __restrict__ bias,
               void* __restrict__ out, float scale, int mode,
               int bm, int bn, __nv_bfloat16* smem)
{
    __nv_bfloat16* sA = smem;
    __nv_bfloat16* sB = smem + STAGES * STAGE_ELEMS;
    __shared__ float biasS[128];

    const int tid = threadIdx.x;
    const int wid = tid >> 5, lane = tid & 31;
    const int wm = wid & 3;
    const int wn = wid >> 2;

    if (tid < 128) biasS[tid] = bias[bn + tid];

    const __nv_bfloat16* Ag = A + (size_t)bm * K2_;
    const __nv_bfloat16* Wg = W + (size_t)bn * K2_;

    const int ldrow = tid >> 1;
    const int ldoff = (tid & 1) * 16;

    const uint32_t sAu = smem_u32(sA);
    const uint32_t sBu = smem_u32(sB);

    auto stage = [&](int c) {
        const int slot = c & (STAGES - 1);
        const int seg = c >> 5;
        const int col = (c & 31) * BK;
        const int gA = ((seg == 2) ? 1024 : 0) + col;   // A: hi,hi,lo
        const int gW = ((seg == 1) ? 1024 : 0) + col;   // W: hi,lo,hi
        const size_t ga = (size_t)ldrow * K2_ + gA + ldoff;
        const size_t gw = (size_t)ldrow * K2_ + gW + ldoff;
        const uint32_t sa = sAu + (slot * STAGE_ELEMS + ldrow * SROW + ldoff) * 2;
        const uint32_t sb = sBu + (slot * STAGE_ELEMS + ldrow * SROW + ldoff) * 2;
        CP_ASYNC16(sa,      Ag + ga);
        CP_ASYNC16(sa + 16, Ag + ga + 8);
        CP_ASYNC16(sb,      Wg + gw);
        CP_ASYNC16(sb + 16, Wg + gw + 8);
    };

    float acc[2][8][4];
#pragma unroll
    for (int mt = 0; mt < 2; mt++)
#pragma unroll
        for (int nf = 0; nf < 8; nf++)
#pragma unroll
            for (int r = 0; r < 4; r++) acc[mt][nf][r] = 0.f;

    stage(0); CP_COMMIT();
    stage(1); CP_COMMIT();
    stage(2); CP_COMMIT();

    const int lrow = lane & 15;
    const int lcol = (lane >> 4) * 16;

    for (int c = 0; c < N_CHUNK; ++c) {
        CP_WAIT2();
        __syncthreads();

        if (c + 3 < N_CHUNK) { stage(c + 3); CP_COMMIT(); }

        const int slot = c & (STAGES - 1);
        const uint32_t aBase = sAu + slot * STAGE_ELEMS * 2;
        const uint32_t bBase = sBu + slot * STAGE_ELEMS * 2;

#pragma unroll
        for (int kk = 0; kk < 2; kk++) {
            const int kbyte = kk * 32 + lcol;

            uint32_t a[2][4];
#pragma unroll
            for (int mt = 0; mt < 2; mt++) {
                const int row = wm * 32 + mt * 16 + lrow;
                ldmatrix_x4(a[mt][0], a[mt][1], a[mt][2], a[mt][3],
                            aBase + row * (SROW * 2) + kbyte);
            }
            uint32_t b[4][4];
#pragma unroll
            for (int nb = 0; nb < 4; nb++) {
                const int row = wn * 64 + nb * 16 + lrow;
                ldmatrix_x4(b[nb][0], b[nb][1], b[nb][2], b[nb][3],
                            bBase + row * (SROW * 2) + kbyte);
            }
#pragma unroll
            for (int mt = 0; mt < 2; mt++)
#pragma unroll
                for (int nf = 0; nf < 8; nf++) {
                    const int nb = nf >> 1;
                    const uint32_t b0 = (nf & 1) ? b[nb][1] : b[nb][0];
                    const uint32_t b1 = (nf & 1) ? b[nb][3] : b[nb][2];
                    mma_bf16(acc[mt][nf], a[mt][0], a[mt][1], a[mt][2], a[mt][3],
                             b0, b1);
                }
        }
    }

    const int g_  = lane >> 2;
    const int tig = lane & 3;
#pragma unroll
    for (int mt = 0; mt < 2; mt++) {
        const int row0 = bm + wm * 32 + mt * 16 + g_;
#pragma unroll
        for (int nf = 0; nf < 8; nf++) {
            const int lc  = wn * 64 + nf * 8 + tig * 2;
            const int col = bn + lc;
            const float b0 = biasS[lc], b1 = biasS[lc + 1];
            const float x0 = scale * (acc[mt][nf][0] + b0);
            const float x1 = scale * (acc[mt][nf][1] + b1);
            const float x2 = scale * (acc[mt][nf][2] + b0);
            const float x3 = scale * (acc[mt][nf][3] + b1);
            if (mode == MODE_F32) {
                float* C = (float*)out;
                *reinterpret_cast<float2*>(C + (size_t)row0 * 1024 + col)
                    = make_float2(x0, x1);
                *reinterpret_cast<float2*>(C + (size_t)(row0 + 8) * 1024 + col)
                    = make_float2(x2, x3);
            } else if (mode == MODE_BF16) {
                __nv_bfloat16* C = (__nv_bfloat16*)out;
                *reinterpret_cast<uint32_t*>(C + (size_t)row0 * 1024 + col)
                    = pack_bf162(x0, x1);
                *reinterpret_cast<uint32_t*>(C + (size_t)(row0 + 8) * 1024 + col)
                    = pack_bf162(x2, x3);
            } else {
                __nv_bfloat16* C = (__nv_bfloat16*)out;
                uint32_t h0, l0, h1, l1;
                split_pair(x0, x1, h0, l0);
                split_pair(x2, x3, h1, l1);
                *reinterpret_cast<uint32_t*>(C + (size_t)row0 * K2_ + col) = h0;
                *reinterpret_cast<uint32_t*>(C + (size_t)row0 * K2_ + 1024 + col) = l0;
                *reinterpret_cast<uint32_t*>(C + (size_t)(row0 + 8) * K2_ + col) = h1;
                *reinterpret_cast<uint32_t*>(C + (size_t)(row0 + 8) * K2_ + 1024 + col) = l1;
            }
        }
    }
}

// merged q-proj (256 tiles, bf16 out) + tk-proj (32 tiles, fp32 out)
__global__ __launch_bounds__(256, 2)
void gemm_qtk_kernel(const __nv_bfloat16* __restrict__ hA,
                     const __nv_bfloat16* __restrict__ Wq2,
                     const float* __restrict__ bq,
                     __nv_bfloat16* __restrict__ qb,
                     const __nv_bfloat16* __restrict__ tA,
                     const __nv_bfloat16* __restrict__ Wwk2,
                     const float* __restrict__ bwk,
                     float* __restrict__ tk)
{
    extern __shared__ __nv_bfloat16 smem[];
    const int x = blockIdx.x;
    if (x < 256)
        gemm_core(hA, Wq2, bq, qb, SCALING_, MODE_BF16,
                  (x >> 3) * 128, (x & 7) * 128, smem);
    else {
        const int t = x - 256;
        gemm_core(tA, Wwk2, bwk, tk, 1.0f, MODE_F32,
                  (t >> 3) * 128, (t & 7) * 128, smem);
    }
}

// fused k (bf16) / v (hi|lo) / tq (fp32, scaled): blockIdx.z selects
__global__ __launch_bounds__(256, 2)
void gemm_kvt_kernel(const __nv_bfloat16* __restrict__ kvA,
                     const __nv_bfloat16* __restrict__ Wk2,
                     const float* __restrict__ bk,
                     __nv_bfloat16* __restrict__ kb,
                     const __nv_bfloat16* __restrict__ Wv2,
                     const float* __restrict__ bv,
                     __nv_bfloat16* __restrict__ v2,
                     const __nv_bfloat16* __restrict__ Wwq2,
                     const float* __restrict__ bwq,
                     float* __restrict__ tq)
{
    extern __shared__ __nv_bfloat16 smem[];
    const int z = blockIdx.z;
    const int bm = blockIdx.y * 128, bn = blockIdx.x * 128;
    if (z == 0)
        gemm_core(kvA, Wk2, bk, kb, 1.0f, MODE_BF16, bm, bn, smem);
    else if (z == 1)
        gemm_core(kvA, Wv2, bv, v2, 1.0f, MODE_SPLIT, bm, bn, smem);
    else
        gemm_core(kvA, Wwq2, bwq, tq, SCALING_, MODE_F32, bm, bn, smem);
}

// out projection (fp32 out)
__global__ __launch_bounds__(256, 2)
void gemm_out_kernel(const __nv_bfloat16* __restrict__ A,
                     const __nv_bfloat16* __restrict__ W,
                     const float* __restrict__ bias,
                     float* __restrict__ C)
{
    extern __shared__ __nv_bfloat16 smem[];
    gemm_core(A, W, bias, C, 1.0f, MODE_F32,
              blockIdx.y * 128, blockIdx.x * 128, smem);
}

// ---------------------------------------------------------------------------
// weights[b,h,s] = (tq . (mask @ tk)) / sum(mask)
// ---------------------------------------------------------------------------
__global__ __launch_bounds__(256)
void weights_kernel(const float* __restrict__ tq, const float* __restrict__ tk,
                    const float* __restrict__ mask, float* __restrict__ wgt)
{
    const int bh = blockIdx.x;
    const int b = bh >> 4;
    const int h = bh & 15;

    __shared__ float tks[TL_][HD_];

    const int tid = threadIdx.x;
    for (int idx = tid; idx < TL_ * HD_; idx += 256) {
        const int t = idx >> 6, d = idx & 63;
        tks[t][d] = tk[((size_t)b * TL_ + t) * D_ + h * HD_ + d];
    }
    __syncthreads();

    const int warp = tid >> 5, lane = tid & 31;

    for (int s = warp; s < S_; s += 8) {
        const size_t tqo = ((size_t)b * S_ + s) * D_ + h * HD_;
        const float tq0 = __ldg(&tq[tqo + lane]);
        const float tq1 = __ldg(&tq[tqo + lane + 32]);
        const float* mrow = mask + ((size_t)b * S_ + s) * TL_;

        float mk0 = 0.f, mk1 = 0.f, cnt = 0.f;
#pragma unroll
        for (int t = 0; t < TL_; t++) {
            const float m = __ldg(&mrow[t]);
            cnt += m;
            mk0 = fmaf(m, tks[t][lane], mk0);
            mk1 = fmaf(m, tks[t][lane + 32], mk1);
        }
        float dotv = tq0 * mk0 + tq1 * mk1;
#pragma unroll
        for (int off = 16; off; off >>= 1)
            dotv += __shfl_xor_sync(0xffffffffu, dotv, off);

        if (lane == 0)
            wgt[(size_t)bh * S_ + s] = dotv / cnt;
    }
}

// ---------------------------------------------------------------------------
// fast exp on FMA pipe
// ---------------------------------------------------------------------------
__device__ __forceinline__ float fast_exp(float x)
{
    const float y = x * 1.44269504088896341f;
    const float n = rintf(y);
    const float t = (y - n) * 0.69314718055994531f;
    float p = 1.9841269841e-4f;
    p = fmaf(p, t, 1.38888888889e-3f);
    p = fmaf(p, t, 8.33333333333e-3f);
    p = fmaf(p, t, 4.16666666667e-2f);
    p = fmaf(p, t, 1.66666666667e-1f);
    p = fmaf(p, t, 0.5f);
    p = fmaf(p, t, 1.0f);
    p = fmaf(p, t, 1.0f);
    int e = (int)n;
    e = e < -126 ? -126 : e;
    const float s = __int_as_float((e + 127) << 23);
    return p * s;
}

// ---------------------------------------------------------------------------
// Tensor-core flash attention; all operands pre-converted bf16.
//   grid = (T/128, B*H), 256 threads. Writes ctxA [hi|lo] directly.
// ---------------------------------------------------------------------------
#define VPAD 72

__global__ __launch_bounds__(256)
void attn_tc_kernel(const __nv_bfloat16* __restrict__ qb,
                    const __nv_bfloat16* __restrict__ kb,
                    const __nv_bfloat16* __restrict__ v2,
                    const float* __restrict__ wgt,
                    __nv_bfloat16* __restrict__ ctxA)
{
    __shared__ __nv_bfloat16 sQ [128 * VPAD];
    __shared__ __nv_bfloat16 sK [64 * VPAD];
    __shared__ __nv_bfloat16 sVh[64 * VPAD];
    __shared__ __nv_bfloat16 sVl[64 * VPAD];
    __shared__ float ws[64];

    const int qt = blockIdx.x, bh = blockIdx.y;
    const int b = bh >> 4, h = bh & 15;
    const int tid = threadIdx.x, wid = tid >> 5, lane = tid & 31;
    const int g = lane >> 2, tig = lane & 3;
    const int lrow = lane & 15, lcolb = (lane >> 4) * 16;

    const int trow = ((lane >> 3) & 1) * 8 + (lane & 7);
    const int tcol = (lane >> 4) * 8;

    // load Q tile (128 x 64 bf16) — pure copy
    const size_t qbase = ((size_t)b * T_ + qt * 128) * D_ + h * HD_;
#pragma unroll
    for (int it = 0; it < 4; ++it) {
        const int idx = it * 256 + tid;            // 1024 uint4
        const int r = idx >> 3, c8 = (idx & 7) * 8;
        const uint4 t = *reinterpret_cast<const uint4*>(qb + qbase + (size_t)r * D_ + c8);
        *reinterpret_cast<uint4*>(&sQ[r * VPAD + c8]) = t;
    }

    float o[8][4];
#pragma unroll
    for (int nf = 0; nf < 8; nf++)
#pragma unroll
        for (int r = 0; r < 4; r++) o[nf][r] = 0.f;
    float m0 = -1e30f, m1 = -1e30f, l0 = 0.f, l1 = 0.f;

    const uint32_t sQb = smem_u32(sQ), sKb = smem_u32(sK);
    const uint32_t sVhb = smem_u32(sVh), sVlb = smem_u32(sVl);

    const float* wrow = wgt + (size_t)bh * S_;

    for (int sc = 0; sc < S_ / 64; ++sc) {
        __syncthreads();
        const size_t krow0 = (size_t)b * S_ + sc * 64;
#pragma unroll
        for (int it = 0; it < 2; ++it) {
            const int idx = it * 256 + tid;        // 512 uint4 per array
            const int r = idx >> 3, c8 = (idx & 7) * 8;
            const uint4 tk4 = *reinterpret_cast<const uint4*>(
                kb + (krow0 + r) * D_ + h * HD_ + c8);
            *reinterpret_cast<uint4*>(&sK[r * VPAD + c8]) = tk4;
            const uint4 th4 = *reinterpret_cast<const uint4*>(
                v2 + (krow0 + r) * K2_ + h * HD_ + c8);
            *reinterpret_cast<uint4*>(&sVh[r * VPAD + c8]) = th4;
            const uint4 tl4 = *reinterpret_cast<const uint4*>(
                v2 + (krow0 + r) * K2_ + 1024 + h * HD_ + c8);
            *reinterpret_cast<uint4*>(&sVl[r * VPAD + c8]) = tl4;
        }
        if (tid < 64) ws[tid] = wrow[sc * 64 + tid];
        __syncthreads();

        // ---- S = Q @ K^T
        float sv[8][4];
#pragma unroll
        for (int nf = 0; nf < 8; nf++)
#pragma unroll
            for (int r = 0; r < 4; r++) sv[nf][r] = 0.f;

#pragma unroll
        for (int kk = 0; kk < 4; kk++) {
            const int kb_ = kk * 32 + lcolb;
            uint32_t a0, a1, a2, a3;
            ldmatrix_x4(a0, a1, a2, a3,
                        sQb + (wid * 16 + lrow) * (VPAD * 2) + kb_);
#pragma unroll
            for (int nb = 0; nb < 4; nb++) {
                uint32_t b0, b1, b2, b3;
                ldmatrix_x4(b0, b1, b2, b3,
                            sKb + (nb * 16 + lrow) * (VPAD * 2) + kb_);
                mma_bf16(sv[2 * nb],     a0, a1, a2, a3, b0, b2);
                mma_bf16(sv[2 * nb + 1], a0, a1, a2, a3, b1, b3);
            }
        }

        // ---- per-key-column weight scaling
#pragma unroll
        for (int nf = 0; nf < 8; nf++) {
            const int col = nf * 8 + tig * 2;
            const float w0 = ws[col], w1 = ws[col + 1];
            sv[nf][0] *= w0; sv[nf][1] *= w1;
            sv[nf][2] *= w0; sv[nf][3] *= w1;
        }

        // ---- online softmax
        float mx0 = -1e30f, mx1 = -1e30f;
#pragma unroll
        for (int nf = 0; nf < 8; nf++) {
            mx0 = fmaxf(mx0, fmaxf(sv[nf][0], sv[nf][1]));
            mx1 = fmaxf(mx1, fmaxf(sv[nf][2], sv[nf][3]));
        }
        mx0 = fmaxf(mx0, __shfl_xor_sync(0xffffffffu, mx0, 1));
        mx0 = fmaxf(mx0, __shfl_xor_sync(0xffffffffu, mx0, 2));
        mx1 = fmaxf(mx1, __shfl_xor_sync(0xffffffffu, mx1, 1));
        mx1 = fmaxf(mx1, __shfl_xor_sync(0xffffffffu, mx1, 2));

        const float mn0 = fmaxf(m0, mx0), mn1 = fmaxf(m1, mx1);
        const float al0 = fast_exp(m0 - mn0), al1 = fast_exp(m1 - mn1);
        m0 = mn0; m1 = mn1;

        float s0 = 0.f, s1 = 0.f;
#pragma unroll
        for (int nf = 0; nf < 8; nf++) {
            sv[nf][0] = fast_exp(sv[nf][0] - mn0);
            sv[nf][1] = fast_exp(sv[nf][1] - mn0);
            sv[nf][2] = fast_exp(sv[nf][2] - mn1);
            sv[nf][3] = fast_exp(sv[nf][3] - mn1);
            s0 += sv[nf][0] + sv[nf][1];
            s1 += sv[nf][2] + sv[nf][3];
        }
        s0 += __shfl_xor_sync(0xffffffffu, s0, 1);
        s0 += __shfl_xor_sync(0xffffffffu, s0, 2);
        s1 += __shfl_xor_sync(0xffffffffu, s1, 1);
        s1 += __shfl_xor_sync(0xffffffffu, s1, 2);
        l0 = l0 * al0 + s0;
        l1 = l1 * al1 + s1;

#pragma unroll
        for (int nf = 0; nf < 8; nf++) {
            o[nf][0] *= al0; o[nf][1] *= al0;
            o[nf][2] *= al1; o[nf][3] *= al1;
        }

        // ---- O += P @ V  (3-term hi/lo; V row-major + ldmatrix.trans)
#pragma unroll
        for (int j = 0; j < 4; j++) {
            uint32_t ph[4], pl[4];
            split_pair(sv[2 * j][0],     sv[2 * j][1],     ph[0], pl[0]);
            split_pair(sv[2 * j][2],     sv[2 * j][3],     ph[1], pl[1]);
            split_pair(sv[2 * j + 1][0], sv[2 * j + 1][1], ph[2], pl[2]);
            split_pair(sv[2 * j + 1][2], sv[2 * j + 1][3], ph[3], pl[3]);

            const uint32_t vrow = (j * 16 + trow) * (VPAD * 2);
#pragma unroll
            for (int nb = 0; nb < 4; nb++) {
                const uint32_t vaddr = vrow + (nb * 16 + tcol) * 2;
                uint32_t h0, h1, h2, h3, q0, q1, q2, q3;
                ldmatrix_x4_trans(h0, h1, h2, h3, sVhb + vaddr);
                ldmatrix_x4_trans(q0, q1, q2, q3, sVlb + vaddr);
                mma_bf16(o[2 * nb],     ph[0], ph[1], ph[2], ph[3], h0, h1);
                mma_bf16(o[2 * nb + 1], ph[0], ph[1], ph[2], ph[3], h2, h3);
                mma_bf16(o[2 * nb],     ph[0], ph[1], ph[2], ph[3], q0, q1);
                mma_bf16(o[2 * nb + 1], ph[0], ph[1], ph[2], ph[3], q2, q3);
                mma_bf16(o[2 * nb],     pl[0], pl[1], pl[2], pl[3], h0, h1);
                mma_bf16(o[2 * nb + 1], pl[0], pl[1], pl[2], pl[3], h2, h3);
            }
        }
    }

    // ---- epilogue: write ctxA [hi|lo] directly
    const float inv0 = 1.0f / l0, inv1 = 1.0f / l1;
    const int row0 = qt * 128 + wid * 16 + g;
#pragma unroll
    for (int nf = 0; nf < 8; nf++) {
        const int col = h * HD_ + nf * 8 + tig * 2;
        uint32_t h0, l0w, h1, l1w;
        split_pair(o[nf][0] * inv0, o[nf][1] * inv0, h0, l0w);
        split_pair(o[nf][2] * inv1, o[nf][3] * inv1, h1, l1w);
        const size_t r0 = ((size_t)b * T_ + row0) * K2_;
        const size_t r1 = ((size_t)b * T_ + row0 + 8) * K2_;
        *reinterpret_cast<uint32_t*>(ctxA + r0 + col)        = h0;
        *reinterpret_cast<uint32_t*>(ctxA + r0 + 1024 + col) = l0w;
        *reinterpret_cast<uint32_t*>(ctxA + r1 + col)        = h1;
        *reinterpret_cast<uint32_t*>(ctxA + r1 + 1024 + col) = l1w;
    }
}

// ---------------------------------------------------------------------------
// launch
// ---------------------------------------------------------------------------
extern "C" void kernel_launch(void* const* d_in, const int* in_sizes, int n_in,
                              void* d_out, int out_size)
{
    const float* hidden = (const float*)d_in[0];
    const float* kv     = (const float*)d_in[1];
    const float* target = (const float*)d_in[2];
    const float* mask   = (const float*)d_in[3];
    const float* Wq  = (const float*)d_in[4];
    const float* bq  = (const float*)d_in[5];
    const float* Wk  = (const float*)d_in[6];
    const float* bk  = (const float*)d_in[7];
    const float* Wv  = (const float*)d_in[8];
    const float* bv  = (const float*)d_in[9];
    const float* Wwq = (const float*)d_in[10];
    const float* bwq = (const float*)d_in[11];
    const float* Wwk = (const float*)d_in[12];
    const float* bwk = (const float*)d_in[13];
    const float* Wo  = (const float*)d_in[14];
    const float* bo  = (const float*)d_in[15];
    float* out = (float*)d_out;

    float *tq, *tk, *w;
    cudaGetSymbolAddress((void**)&tq,  g_tq);
    cudaGetSymbolAddress((void**)&tk,  g_tk);
    cudaGetSymbolAddress((void**)&w,   g_w);

    __nv_bfloat16 *qb, *kb, *v2;
    cudaGetSymbolAddress((void**)&qb, g_qb);
    cudaGetSymbolAddress((void**)&kb, g_kb);
    cudaGetSymbolAddress((void**)&v2, g_v2);

    __nv_bfloat16 *hA, *kvA, *tA, *ctxA, *Wq2, *Wk2, *Wv2, *Wwq2, *Wwk2, *Wo2;
    cudaGetSymbolAddress((void**)&hA,   g_hA);
    cudaGetSymbolAddress((void**)&kvA,  g_kvA);
    cudaGetSymbolAddress((void**)&tA,   g_tA);
    cudaGetSymbolAddress((void**)&ctxA, g_ctxA);
    cudaGetSymbolAddress((void**)&Wq2,  g_Wq2);
    cudaGetSymbolAddress((void**)&Wk2,  g_Wk2);
    cudaGetSymbolAddress((void**)&Wv2,  g_Wv2);
    cudaGetSymbolAddress((void**)&Wwq2, g_Wwq2);
    cudaGetSymbolAddress((void**)&Wwk2, g_Wwk2);
    cudaGetSymbolAddress((void**)&Wo2,  g_Wo2);

    cudaFuncSetAttribute(gemm_qtk_kernel,
                         cudaFuncAttributeMaxDynamicSharedMemorySize, GEMM_SMEM_BYTES);
    cudaFuncSetAttribute(gemm_kvt_kernel,
                         cudaFuncAttributeMaxDynamicSharedMemorySize, GEMM_SMEM_BYTES);
    cudaFuncSetAttribute(gemm_out_kernel,
                         cudaFuncAttributeMaxDynamicSharedMemorySize, GEMM_SMEM_BYTES);

    // 1) fp32 -> bf16 hi|lo splits (inputs + weights)
    split_kernel<<<B_ * T_,  256>>>(hidden, hA);
    split_kernel<<<B_ * S_,  256>>>(kv,     kvA);
    split_kernel<<<B_ * TL_, 256>>>(target, tA);
    split_kernel<<<D_, 256>>>(Wq,  Wq2);
    split_kernel<<<D_, 256>>>(Wk,  Wk2);
    split_kernel<<<D_, 256>>>(Wv,  Wv2);
    split_kernel<<<D_, 256>>>(Wwq, Wwq2);
    split_kernel<<<D_, 256>>>(Wwk, Wwk2);
    split_kernel<<<D_, 256>>>(Wo,  Wo2);

    // 2) merged q-proj (bf16 out) + tk-proj (fp32 out)
    gemm_qtk_kernel<<<288, 256, GEMM_SMEM_BYTES>>>(
        hA, Wq2, bq, qb, tA, Wwk2, bwk, tk);

    // 3) fused k / v / tq projections
    gemm_kvt_kernel<<<dim3(8, (B_ * S_) / 128, 3), 256, GEMM_SMEM_BYTES>>>(
        kvA, Wk2, bk, kb, Wv2, bv, v2, Wwq2, bwq, tq);

    // 4) masked-mean weights
    weights_kernel<<<B_ * H_, 256>>>(tq, tk, mask, w);

    // 5) tensor-core flash attention -> ctxA (hi|lo)
    attn_tc_kernel<<<dim3(T_ / 128, B_ * H_), 256>>>(qb, kb, v2, w, ctxA);

    // 6) output projection
    gemm_out_kernel<<<dim3(8, (B_ * T_) / 128), 256, GEMM_SMEM_BYTES>>>(
        ctxA, Wo2, bo, out);
}

// round 11
// speedup vs baseline: 2.5310x; 1.3089x over previous
#include <cuda_runtime.h>
#include <cuda_bf16.h>
#include <cstdint>

// ============================================================================
// KTMutualAttention — mma.sync bf16 GEMMs with precision-budgeted terms:
//   logit-path projections (q, k, tq, tk) = 1-term bf16 (hi*hi only)
//   value-path projections (v, out)       = 3-term split (hi*hi+hi*lo+lo*hi)
//   + mma.sync flash attention (bf16 QK, 3-term PV), fused epilogue formats.
//   B=8, T=512, S=1024, TL=64, D=1024, H=16, hd=64
// ============================================================================

#define B_   8
#define T_   512
#define S_   1024
#define TL_  64
#define D_   1024
#define H_   16
#define HD_  64
#define SCALING_ 0.125f
#define K2_  2048          // [hi|lo] split width

#define MODE_F32   0
#define MODE_BF16  1
#define MODE_SPLIT 2

// ---------------------------------------------------------------------------
// scratch (device globals)
// ---------------------------------------------------------------------------
__device__ __align__(256) float g_tq [B_ * S_ * D_];
__device__ __align__(256) float g_tk [B_ * TL_ * D_];
__device__ __align__(256) float g_w  [B_ * H_ * S_];

__device__ __align__(256) __nv_bfloat16 g_qb  [(size_t)B_ * T_ * D_];
__device__ __align__(256) __nv_bfloat16 g_kb  [(size_t)B_ * S_ * D_];
__device__ __align__(256) __nv_bfloat16 g_v2  [(size_t)B_ * S_ * K2_];

__device__ __align__(256) __nv_bfloat16 g_hA  [(size_t)B_ * T_  * K2_];
__device__ __align__(256) __nv_bfloat16 g_kvA [(size_t)B_ * S_  * K2_];
__device__ __align__(256) __nv_bfloat16 g_tA  [(size_t)B_ * TL_ * K2_];
__device__ __align__(256) __nv_bfloat16 g_ctxA[(size_t)B_ * T_  * K2_];
__device__ __align__(256) __nv_bfloat16 g_Wq2 [(size_t)D_ * K2_];
__device__ __align__(256) __nv_bfloat16 g_Wk2 [(size_t)D_ * K2_];
__device__ __align__(256) __nv_bfloat16 g_Wv2 [(size_t)D_ * K2_];
__device__ __align__(256) __nv_bfloat16 g_Wwq2[(size_t)D_ * K2_];
__device__ __align__(256) __nv_bfloat16 g_Wwk2[(size_t)D_ * K2_];
__device__ __align__(256) __nv_bfloat16 g_Wo2 [(size_t)D_ * K2_];

// ---------------------------------------------------------------------------
// PTX helpers (portable sm_80+)
// ---------------------------------------------------------------------------
__device__ __forceinline__ uint32_t smem_u32(const void* p) {
    uint32_t a;
    asm("{ .reg .u64 t; cvta.to.shared.u64 t, %1; cvt.u32.u64 %0, t; }"
        : "=r"(a) : "l"(p));
    return a;
}

#define CP_ASYNC16(dst_u32, src_ptr) \
    asm volatile("cp.async.cg.shared.global [%0], [%1], 16;" \
                 :: "r"(dst_u32), "l"(src_ptr) : "memory")
#define CP_COMMIT() asm volatile("cp.async.commit_group;" ::: "memory")
#define CP_WAIT2()  asm volatile("cp.async.wait_group 2;" ::: "memory")

__device__ __forceinline__ void ldmatrix_x4(uint32_t& r0, uint32_t& r1,
                                            uint32_t& r2, uint32_t& r3,
                                            uint32_t addr)
{
    asm volatile("ldmatrix.sync.aligned.m8n8.x4.shared.b16 {%0,%1,%2,%3}, [%4];"
                 : "=r"(r0), "=r"(r1), "=r"(r2), "=r"(r3) : "r"(addr));
}

__device__ __forceinline__ void ldmatrix_x4_trans(uint32_t& r0, uint32_t& r1,
                                                  uint32_t& r2, uint32_t& r3,
                                                  uint32_t addr)
{
    asm volatile("ldmatrix.sync.aligned.m8n8.x4.trans.shared.b16 {%0,%1,%2,%3}, [%4];"
                 : "=r"(r0), "=r"(r1), "=r"(r2), "=r"(r3) : "r"(addr));
}

__device__ __forceinline__ void mma_bf16(float* c, uint32_t a0, uint32_t a1,
                                         uint32_t a2, uint32_t a3,
                                         uint32_t b0, uint32_t b1)
{
    asm volatile(
        "mma.sync.aligned.m16n8k16.row.col.f32.bf16.bf16.f32 "
        "{%0,%1,%2,%3}, {%4,%5,%6,%7}, {%8,%9}, {%0,%1,%2,%3};"
        : "+f"(c[0]), "+f"(c[1]), "+f"(c[2]), "+f"(c[3])
        : "r"(a0), "r"(a1), "r"(a2), "r"(a3), "r"(b0), "r"(b1));
}

__device__ __forceinline__ uint32_t pack_bf162(float x, float y)
{
    __nv_bfloat162 t = __floats2bfloat162_rn(x, y);
    return *reinterpret_cast<uint32_t*>(&t);
}

__device__ __forceinline__ void split_pair(float x, float y,
                                           uint32_t& hi, uint32_t& lo)
{
    __nv_bfloat16 hx = __float2bfloat16_rn(x);
    __nv_bfloat16 hy = __float2bfloat16_rn(y);
    __nv_bfloat162 th(hx, hy);
    hi = *reinterpret_cast<uint32_t*>(&th);
    __nv_bfloat162 tl(__float2bfloat16_rn(x - __bfloat162float(hx)),
                      __float2bfloat16_rn(y - __bfloat162float(hy)));
    lo = *reinterpret_cast<uint32_t*>(&tl);
}

// ---------------------------------------------------------------------------
// fp32 -> bf16 hi|lo split kernel
// ---------------------------------------------------------------------------
__global__ __launch_bounds__(256)
void split_kernel(const float* __restrict__ x, __nv_bfloat16* __restrict__ y)
{
    const int idx = blockIdx.x * 256 + threadIdx.x;
    const int row = idx >> 8;
    const int c4  = (idx & 255) * 4;
    const float4 v = *reinterpret_cast<const float4*>(x + ((size_t)row << 10) + c4);

    uint32_t h0, l0, h1, l1;
    split_pair(v.x, v.y, h0, l0);
    split_pair(v.z, v.w, h1, l1);
    uint32_t* dh = reinterpret_cast<uint32_t*>(y + (size_t)row * K2_ + c4);
    dh[0] = h0; dh[1] = h1;
    uint32_t* dl = reinterpret_cast<uint32_t*>(y + (size_t)row * K2_ + 1024 + c4);
    dl[0] = l0; dl[1] = l1;
}

// ---------------------------------------------------------------------------
// GEMM core: out[bm:+128, bn:+128] = scale*(A@W^T + bias)
//   nchunk = 32 (1-term hi*hi) or 96 (3-term), 4-stage cp.async ring.
// ---------------------------------------------------------------------------
#define BK 32
#define SROW 40
#define STAGES 4
#define STAGE_ELEMS (128 * SROW)
#define GEMM_SMEM_BYTES (STAGES * STAGE_ELEMS * 2 * 2)

__device__ __forceinline__
void gemm_core(const __nv_bfloat16* __restrict__ A,
               const __nv_bfloat16* __restrict__ W,
               const float* __restrict__ bias,
               void* __restrict__ out, float scale, int mode, int nchunk,
               int bm, int bn, __nv_bfloat16* smem)
{
    __nv_bfloat16* sA = smem;
    __nv_bfloat16* sB = smem + STAGES * STAGE_ELEMS;
    __shared__ float biasS[128];

    const int tid = threadIdx.x;
    const int wid = tid >> 5, lane = tid & 31;
    const int wm = wid & 3;
    const int wn = wid >> 2;

    if (tid < 128) biasS[tid] = bias[bn + tid];

    const __nv_bfloat16* Ag = A + (size_t)bm * K2_;
    const __nv_bfloat16* Wg = W + (size_t)bn * K2_;

    const int ldrow = tid >> 1;
    const int ldoff = (tid & 1) * 16;

    const uint32_t sAu = smem_u32(sA);
    const uint32_t sBu = smem_u32(sB);

    auto stage = [&](int c) {
        const int slot = c & (STAGES - 1);
        const int seg = c >> 5;
        const int col = (c & 31) * BK;
        const int gA = ((seg == 2) ? 1024 : 0) + col;   // A: hi,hi,lo
        const int gW = ((seg == 1) ? 1024 : 0) + col;   // W: hi,lo,hi
        const size_t ga = (size_t)ldrow * K2_ + gA + ldoff;
        const size_t gw = (size_t)ldrow * K2_ + gW + ldoff;
        const uint32_t sa = sAu + (slot * STAGE_ELEMS + ldrow * SROW + ldoff) * 2;
        const uint32_t sb = sBu + (slot * STAGE_ELEMS + ldrow * SROW + ldoff) * 2;
        CP_ASYNC16(sa,      Ag + ga);
        CP_ASYNC16(sa + 16, Ag + ga + 8);
        CP_ASYNC16(sb,      Wg + gw);
        CP_ASYNC16(sb + 16, Wg + gw + 8);
    };

    float acc[2][8][4];
#pragma unroll
    for (int mt = 0; mt < 2; mt++)
#pragma unroll
        for (int nf = 0; nf < 8; nf++)
#pragma unroll
            for (int r = 0; r < 4; r++) acc[mt][nf][r] = 0.f;

    stage(0); CP_COMMIT();
    stage(1); CP_COMMIT();
    stage(2); CP_COMMIT();

    const int lrow = lane & 15;
    const int lcol = (lane >> 4) * 16;

    for (int c = 0; c < nchunk; ++c) {
        CP_WAIT2();
        __syncthreads();

        if (c + 3 < nchunk) { stage(c + 3); CP_COMMIT(); }
        else { CP_COMMIT(); }   // keep group-count accounting uniform

        const int slot = c & (STAGES - 1);
        const uint32_t aBase = sAu + slot * STAGE_ELEMS * 2;
        const uint32_t bBase = sBu + slot * STAGE_ELEMS * 2;

#pragma unroll
        for (int kk = 0; kk < 2; kk++) {
            const int kbyte = kk * 32 + lcol;

            uint32_t a[2][4];
#pragma unroll
            for (int mt = 0; mt < 2; mt++) {
                const int row = wm * 32 + mt * 16 + lrow;
                ldmatrix_x4(a[mt][0], a[mt][1], a[mt][2], a[mt][3],
                            aBase + row * (SROW * 2) + kbyte);
            }
            uint32_t b[4][4];
#pragma unroll
            for (int nb = 0; nb < 4; nb++) {
                const int row = wn * 64 + nb * 16 + lrow;
                ldmatrix_x4(b[nb][0], b[nb][1], b[nb][2], b[nb][3],
                            bBase + row * (SROW * 2) + kbyte);
            }
#pragma unroll
            for (int mt = 0; mt < 2; mt++)
#pragma unroll
                for (int nf = 0; nf < 8; nf++) {
                    const int nb = nf >> 1;
                    const uint32_t b0 = (nf & 1) ? b[nb][1] : b[nb][0];
                    const uint32_t b1 = (nf & 1) ? b[nb][3] : b[nb][2];
                    mma_bf16(acc[mt][nf], a[mt][0], a[mt][1], a[mt][2], a[mt][3],
                             b0, b1);
                }
        }
    }

    const int g_  = lane >> 2;
    const int tig = lane & 3;
#pragma unroll
    for (int mt = 0; mt < 2; mt++) {
        const int row0 = bm + wm * 32 + mt * 16 + g_;
#pragma unroll
        for (int nf = 0; nf < 8; nf++) {
            const int lc  = wn * 64 + nf * 8 + tig * 2;
            const int col = bn + lc;
            const float b0 = biasS[lc], b1 = biasS[lc + 1];
            const float x0 = scale * (acc[mt][nf][0] + b0);
            const float x1 = scale * (acc[mt][nf][1] + b1);
            const float x2 = scale * (acc[mt][nf][2] + b0);
            const float x3 = scale * (acc[mt][nf][3] + b1);
            if (mode == MODE_F32) {
                float* C = (float*)out;
                *reinterpret_cast<float2*>(C + (size_t)row0 * 1024 + col)
                    = make_float2(x0, x1);
                *reinterpret_cast<float2*>(C + (size_t)(row0 + 8) * 1024 + col)
                    = make_float2(x2, x3);
            } else if (mode == MODE_BF16) {
                __nv_bfloat16* C = (__nv_bfloat16*)out;
                *reinterpret_cast<uint32_t*>(C + (size_t)row0 * 1024 + col)
                    = pack_bf162(x0, x1);
                *reinterpret_cast<uint32_t*>(C + (size_t)(row0 + 8) * 1024 + col)
                    = pack_bf162(x2, x3);
            } else {
                __nv_bfloat16* C = (__nv_bfloat16*)out;
                uint32_t h0, l0, h1, l1;
                split_pair(x0, x1, h0, l0);
                split_pair(x2, x3, h1, l1);
                *reinterpret_cast<uint32_t*>(C + (size_t)row0 * K2_ + col) = h0;
                *reinterpret_cast<uint32_t*>(C + (size_t)row0 * K2_ + 1024 + col) = l0;
                *reinterpret_cast<uint32_t*>(C + (size_t)(row0 + 8) * K2_ + col) = h1;
                *reinterpret_cast<uint32_t*>(C + (size_t)(row0 + 8) * K2_ + 1024 + col) = l1;
            }
        }
    }
}

// 1-term logit-path GEMMs: q(256) + k(512) + tq(512) + tk(32) = 1312 CTAs
__global__ __launch_bounds__(256, 2)
void gemm_logit_kernel(const __nv_bfloat16* __restrict__ hA,
                       const __nv_bfloat16* __restrict__ Wq2,
                       const float* __restrict__ bq,
                       __nv_bfloat16* __restrict__ qb,
                       const __nv_bfloat16* __restrict__ kvA,
                       const __nv_bfloat16* __restrict__ Wk2,
                       const float* __restrict__ bk,
                       __nv_bfloat16* __restrict__ kb,
                       const __nv_bfloat16* __restrict__ Wwq2,
                       const float* __restrict__ bwq,
                       float* __restrict__ tq,
                       const __nv_bfloat16* __restrict__ tA,
                       const __nv_bfloat16* __restrict__ Wwk2,
                       const float* __restrict__ bwk,
                       float* __restrict__ tk)
{
    extern __shared__ __nv_bfloat16 smem[];
    const int x = blockIdx.x;
    if (x < 256) {
        gemm_core(hA, Wq2, bq, qb, SCALING_, MODE_BF16, 32,
                  (x >> 3) * 128, (x & 7) * 128, smem);
    } else if (x < 768) {
        const int t = x - 256;
        gemm_core(kvA, Wk2, bk, kb, 1.0f, MODE_BF16, 32,
                  (t >> 3) * 128, (t & 7) * 128, smem);
    } else if (x < 1280) {
        const int t = x - 768;
        gemm_core(kvA, Wwq2, bwq, tq, SCALING_, MODE_F32, 32,
                  (t >> 3) * 128, (t & 7) * 128, smem);
    } else {
        const int t = x - 1280;
        gemm_core(tA, Wwk2, bwk, tk, 1.0f, MODE_F32, 32,
                  (t >> 3) * 128, (t & 7) * 128, smem);
    }
}

// 3-term v projection (hi|lo out)
__global__ __launch_bounds__(256, 2)
void gemm_v_kernel(const __nv_bfloat16* __restrict__ kvA,
                   const __nv_bfloat16* __restrict__ Wv2,
                   const float* __restrict__ bv,
                   __nv_bfloat16* __restrict__ v2)
{
    extern __shared__ __nv_bfloat16 smem[];
    gemm_core(kvA, Wv2, bv, v2, 1.0f, MODE_SPLIT, 96,
              blockIdx.y * 128, blockIdx.x * 128, smem);
}

// 3-term out projection (fp32 out)
__global__ __launch_bounds__(256, 2)
void gemm_out_kernel(const __nv_bfloat16* __restrict__ A,
                     const __nv_bfloat16* __restrict__ W,
                     const float* __restrict__ bias,
                     float* __restrict__ C)
{
    extern __shared__ __nv_bfloat16 smem[];
    gemm_core(A, W, bias, C, 1.0f, MODE_F32, 96,
              blockIdx.y * 128, blockIdx.x * 128, smem);
}

// ---------------------------------------------------------------------------
// weights[b,h,s] = (tq . (mask @ tk)) / sum(mask)
// ---------------------------------------------------------------------------
__global__ __launch_bounds__(256)
void weights_kernel(const float* __restrict__ tq, const float* __restrict__ tk,
                    const float* __restrict__ mask, float* __restrict__ wgt)
{
    const int bh = blockIdx.x;
    const int b = bh >> 4;
    const int h = bh & 15;

    __shared__ float tks[TL_][HD_];

    const int tid = threadIdx.x;
    for (int idx = tid; idx < TL_ * HD_; idx += 256) {
        const int t = idx >> 6, d = idx & 63;
        tks[t][d] = tk[((size_t)b * TL_ + t) * D_ + h * HD_ + d];
    }
    __syncthreads();

    const int warp = tid >> 5, lane = tid & 31;

    for (int s = warp; s < S_; s += 8) {
        const size_t tqo = ((size_t)b * S_ + s) * D_ + h * HD_;
        const float tq0 = __ldg(&tq[tqo + lane]);
        const float tq1 = __ldg(&tq[tqo + lane + 32]);
        const float* mrow = mask + ((size_t)b * S_ + s) * TL_;

        float mk0 = 0.f, mk1 = 0.f, cnt = 0.f;
#pragma unroll
        for (int t = 0; t < TL_; t++) {
            const float m = __ldg(&mrow[t]);
            cnt += m;
            mk0 = fmaf(m, tks[t][lane], mk0);
            mk1 = fmaf(m, tks[t][lane + 32], mk1);
        }
        float dotv = tq0 * mk0 + tq1 * mk1;
#pragma unroll
        for (int off = 16; off; off >>= 1)
            dotv += __shfl_xor_sync(0xffffffffu, dotv, off);

        if (lane == 0)
            wgt[(size_t)bh * S_ + s] = dotv / cnt;
    }
}

// ---------------------------------------------------------------------------
// fast exp on FMA pipe
// ---------------------------------------------------------------------------
__device__ __forceinline__ float fast_exp(float x)
{
    const float y = x * 1.44269504088896341f;
    const float n = rintf(y);
    const float t = (y - n) * 0.69314718055994531f;
    float p = 1.9841269841e-4f;
    p = fmaf(p, t, 1.38888888889e-3f);
    p = fmaf(p, t, 8.33333333333e-3f);
    p = fmaf(p, t, 4.16666666667e-2f);
    p = fmaf(p, t, 1.66666666667e-1f);
    p = fmaf(p, t, 0.5f);
    p = fmaf(p, t, 1.0f);
    p = fmaf(p, t, 1.0f);
    int e = (int)n;
    e = e < -126 ? -126 : e;
    const float s = __int_as_float((e + 127) << 23);
    return p * s;
}

// ---------------------------------------------------------------------------
// Tensor-core flash attention; operands pre-converted bf16. ctxA hi|lo out.
// ---------------------------------------------------------------------------
#define VPAD 72

__global__ __launch_bounds__(256)
void attn_tc_kernel(const __nv_bfloat16* __restrict__ qb,
                    const __nv_bfloat16* __restrict__ kb,
                    const __nv_bfloat16* __restrict__ v2,
                    const float* __restrict__ wgt,
                    __nv_bfloat16* __restrict__ ctxA)
{
    __shared__ __nv_bfloat16 sQ [128 * VPAD];
    __shared__ __nv_bfloat16 sK [64 * VPAD];
    __shared__ __nv_bfloat16 sVh[64 * VPAD];
    __shared__ __nv_bfloat16 sVl[64 * VPAD];
    __shared__ float ws[64];

    const int qt = blockIdx.x, bh = blockIdx.y;
    const int b = bh >> 4, h = bh & 15;
    const int tid = threadIdx.x, wid = tid >> 5, lane = tid & 31;
    const int g = lane >> 2, tig = lane & 3;
    const int lrow = lane & 15, lcolb = (lane >> 4) * 16;

    const int trow = ((lane >> 3) & 1) * 8 + (lane & 7);
    const int tcol = (lane >> 4) * 8;

    const size_t qbase = ((size_t)b * T_ + qt * 128) * D_ + h * HD_;
#pragma unroll
    for (int it = 0; it < 4; ++it) {
        const int idx = it * 256 + tid;
        const int r = idx >> 3, c8 = (idx & 7) * 8;
        const uint4 t = *reinterpret_cast<const uint4*>(qb + qbase + (size_t)r * D_ + c8);
        *reinterpret_cast<uint4*>(&sQ[r * VPAD + c8]) = t;
    }

    float o[8][4];
#pragma unroll
    for (int nf = 0; nf < 8; nf++)
#pragma unroll
        for (int r = 0; r < 4; r++) o[nf][r] = 0.f;
    float m0 = -1e30f, m1 = -1e30f, l0 = 0.f, l1 = 0.f;

    const uint32_t sQb = smem_u32(sQ), sKb = smem_u32(sK);
    const uint32_t sVhb = smem_u32(sVh), sVlb = smem_u32(sVl);

    const float* wrow = wgt + (size_t)bh * S_;

    for (int sc = 0; sc < S_ / 64; ++sc) {
        __syncthreads();
        const size_t krow0 = (size_t)b * S_ + sc * 64;
#pragma unroll
        for (int it = 0; it < 2; ++it) {
            const int idx = it * 256 + tid;
            const int r = idx >> 3, c8 = (idx & 7) * 8;
            const uint4 tk4 = *reinterpret_cast<const uint4*>(
                kb + (krow0 + r) * D_ + h * HD_ + c8);
            *reinterpret_cast<uint4*>(&sK[r * VPAD + c8]) = tk4;
            const uint4 th4 = *reinterpret_cast<const uint4*>(
                v2 + (krow0 + r) * K2_ + h * HD_ + c8);
            *reinterpret_cast<uint4*>(&sVh[r * VPAD + c8]) = th4;
            const uint4 tl4 = *reinterpret_cast<const uint4*>(
                v2 + (krow0 + r) * K2_ + 1024 + h * HD_ + c8);
            *reinterpret_cast<uint4*>(&sVl[r * VPAD + c8]) = tl4;
        }
        if (tid < 64) ws[tid] = wrow[sc * 64 + tid];
        __syncthreads();

        float sv[8][4];
#pragma unroll
        for (int nf = 0; nf < 8; nf++)
#pragma unroll
            for (int r = 0; r < 4; r++) sv[nf][r] = 0.f;

#pragma unroll
        for (int kk = 0; kk < 4; kk++) {
            const int kb_ = kk * 32 + lcolb;
            uint32_t a0, a1, a2, a3;
            ldmatrix_x4(a0, a1, a2, a3,
                        sQb + (wid * 16 + lrow) * (VPAD * 2) + kb_);
#pragma unroll
            for (int nb = 0; nb < 4; nb++) {
                uint32_t b0, b1, b2, b3;
                ldmatrix_x4(b0, b1, b2, b3,
                            sKb + (nb * 16 + lrow) * (VPAD * 2) + kb_);
                mma_bf16(sv[2 * nb],     a0, a1, a2, a3, b0, b2);
                mma_bf16(sv[2 * nb + 1], a0, a1, a2, a3, b1, b3);
            }
        }

#pragma unroll
        for (int nf = 0; nf < 8; nf++) {
            const int col = nf * 8 + tig * 2;
            const float w0 = ws[col], w1 = ws[col + 1];
            sv[nf][0] *= w0; sv[nf][1] *= w1;
            sv[nf][2] *= w0; sv[nf][3] *= w1;
        }

        float mx0 = -1e30f, mx1 = -1e30f;
#pragma unroll
        for (int nf = 0; nf < 8; nf++) {
            mx0 = fmaxf(mx0, fmaxf(sv[nf][0], sv[nf][1]));
            mx1 = fmaxf(mx1, fmaxf(sv[nf][2], sv[nf][3]));
        }
        mx0 = fmaxf(mx0, __shfl_xor_sync(0xffffffffu, mx0, 1));
        mx0 = fmaxf(mx0, __shfl_xor_sync(0xffffffffu, mx0, 2));
        mx1 = fmaxf(mx1, __shfl_xor_sync(0xffffffffu, mx1, 1));
        mx1 = fmaxf(mx1, __shfl_xor_sync(0xffffffffu, mx1, 2));

        const float mn0 = fmaxf(m0, mx0), mn1 = fmaxf(m1, mx1);
        const float al0 = fast_exp(m0 - mn0), al1 = fast_exp(m1 - mn1);
        m0 = mn0; m1 = mn1;

        float s0 = 0.f, s1 = 0.f;
#pragma unroll
        for (int nf = 0; nf < 8; nf++) {
            sv[nf][0] = fast_exp(sv[nf][0] - mn0);
            sv[nf][1] = fast_exp(sv[nf][1] - mn0);
            sv[nf][2] = fast_exp(sv[nf][2] - mn1);
            sv[nf][3] = fast_exp(sv[nf][3] - mn1);
            s0 += sv[nf][0] + sv[nf][1];
            s1 += sv[nf][2] + sv[nf][3];
        }
        s0 += __shfl_xor_sync(0xffffffffu, s0, 1);
        s0 += __shfl_xor_sync(0xffffffffu, s0, 2);
        s1 += __shfl_xor_sync(0xffffffffu, s1, 1);
        s1 += __shfl_xor_sync(0xffffffffu, s1, 2);
        l0 = l0 * al0 + s0;
        l1 = l1 * al1 + s1;

#pragma unroll
        for (int nf = 0; nf < 8; nf++) {
            o[nf][0] *= al0; o[nf][1] *= al0;
            o[nf][2] *= al1; o[nf][3] *= al1;
        }

#pragma unroll
        for (int j = 0; j < 4; j++) {
            uint32_t ph[4], pl[4];
            split_pair(sv[2 * j][0],     sv[2 * j][1],     ph[0], pl[0]);
            split_pair(sv[2 * j][2],     sv[2 * j][3],     ph[1], pl[1]);
            split_pair(sv[2 * j + 1][0], sv[2 * j + 1][1], ph[2], pl[2]);
            split_pair(sv[2 * j + 1][2], sv[2 * j + 1][3], ph[3], pl[3]);

            const uint32_t vrow = (j * 16 + trow) * (VPAD * 2);
#pragma unroll
            for (int nb = 0; nb < 4; nb++) {
                const uint32_t vaddr = vrow + (nb * 16 + tcol) * 2;
                uint32_t h0, h1, h2, h3, q0, q1, q2, q3;
                ldmatrix_x4_trans(h0, h1, h2, h3, sVhb + vaddr);
                ldmatrix_x4_trans(q0, q1, q2, q3, sVlb + vaddr);
                mma_bf16(o[2 * nb],     ph[0], ph[1], ph[2], ph[3], h0, h1);
                mma_bf16(o[2 * nb + 1], ph[0], ph[1], ph[2], ph[3], h2, h3);
                mma_bf16(o[2 * nb],     ph[0], ph[1], ph[2], ph[3], q0, q1);
                mma_bf16(o[2 * nb + 1], ph[0], ph[1], ph[2], ph[3], q2, q3);
                mma_bf16(o[2 * nb],     pl[0], pl[1], pl[2], pl[3], h0, h1);
                mma_bf16(o[2 * nb + 1], pl[0], pl[1], pl[2], pl[3], h2, h3);
            }
        }
    }

    const float inv0 = 1.0f / l0, inv1 = 1.0f / l1;
    const int row0 = qt * 128 + wid * 16 + g;
#pragma unroll
    for (int nf = 0; nf < 8; nf++) {
        const int col = h * HD_ + nf * 8 + tig * 2;
        uint32_t h0, l0w, h1, l1w;
        split_pair(o[nf][0] * inv0, o[nf][1] * inv0, h0, l0w);
        split_pair(o[nf][2] * inv1, o[nf][3] * inv1, h1, l1w);
        const size_t r0 = ((size_t)b * T_ + row0) * K2_;
        const size_t r1 = ((size_t)b * T_ + row0 + 8) * K2_;
        *reinterpret_cast<uint32_t*>(ctxA + r0 + col)        = h0;
        *reinterpret_cast<uint32_t*>(ctxA + r0 + 1024 + col) = l0w;
        *reinterpret_cast<uint32_t*>(ctxA + r1 + col)        = h1;
        *reinterpret_cast<uint32_t*>(ctxA + r1 + 1024 + col) = l1w;
    }
}

// ---------------------------------------------------------------------------
// launch
// ---------------------------------------------------------------------------
extern "C" void kernel_launch(void* const* d_in, const int* in_sizes, int n_in,
                              void* d_out, int out_size)
{
    const float* hidden = (const float*)d_in[0];
    const float* kv     = (const float*)d_in[1];
    const float* target = (const float*)d_in[2];
    const float* mask   = (const float*)d_in[3];
    const float* Wq  = (const float*)d_in[4];
    const float* bq  = (const float*)d_in[5];
    const float* Wk  = (const float*)d_in[6];
    const float* bk  = (const float*)d_in[7];
    const float* Wv  = (const float*)d_in[8];
    const float* bv  = (const float*)d_in[9];
    const float* Wwq = (const float*)d_in[10];
    const float* bwq = (const float*)d_in[11];
    const float* Wwk = (const float*)d_in[12];
    const float* bwk = (const float*)d_in[13];
    const float* Wo  = (const float*)d_in[14];
    const float* bo  = (const float*)d_in[15];
    float* out = (float*)d_out;

    float *tq, *tk, *w;
    cudaGetSymbolAddress((void**)&tq,  g_tq);
    cudaGetSymbolAddress((void**)&tk,  g_tk);
    cudaGetSymbolAddress((void**)&w,   g_w);

    __nv_bfloat16 *qb, *kb, *v2;
    cudaGetSymbolAddress((void**)&qb, g_qb);
    cudaGetSymbolAddress((void**)&kb, g_kb);
    cudaGetSymbolAddress((void**)&v2, g_v2);

    __nv_bfloat16 *hA, *kvA, *tA, *ctxA, *Wq2, *Wk2, *Wv2, *Wwq2, *Wwk2, *Wo2;
    cudaGetSymbolAddress((void**)&hA,   g_hA);
    cudaGetSymbolAddress((void**)&kvA,  g_kvA);
    cudaGetSymbolAddress((void**)&tA,   g_tA);
    cudaGetSymbolAddress((void**)&ctxA, g_ctxA);
    cudaGetSymbolAddress((void**)&Wq2,  g_Wq2);
    cudaGetSymbolAddress((void**)&Wk2,  g_Wk2);
    cudaGetSymbolAddress((void**)&Wv2,  g_Wv2);
    cudaGetSymbolAddress((void**)&Wwq2, g_Wwq2);
    cudaGetSymbolAddress((void**)&Wwk2, g_Wwk2);
    cudaGetSymbolAddress((void**)&Wo2,  g_Wo2);

    cudaFuncSetAttribute(gemm_logit_kernel,
                         cudaFuncAttributeMaxDynamicSharedMemorySize, GEMM_SMEM_BYTES);
    cudaFuncSetAttribute(gemm_v_kernel,
                         cudaFuncAttributeMaxDynamicSharedMemorySize, GEMM_SMEM_BYTES);
    cudaFuncSetAttribute(gemm_out_kernel,
                         cudaFuncAttributeMaxDynamicSharedMemorySize, GEMM_SMEM_BYTES);

    // 1) fp32 -> bf16 hi|lo splits
    split_kernel<<<B_ * T_,  256>>>(hidden, hA);
    split_kernel<<<B_ * S_,  256>>>(kv,     kvA);
    split_kernel<<<B_ * TL_, 256>>>(target, tA);
    split_kernel<<<D_, 256>>>(Wq,  Wq2);
    split_kernel<<<D_, 256>>>(Wk,  Wk2);
    split_kernel<<<D_, 256>>>(Wv,  Wv2);
    split_kernel<<<D_, 256>>>(Wwq, Wwq2);
    split_kernel<<<D_, 256>>>(Wwk, Wwk2);
    split_kernel<<<D_, 256>>>(Wo,  Wo2);

    // 2) 1-term logit-path projections (q, k, tq, tk) — one launch
    gemm_logit_kernel<<<1312, 256, GEMM_SMEM_BYTES>>>(
        hA, Wq2, bq, qb,
        kvA, Wk2, bk, kb, Wwq2, bwq, tq,
        tA, Wwk2, bwk, tk);

    // 3) 3-term v projection
    gemm_v_kernel<<<dim3(8, (B_ * S_) / 128), 256, GEMM_SMEM_BYTES>>>(
        kvA, Wv2, bv, v2);

    // 4) masked-mean weights
    weights_kernel<<<B_ * H_, 256>>>(tq, tk, mask, w);

    // 5) tensor-core flash attention -> ctxA (hi|lo)
    attn_tc_kernel<<<dim3(T_ / 128, B_ * H_), 256>>>(qb, kb, v2, w, ctxA);

    // 6) 3-term output projection
    gemm_out_kernel<<<dim3(8, (B_ * T_) / 128), 256, GEMM_SMEM_BYTES>>>(
        ctxA, Wo2, bo, out);
}

// round 12
// speedup vs baseline: 2.7080x; 1.0699x over previous
#include <cuda_runtime.h>
#include <cuda_bf16.h>
#include <cstdint>

// ============================================================================
// KTMutualAttention — consolidated-launch pipeline:
//   1 convert launch (dense bf16 for 1-term operands, hi|lo for 3-term)
//   1 pre-attention GEMM mega-launch (v heavy-first + q/k/tq/tk light)
//   weights, flash attention, out-projection.
//   B=8, T=512, S=1024, TL=64, D=1024, H=16, hd=64
// ============================================================================

#define B_   8
#define T_   512
#define S_   1024
#define TL_  64
#define D_   1024
#define H_   16
#define HD_  64
#define SCALING_ 0.125f
#define K2_  2048

#define MODE_F32   0
#define MODE_BF16  1
#define MODE_SPLIT 2

// ---------------------------------------------------------------------------
// scratch (device globals)
// ---------------------------------------------------------------------------
__device__ __align__(256) float g_tq [B_ * S_ * D_];
__device__ __align__(256) float g_tk [B_ * TL_ * D_];
__device__ __align__(256) float g_w  [B_ * H_ * S_];

__device__ __align__(256) __nv_bfloat16 g_qb  [(size_t)B_ * T_ * D_];
__device__ __align__(256) __nv_bfloat16 g_kb  [(size_t)B_ * S_ * D_];
__device__ __align__(256) __nv_bfloat16 g_v2  [(size_t)B_ * S_ * K2_];

// dense bf16 (1-term operands)
__device__ __align__(256) __nv_bfloat16 g_hb  [(size_t)B_ * T_  * D_];
__device__ __align__(256) __nv_bfloat16 g_tb  [(size_t)B_ * TL_ * D_];
__device__ __align__(256) __nv_bfloat16 g_Wqb [(size_t)D_ * D_];
__device__ __align__(256) __nv_bfloat16 g_Wkb [(size_t)D_ * D_];
__device__ __align__(256) __nv_bfloat16 g_Wwqb[(size_t)D_ * D_];
__device__ __align__(256) __nv_bfloat16 g_Wwkb[(size_t)D_ * D_];

// hi|lo split (3-term operands)
__device__ __align__(256) __nv_bfloat16 g_kvA [(size_t)B_ * S_ * K2_];
__device__ __align__(256) __nv_bfloat16 g_ctxA[(size_t)B_ * T_ * K2_];
__device__ __align__(256) __nv_bfloat16 g_Wv2 [(size_t)D_ * K2_];
__device__ __align__(256) __nv_bfloat16 g_Wo2 [(size_t)D_ * K2_];

// ---------------------------------------------------------------------------
// PTX helpers (portable sm_80+)
// ---------------------------------------------------------------------------
__device__ __forceinline__ uint32_t smem_u32(const void* p) {
    uint32_t a;
    asm("{ .reg .u64 t; cvta.to.shared.u64 t, %1; cvt.u32.u64 %0, t; }"
        : "=r"(a) : "l"(p));
    return a;
}

#define CP_ASYNC16(dst_u32, src_ptr) \
    asm volatile("cp.async.cg.shared.global [%0], [%1], 16;" \
                 :: "r"(dst_u32), "l"(src_ptr) : "memory")
#define CP_COMMIT() asm volatile("cp.async.commit_group;" ::: "memory")
#define CP_WAIT2()  asm volatile("cp.async.wait_group 2;" ::: "memory")

__device__ __forceinline__ void ldmatrix_x4(uint32_t& r0, uint32_t& r1,
                                            uint32_t& r2, uint32_t& r3,
                                            uint32_t addr)
{
    asm volatile("ldmatrix.sync.aligned.m8n8.x4.shared.b16 {%0,%1,%2,%3}, [%4];"
                 : "=r"(r0), "=r"(r1), "=r"(r2), "=r"(r3) : "r"(addr));
}

__device__ __forceinline__ void ldmatrix_x4_trans(uint32_t& r0, uint32_t& r1,
                                                  uint32_t& r2, uint32_t& r3,
                                                  uint32_t addr)
{
    asm volatile("ldmatrix.sync.aligned.m8n8.x4.trans.shared.b16 {%0,%1,%2,%3}, [%4];"
                 : "=r"(r0), "=r"(r1), "=r"(r2), "=r"(r3) : "r"(addr));
}

__device__ __forceinline__ void mma_bf16(float* c, uint32_t a0, uint32_t a1,
                                         uint32_t a2, uint32_t a3,
                                         uint32_t b0, uint32_t b1)
{
    asm volatile(
        "mma.sync.aligned.m16n8k16.row.col.f32.bf16.bf16.f32 "
        "{%0,%1,%2,%3}, {%4,%5,%6,%7}, {%8,%9}, {%0,%1,%2,%3};"
        : "+f"(c[0]), "+f"(c[1]), "+f"(c[2]), "+f"(c[3])
        : "r"(a0), "r"(a1), "r"(a2), "r"(a3), "r"(b0), "r"(b1));
}

__device__ __forceinline__ uint32_t pack_bf162(float x, float y)
{
    __nv_bfloat162 t = __floats2bfloat162_rn(x, y);
    return *reinterpret_cast<uint32_t*>(&t);
}

__device__ __forceinline__ void split_pair(float x, float y,
                                           uint32_t& hi, uint32_t& lo)
{
    __nv_bfloat16 hx = __float2bfloat16_rn(x);
    __nv_bfloat16 hy = __float2bfloat16_rn(y);
    __nv_bfloat162 th(hx, hy);
    hi = *reinterpret_cast<uint32_t*>(&th);
    __nv_bfloat162 tl(__float2bfloat16_rn(x - __bfloat162float(hx)),
                      __float2bfloat16_rn(y - __bfloat162float(hy)));
    lo = *reinterpret_cast<uint32_t*>(&tl);
}

// ---------------------------------------------------------------------------
// merged convert kernel: one block = one 1024-float row.
// ranges: [0,4096) hidden->hb CONV | [4096,12288) kv->kvA SPLIT |
// [12288,12800) target->tb CONV | then Wq,Wk,Wwq,Wwk CONV; Wv,Wo SPLIT.
// ---------------------------------------------------------------------------
__global__ __launch_bounds__(256)
void convert_kernel(const float* __restrict__ hidden, __nv_bfloat16* __restrict__ hb,
                    const float* __restrict__ kv,     __nv_bfloat16* __restrict__ kvA,
                    const float* __restrict__ target, __nv_bfloat16* __restrict__ tb,
                    const float* __restrict__ Wq,  __nv_bfloat16* __restrict__ Wqb,
                    const float* __restrict__ Wk,  __nv_bfloat16* __restrict__ Wkb,
                    const float* __restrict__ Wwq, __nv_bfloat16* __restrict__ Wwqb,
                    const float* __restrict__ Wwk, __nv_bfloat16* __restrict__ Wwkb,
                    const float* __restrict__ Wv,  __nv_bfloat16* __restrict__ Wv2,
                    const float* __restrict__ Wo,  __nv_bfloat16* __restrict__ Wo2)
{
    const int x = blockIdx.x;
    const float* src;
    __nv_bfloat16* dst;
    int split, row;
    if (x < 4096)       { src = hidden; dst = hb;   split = 0; row = x; }
    else if (x < 12288) { src = kv;     dst = kvA;  split = 1; row = x - 4096; }
    else if (x < 12800) { src = target; dst = tb;   split = 0; row = x - 12288; }
    else if (x < 13824) { src = Wq;     dst = Wqb;  split = 0; row = x - 12800; }
    else if (x < 14848) { src = Wk;     dst = Wkb;  split = 0; row = x - 13824; }
    else if (x < 15872) { src = Wwq;    dst = Wwqb; split = 0; row = x - 14848; }
    else if (x < 16896) { src = Wwk;    dst = Wwkb; split = 0; row = x - 15872; }
    else if (x < 17920) { src = Wv;     dst = Wv2;  split = 1; row = x - 16896; }
    else                { src = Wo;     dst = Wo2;  split = 1; row = x - 17920; }

    const int c4 = threadIdx.x * 4;
    const float4 v = *reinterpret_cast<const float4*>(src + ((size_t)row << 10) + c4);

    uint32_t h0, l0, h1, l1;
    split_pair(v.x, v.y, h0, l0);
    split_pair(v.z, v.w, h1, l1);
    if (!split) {
        uint32_t* d = reinterpret_cast<uint32_t*>(dst + (size_t)row * D_ + c4);
        d[0] = h0; d[1] = h1;
    } else {
        uint32_t* dh = reinterpret_cast<uint32_t*>(dst + (size_t)row * K2_ + c4);
        dh[0] = h0; dh[1] = h1;
        uint32_t* dl = reinterpret_cast<uint32_t*>(dst + (size_t)row * K2_ + 1024 + c4);
        dl[0] = l0; dl[1] = l1;
    }
}

// ---------------------------------------------------------------------------
// GEMM core with per-operand strides.
//   nchunk = 32 (1-term) or 96 (3-term: A hi,hi,lo / W hi,lo,hi at +1024)
// ---------------------------------------------------------------------------
#define BK 32
#define SROW 40
#define STAGES 4
#define STAGE_ELEMS (128 * SROW)
#define GEMM_SMEM_BYTES (STAGES * STAGE_ELEMS * 2 * 2)

__device__ __forceinline__
void gemm_core(const __nv_bfloat16* __restrict__ A, int astride,
               const __nv_bfloat16* __restrict__ W, int wstride,
               const float* __restrict__ bias,
               void* __restrict__ out, float scale, int mode, int nchunk,
               int bm, int bn, __nv_bfloat16* smem)
{
    __nv_bfloat16* sA = smem;
    __nv_bfloat16* sB = smem + STAGES * STAGE_ELEMS;
    __shared__ float biasS[128];

    const int tid = threadIdx.x;
    const int wid = tid >> 5, lane = tid & 31;
    const int wm = wid & 3;
    const int wn = wid >> 2;

    if (tid < 128) biasS[tid] = bias[bn + tid];

    const __nv_bfloat16* Ag = A + (size_t)bm * astride;
    const __nv_bfloat16* Wg = W + (size_t)bn * wstride;

    const int ldrow = tid >> 1;
    const int ldoff = (tid & 1) * 16;

    const uint32_t sAu = smem_u32(sA);
    const uint32_t sBu = smem_u32(sB);

    auto stage = [&](int c) {
        const int slot = c & (STAGES - 1);
        const int seg = c >> 5;
        const int col = (c & 31) * BK;
        const int aoff = (seg == 2) ? 1024 : 0;
        const int woff = (seg == 1) ? 1024 : 0;
        const size_t ga = (size_t)ldrow * astride + aoff + col + ldoff;
        const size_t gw = (size_t)ldrow * wstride + woff + col + ldoff;
        const uint32_t sa = sAu + (slot * STAGE_ELEMS + ldrow * SROW + ldoff) * 2;
        const uint32_t sb = sBu + (slot * STAGE_ELEMS + ldrow * SROW + ldoff) * 2;
        CP_ASYNC16(sa,      Ag + ga);
        CP_ASYNC16(sa + 16, Ag + ga + 8);
        CP_ASYNC16(sb,      Wg + gw);
        CP_ASYNC16(sb + 16, Wg + gw + 8);
    };

    float acc[2][8][4];
#pragma unroll
    for (int mt = 0; mt < 2; mt++)
#pragma unroll
        for (int nf = 0; nf < 8; nf++)
#pragma unroll
            for (int r = 0; r < 4; r++) acc[mt][nf][r] = 0.f;

    stage(0); CP_COMMIT();
    stage(1); CP_COMMIT();
    stage(2); CP_COMMIT();

    const int lrow = lane & 15;
    const int lcol = (lane >> 4) * 16;

    for (int c = 0; c < nchunk; ++c) {
        CP_WAIT2();
        __syncthreads();

        if (c + 3 < nchunk) { stage(c + 3); CP_COMMIT(); }
        else { CP_COMMIT(); }

        const int slot = c & (STAGES - 1);
        const uint32_t aBase = sAu + slot * STAGE_ELEMS * 2;
        const uint32_t bBase = sBu + slot * STAGE_ELEMS * 2;

#pragma unroll
        for (int kk = 0; kk < 2; kk++) {
            const int kbyte = kk * 32 + lcol;

            uint32_t a[2][4];
#pragma unroll
            for (int mt = 0; mt < 2; mt++) {
                const int row = wm * 32 + mt * 16 + lrow;
                ldmatrix_x4(a[mt][0], a[mt][1], a[mt][2], a[mt][3],
                            aBase + row * (SROW * 2) + kbyte);
            }
            uint32_t b[4][4];
#pragma unroll
            for (int nb = 0; nb < 4; nb++) {
                const int row = wn * 64 + nb * 16 + lrow;
                ldmatrix_x4(b[nb][0], b[nb][1], b[nb][2], b[nb][3],
                            bBase + row * (SROW * 2) + kbyte);
            }
#pragma unroll
            for (int mt = 0; mt < 2; mt++)
#pragma unroll
                for (int nf = 0; nf < 8; nf++) {
                    const int nb = nf >> 1;
                    const uint32_t b0 = (nf & 1) ? b[nb][1] : b[nb][0];
                    const uint32_t b1 = (nf & 1) ? b[nb][3] : b[nb][2];
                    mma_bf16(acc[mt][nf], a[mt][0], a[mt][1], a[mt][2], a[mt][3],
                             b0, b1);
                }
        }
    }

    const int g_  = lane >> 2;
    const int tig = lane & 3;
#pragma unroll
    for (int mt = 0; mt < 2; mt++) {
        const int row0 = bm + wm * 32 + mt * 16 + g_;
#pragma unroll
        for (int nf = 0; nf < 8; nf++) {
            const int lc  = wn * 64 + nf * 8 + tig * 2;
            const int col = bn + lc;
            const float b0 = biasS[lc], b1 = biasS[lc + 1];
            const float x0 = scale * (acc[mt][nf][0] + b0);
            const float x1 = scale * (acc[mt][nf][1] + b1);
            const float x2 = scale * (acc[mt][nf][2] + b0);
            const float x3 = scale * (acc[mt][nf][3] + b1);
            if (mode == MODE_F32) {
                float* C = (float*)out;
                *reinterpret_cast<float2*>(C + (size_t)row0 * 1024 + col)
                    = make_float2(x0, x1);
                *reinterpret_cast<float2*>(C + (size_t)(row0 + 8) * 1024 + col)
                    = make_float2(x2, x3);
            } else if (mode == MODE_BF16) {
                __nv_bfloat16* C = (__nv_bfloat16*)out;
                *reinterpret_cast<uint32_t*>(C + (size_t)row0 * 1024 + col)
                    = pack_bf162(x0, x1);
                *reinterpret_cast<uint32_t*>(C + (size_t)(row0 + 8) * 1024 + col)
                    = pack_bf162(x2, x3);
            } else {
                __nv_bfloat16* C = (__nv_bfloat16*)out;
                uint32_t h0, l0, h1, l1;
                split_pair(x0, x1, h0, l0);
                split_pair(x2, x3, h1, l1);
                *reinterpret_cast<uint32_t*>(C + (size_t)row0 * K2_ + col) = h0;
                *reinterpret_cast<uint32_t*>(C + (size_t)row0 * K2_ + 1024 + col) = l0;
                *reinterpret_cast<uint32_t*>(C + (size_t)(row0 + 8) * K2_ + col) = h1;
                *reinterpret_cast<uint32_t*>(C + (size_t)(row0 + 8) * K2_ + 1024 + col) = l1;
            }
        }
    }
}

// pre-attention GEMM mega-launch: v (512 heavy) first, then q/k/tq/tk light.
__global__ __launch_bounds__(256, 2)
void gemm_pre_kernel(const __nv_bfloat16* __restrict__ kvA,
                     const __nv_bfloat16* __restrict__ Wv2,
                     const float* __restrict__ bv,
                     __nv_bfloat16* __restrict__ v2,
                     const __nv_bfloat16* __restrict__ hb,
                     const __nv_bfloat16* __restrict__ Wqb,
                     const float* __restrict__ bq,
                     __nv_bfloat16* __restrict__ qb,
                     const __nv_bfloat16* __restrict__ Wkb,
                     const float* __restrict__ bk,
                     __nv_bfloat16* __restrict__ kb,
                     const __nv_bfloat16* __restrict__ Wwqb,
                     const float* __restrict__ bwq,
                     float* __restrict__ tq,
                     const __nv_bfloat16* __restrict__ tb,
                     const __nv_bfloat16* __restrict__ Wwkb,
                     const float* __restrict__ bwk,
                     float* __restrict__ tk)
{
    extern __shared__ __nv_bfloat16 smem[];
    const int x = blockIdx.x;
    if (x < 512) {                               // v: 3-term, split out
        gemm_core(kvA, K2_, Wv2, K2_, bv, v2, 1.0f, MODE_SPLIT, 96,
                  (x >> 3) * 128, (x & 7) * 128, smem);
    } else if (x < 768) {                        // q: 1-term
        const int t = x - 512;
        gemm_core(hb, D_, Wqb, D_, bq, qb, SCALING_, MODE_BF16, 32,
                  (t >> 3) * 128, (t & 7) * 128, smem);
    } else if (x < 1280) {                       // k: 1-term (A = kvA hi)
        const int t = x - 768;
        gemm_core(kvA, K2_, Wkb, D_, bk, kb, 1.0f, MODE_BF16, 32,
                  (t >> 3) * 128, (t & 7) * 128, smem);
    } else if (x < 1792) {                       // tq: 1-term
        const int t = x - 1280;
        gemm_core(kvA, K2_, Wwqb, D_, bwq, tq, SCALING_, MODE_F32, 32,
                  (t >> 3) * 128, (t & 7) * 128, smem);
    } else {                                     // tk: 1-term (32 CTAs)
        const int t = x - 1792;
        gemm_core(tb, D_, Wwkb, D_, bwk, tk, 1.0f, MODE_F32, 32,
                  (t >> 3) * 128, (t & 7) * 128, smem);
    }
}

// out projection: 3-term
__global__ __launch_bounds__(256, 2)
void gemm_out_kernel(const __nv_bfloat16* __restrict__ A,
                     const __nv_bfloat16* __restrict__ W,
                     const float* __restrict__ bias,
                     float* __restrict__ C)
{
    extern __shared__ __nv_bfloat16 smem[];
    gemm_core(A, K2_, W, K2_, bias, C, 1.0f, MODE_F32, 96,
              blockIdx.y * 128, blockIdx.x * 128, smem);
}

// ---------------------------------------------------------------------------
// weights[b,h,s] = (tq . (mask @ tk)) / sum(mask)
// ---------------------------------------------------------------------------
__global__ __launch_bounds__(256)
void weights_kernel(const float* __restrict__ tq, const float* __restrict__ tk,
                    const float* __restrict__ mask, float* __restrict__ wgt)
{
    const int bh = blockIdx.x;
    const int b = bh >> 4;
    const int h = bh & 15;

    __shared__ float tks[TL_][HD_];

    const int tid = threadIdx.x;
    for (int idx = tid; idx < TL_ * HD_; idx += 256) {
        const int t = idx >> 6, d = idx & 63;
        tks[t][d] = tk[((size_t)b * TL_ + t) * D_ + h * HD_ + d];
    }
    __syncthreads();

    const int warp = tid >> 5, lane = tid & 31;

    for (int s = warp; s < S_; s += 8) {
        const size_t tqo = ((size_t)b * S_ + s) * D_ + h * HD_;
        const float tq0 = __ldg(&tq[tqo + lane]);
        const float tq1 = __ldg(&tq[tqo + lane + 32]);
        const float* mrow = mask + ((size_t)b * S_ + s) * TL_;

        float mk0 = 0.f, mk1 = 0.f, cnt = 0.f;
#pragma unroll
        for (int t = 0; t < TL_; t++) {
            const float m = __ldg(&mrow[t]);
            cnt += m;
            mk0 = fmaf(m, tks[t][lane], mk0);
            mk1 = fmaf(m, tks[t][lane + 32], mk1);
        }
        float dotv = tq0 * mk0 + tq1 * mk1;
#pragma unroll
        for (int off = 16; off; off >>= 1)
            dotv += __shfl_xor_sync(0xffffffffu, dotv, off);

        if (lane == 0)
            wgt[(size_t)bh * S_ + s] = dotv / cnt;
    }
}

// ---------------------------------------------------------------------------
// fast exp on FMA pipe
// ---------------------------------------------------------------------------
__device__ __forceinline__ float fast_exp(float x)
{
    const float y = x * 1.44269504088896341f;
    const float n = rintf(y);
    const float t = (y - n) * 0.69314718055994531f;
    float p = 1.9841269841e-4f;
    p = fmaf(p, t, 1.38888888889e-3f);
    p = fmaf(p, t, 8.33333333333e-3f);
    p = fmaf(p, t, 4.16666666667e-2f);
    p = fmaf(p, t, 1.66666666667e-1f);
    p = fmaf(p, t, 0.5f);
    p = fmaf(p, t, 1.0f);
    p = fmaf(p, t, 1.0f);
    int e = (int)n;
    e = e < -126 ? -126 : e;
    const float s = __int_as_float((e + 127) << 23);
    return p * s;
}

// ---------------------------------------------------------------------------
// Tensor-core flash attention; bf16 operands; ctxA hi|lo out.
// ---------------------------------------------------------------------------
#define VPAD 72

__global__ __launch_bounds__(256)
void attn_tc_kernel(const __nv_bfloat16* __restrict__ qb,
                    const __nv_bfloat16* __restrict__ kb,
                    const __nv_bfloat16* __restrict__ v2,
                    const float* __restrict__ wgt,
                    __nv_bfloat16* __restrict__ ctxA)
{
    __shared__ __nv_bfloat16 sQ [128 * VPAD];
    __shared__ __nv_bfloat16 sK [64 * VPAD];
    __shared__ __nv_bfloat16 sVh[64 * VPAD];
    __shared__ __nv_bfloat16 sVl[64 * VPAD];
    __shared__ float ws[64];

    const int qt = blockIdx.x, bh = blockIdx.y;
    const int b = bh >> 4, h = bh & 15;
    const int tid = threadIdx.x, wid = tid >> 5, lane = tid & 31;
    const int g = lane >> 2, tig = lane & 3;
    const int lrow = lane & 15, lcolb = (lane >> 4) * 16;

    const int trow = ((lane >> 3) & 1) * 8 + (lane & 7);
    const int tcol = (lane >> 4) * 8;

    const size_t qbase = ((size_t)b * T_ + qt * 128) * D_ + h * HD_;
#pragma unroll
    for (int it = 0; it < 4; ++it) {
        const int idx = it * 256 + tid;
        const int r = idx >> 3, c8 = (idx & 7) * 8;
        const uint4 t = *reinterpret_cast<const uint4*>(qb + qbase + (size_t)r * D_ + c8);
        *reinterpret_cast<uint4*>(&sQ[r * VPAD + c8]) = t;
    }

    float o[8][4];
#pragma unroll
    for (int nf = 0; nf < 8; nf++)
#pragma unroll
        for (int r = 0; r < 4; r++) o[nf][r] = 0.f;
    float m0 = -1e30f, m1 = -1e30f, l0 = 0.f, l1 = 0.f;

    const uint32_t sQb = smem_u32(sQ), sKb = smem_u32(sK);
    const uint32_t sVhb = smem_u32(sVh), sVlb = smem_u32(sVl);

    const float* wrow = wgt + (size_t)bh * S_;

    for (int sc = 0; sc < S_ / 64; ++sc) {
        __syncthreads();
        const size_t krow0 = (size_t)b * S_ + sc * 64;
#pragma unroll
        for (int it = 0; it < 2; ++it) {
            const int idx = it * 256 + tid;
            const int r = idx >> 3, c8 = (idx & 7) * 8;
            const uint4 tk4 = *reinterpret_cast<const uint4*>(
                kb + (krow0 + r) * D_ + h * HD_ + c8);
            *reinterpret_cast<uint4*>(&sK[r * VPAD + c8]) = tk4;
            const uint4 th4 = *reinterpret_cast<const uint4*>(
                v2 + (krow0 + r) * K2_ + h * HD_ + c8);
            *reinterpret_cast<uint4*>(&sVh[r * VPAD + c8]) = th4;
            const uint4 tl4 = *reinterpret_cast<const uint4*>(
                v2 + (krow0 + r) * K2_ + 1024 + h * HD_ + c8);
            *reinterpret_cast<uint4*>(&sVl[r * VPAD + c8]) = tl4;
        }
        if (tid < 64) ws[tid] = wrow[sc * 64 + tid];
        __syncthreads();

        float sv[8][4];
#pragma unroll
        for (int nf = 0; nf < 8; nf++)
#pragma unroll
            for (int r = 0; r < 4; r++) sv[nf][r] = 0.f;

#pragma unroll
        for (int kk = 0; kk < 4; kk++) {
            const int kb_ = kk * 32 + lcolb;
            uint32_t a0, a1, a2, a3;
            ldmatrix_x4(a0, a1, a2, a3,
                        sQb + (wid * 16 + lrow) * (VPAD * 2) + kb_);
#pragma unroll
            for (int nb = 0; nb < 4; nb++) {
                uint32_t b0, b1, b2, b3;
                ldmatrix_x4(b0, b1, b2, b3,
                            sKb + (nb * 16 + lrow) * (VPAD * 2) + kb_);
                mma_bf16(sv[2 * nb],     a0, a1, a2, a3, b0, b2);
                mma_bf16(sv[2 * nb + 1], a0, a1, a2, a3, b1, b3);
            }
        }

#pragma unroll
        for (int nf = 0; nf < 8; nf++) {
            const int col = nf * 8 + tig * 2;
            const float w0 = ws[col], w1 = ws[col + 1];
            sv[nf][0] *= w0; sv[nf][1] *= w1;
            sv[nf][2] *= w0; sv[nf][3] *= w1;
        }

        float mx0 = -1e30f, mx1 = -1e30f;
#pragma unroll
        for (int nf = 0; nf < 8; nf++) {
            mx0 = fmaxf(mx0, fmaxf(sv[nf][0], sv[nf][1]));
            mx1 = fmaxf(mx1, fmaxf(sv[nf][2], sv[nf][3]));
        }
        mx0 = fmaxf(mx0, __shfl_xor_sync(0xffffffffu, mx0, 1));
        mx0 = fmaxf(mx0, __shfl_xor_sync(0xffffffffu, mx0, 2));
        mx1 = fmaxf(mx1, __shfl_xor_sync(0xffffffffu, mx1, 1));
        mx1 = fmaxf(mx1, __shfl_xor_sync(0xffffffffu, mx1, 2));

        const float mn0 = fmaxf(m0, mx0), mn1 = fmaxf(m1, mx1);
        const float al0 = fast_exp(m0 - mn0), al1 = fast_exp(m1 - mn1);
        m0 = mn0; m1 = mn1;

        float s0 = 0.f, s1 = 0.f;
#pragma unroll
        for (int nf = 0; nf < 8; nf++) {
            sv[nf][0] = fast_exp(sv[nf][0] - mn0);
            sv[nf][1] = fast_exp(sv[nf][1] - mn0);
            sv[nf][2] = fast_exp(sv[nf][2] - mn1);
            sv[nf][3] = fast_exp(sv[nf][3] - mn1);
            s0 += sv[nf][0] + sv[nf][1];
            s1 += sv[nf][2] + sv[nf][3];
        }
        s0 += __shfl_xor_sync(0xffffffffu, s0, 1);
        s0 += __shfl_xor_sync(0xffffffffu, s0, 2);
        s1 += __shfl_xor_sync(0xffffffffu, s1, 1);
        s1 += __shfl_xor_sync(0xffffffffu, s1, 2);
        l0 = l0 * al0 + s0;
        l1 = l1 * al1 + s1;

#pragma unroll
        for (int nf = 0; nf < 8; nf++) {
            o[nf][0] *= al0; o[nf][1] *= al0;
            o[nf][2] *= al1; o[nf][3] *= al1;
        }

#pragma unroll
        for (int j = 0; j < 4; j++) {
            uint32_t ph[4], pl[4];
            split_pair(sv[2 * j][0],     sv[2 * j][1],     ph[0], pl[0]);
            split_pair(sv[2 * j][2],     sv[2 * j][3],     ph[1], pl[1]);
            split_pair(sv[2 * j + 1][0], sv[2 * j + 1][1], ph[2], pl[2]);
            split_pair(sv[2 * j + 1][2], sv[2 * j + 1][3], ph[3], pl[3]);

            const uint32_t vrow = (j * 16 + trow) * (VPAD * 2);
#pragma unroll
            for (int nb = 0; nb < 4; nb++) {
                const uint32_t vaddr = vrow + (nb * 16 + tcol) * 2;
                uint32_t h0, h1, h2, h3, q0, q1, q2, q3;
                ldmatrix_x4_trans(h0, h1, h2, h3, sVhb + vaddr);
                ldmatrix_x4_trans(q0, q1, q2, q3, sVlb + vaddr);
                mma_bf16(o[2 * nb],     ph[0], ph[1], ph[2], ph[3], h0, h1);
                mma_bf16(o[2 * nb + 1], ph[0], ph[1], ph[2], ph[3], h2, h3);
                mma_bf16(o[2 * nb],     ph[0], ph[1], ph[2], ph[3], q0, q1);
                mma_bf16(o[2 * nb + 1], ph[0], ph[1], ph[2], ph[3], q2, q3);
                mma_bf16(o[2 * nb],     pl[0], pl[1], pl[2], pl[3], h0, h1);
                mma_bf16(o[2 * nb + 1], pl[0], pl[1], pl[2], pl[3], h2, h3);
            }
        }
    }

    const float inv0 = 1.0f / l0, inv1 = 1.0f / l1;
    const int row0 = qt * 128 + wid * 16 + g;
#pragma unroll
    for (int nf = 0; nf < 8; nf++) {
        const int col = h * HD_ + nf * 8 + tig * 2;
        uint32_t h0, l0w, h1, l1w;
        split_pair(o[nf][0] * inv0, o[nf][1] * inv0, h0, l0w);
        split_pair(o[nf][2] * inv1, o[nf][3] * inv1, h1, l1w);
        const size_t r0 = ((size_t)b * T_ + row0) * K2_;
        const size_t r1 = ((size_t)b * T_ + row0 + 8) * K2_;
        *reinterpret_cast<uint32_t*>(ctxA + r0 + col)        = h0;
        *reinterpret_cast<uint32_t*>(ctxA + r0 + 1024 + col) = l0w;
        *reinterpret_cast<uint32_t*>(ctxA + r1 + col)        = h1;
        *reinterpret_cast<uint32_t*>(ctxA + r1 + 1024 + col) = l1w;
    }
}

// ---------------------------------------------------------------------------
// launch
// ---------------------------------------------------------------------------
extern "C" void kernel_launch(void* const* d_in, const int* in_sizes, int n_in,
                              void* d_out, int out_size)
{
    const float* hidden = (const float*)d_in[0];
    const float* kv     = (const float*)d_in[1];
    const float* target = (const float*)d_in[2];
    const float* mask   = (const float*)d_in[3];
    const float* Wq  = (const float*)d_in[4];
    const float* bq  = (const float*)d_in[5];
    const float* Wk  = (const float*)d_in[6];
    const float* bk  = (const float*)d_in[7];
    const float* Wv  = (const float*)d_in[8];
    const float* bv  = (const float*)d_in[9];
    const float* Wwq = (const float*)d_in[10];
    const float* bwq = (const float*)d_in[11];
    const float* Wwk = (const float*)d_in[12];
    const float* bwk = (const float*)d_in[13];
    const float* Wo  = (const float*)d_in[14];
    const float* bo  = (const float*)d_in[15];
    float* out = (float*)d_out;

    float *tq, *tk, *w;
    cudaGetSymbolAddress((void**)&tq,  g_tq);
    cudaGetSymbolAddress((void**)&tk,  g_tk);
    cudaGetSymbolAddress((void**)&w,   g_w);

    __nv_bfloat16 *qb, *kb, *v2, *hb, *tb, *Wqb, *Wkb, *Wwqb, *Wwkb;
    cudaGetSymbolAddress((void**)&qb,   g_qb);
    cudaGetSymbolAddress((void**)&kb,   g_kb);
    cudaGetSymbolAddress((void**)&v2,   g_v2);
    cudaGetSymbolAddress((void**)&hb,   g_hb);
    cudaGetSymbolAddress((void**)&tb,   g_tb);
    cudaGetSymbolAddress((void**)&Wqb,  g_Wqb);
    cudaGetSymbolAddress((void**)&Wkb,  g_Wkb);
    cudaGetSymbolAddress((void**)&Wwqb, g_Wwqb);
    cudaGetSymbolAddress((void**)&Wwkb, g_Wwkb);

    __nv_bfloat16 *kvA, *ctxA, *Wv2, *Wo2;
    cudaGetSymbolAddress((void**)&kvA,  g_kvA);
    cudaGetSymbolAddress((void**)&ctxA, g_ctxA);
    cudaGetSymbolAddress((void**)&Wv2,  g_Wv2);
    cudaGetSymbolAddress((void**)&Wo2,  g_Wo2);

    cudaFuncSetAttribute(gemm_pre_kernel,
                         cudaFuncAttributeMaxDynamicSharedMemorySize, GEMM_SMEM_BYTES);
    cudaFuncSetAttribute(gemm_out_kernel,
                         cudaFuncAttributeMaxDynamicSharedMemorySize, GEMM_SMEM_BYTES);

    // 1) all conversions (one launch, 18944 blocks)
    convert_kernel<<<18944, 256>>>(hidden, hb, kv, kvA, target, tb,
                                   Wq, Wqb, Wk, Wkb, Wwq, Wwqb, Wwk, Wwkb,
                                   Wv, Wv2, Wo, Wo2);

    // 2) all pre-attention projections (one launch, heavy-first)
    gemm_pre_kernel<<<1824, 256, GEMM_SMEM_BYTES>>>(
        kvA, Wv2, bv, v2,
        hb, Wqb, bq, qb,
        Wkb, bk, kb,
        Wwqb, bwq, tq,
        tb, Wwkb, bwk, tk);

    // 3) masked-mean weights
    weights_kernel<<<B_ * H_, 256>>>(tq, tk, mask, w);

    // 4) tensor-core flash attention -> ctxA (hi|lo)
    attn_tc_kernel<<<dim3(T_ / 128, B_ * H_), 256>>>(qb, kb, v2, w, ctxA);

    // 5) output projection
    gemm_out_kernel<<<dim3(8, (B_ * T_) / 128), 256, GEMM_SMEM_BYTES>>>(
        ctxA, Wo2, bo, out);
}

// round 13
// speedup vs baseline: 2.8496x; 1.0523x over previous
#include <cuda_runtime.h>
#include <cuda_bf16.h>
#include <cstdint>

// ============================================================================
// KTMutualAttention — consolidated-launch pipeline:
//   1 convert launch (dense bf16 for 1-term operands, hi|lo for 3-term)
//   1 pre-attention GEMM mega-launch (v heavy-first + q/k/tq/tk light)
//   weights, flash attention (2 CTA/SM), out-projection.
//   B=8, T=512, S=1024, TL=64, D=1024, H=16, hd=64
// ============================================================================

#define B_   8
#define T_   512
#define S_   1024
#define TL_  64
#define D_   1024
#define H_   16
#define HD_  64
#define SCALING_ 0.125f
#define K2_  2048

#define MODE_F32   0
#define MODE_BF16  1
#define MODE_SPLIT 2

// ---------------------------------------------------------------------------
// scratch (device globals)
// ---------------------------------------------------------------------------
__device__ __align__(256) float g_tq [B_ * S_ * D_];
__device__ __align__(256) float g_tk [B_ * TL_ * D_];
__device__ __align__(256) float g_w  [B_ * H_ * S_];

__device__ __align__(256) __nv_bfloat16 g_qb  [(size_t)B_ * T_ * D_];
__device__ __align__(256) __nv_bfloat16 g_kb  [(size_t)B_ * S_ * D_];
__device__ __align__(256) __nv_bfloat16 g_v2  [(size_t)B_ * S_ * K2_];

// dense bf16 (1-term operands)
__device__ __align__(256) __nv_bfloat16 g_hb  [(size_t)B_ * T_  * D_];
__device__ __align__(256) __nv_bfloat16 g_tb  [(size_t)B_ * TL_ * D_];
__device__ __align__(256) __nv_bfloat16 g_Wqb [(size_t)D_ * D_];
__device__ __align__(256) __nv_bfloat16 g_Wkb [(size_t)D_ * D_];
__device__ __align__(256) __nv_bfloat16 g_Wwqb[(size_t)D_ * D_];
__device__ __align__(256) __nv_bfloat16 g_Wwkb[(size_t)D_ * D_];

// hi|lo split (3-term operands)
__device__ __align__(256) __nv_bfloat16 g_kvA [(size_t)B_ * S_ * K2_];
__device__ __align__(256) __nv_bfloat16 g_ctxA[(size_t)B_ * T_ * K2_];
__device__ __align__(256) __nv_bfloat16 g_Wv2 [(size_t)D_ * K2_];
__device__ __align__(256) __nv_bfloat16 g_Wo2 [(size_t)D_ * K2_];

// ---------------------------------------------------------------------------
// PTX helpers (portable sm_80+)
// ---------------------------------------------------------------------------
__device__ __forceinline__ uint32_t smem_u32(const void* p) {
    uint32_t a;
    asm("{ .reg .u64 t; cvta.to.shared.u64 t, %1; cvt.u32.u64 %0, t; }"
        : "=r"(a) : "l"(p));
    return a;
}

#define CP_ASYNC16(dst_u32, src_ptr) \
    asm volatile("cp.async.cg.shared.global [%0], [%1], 16;" \
                 :: "r"(dst_u32), "l"(src_ptr) : "memory")
#define CP_COMMIT() asm volatile("cp.async.commit_group;" ::: "memory")
#define CP_WAIT2()  asm volatile("cp.async.wait_group 2;" ::: "memory")

__device__ __forceinline__ void ldmatrix_x4(uint32_t& r0, uint32_t& r1,
                                            uint32_t& r2, uint32_t& r3,
                                            uint32_t addr)
{
    asm volatile("ldmatrix.sync.aligned.m8n8.x4.shared.b16 {%0,%1,%2,%3}, [%4];"
                 : "=r"(r0), "=r"(r1), "=r"(r2), "=r"(r3) : "r"(addr));
}

__device__ __forceinline__ void ldmatrix_x4_trans(uint32_t& r0, uint32_t& r1,
                                                  uint32_t& r2, uint32_t& r3,
                                                  uint32_t addr)
{
    asm volatile("ldmatrix.sync.aligned.m8n8.x4.trans.shared.b16 {%0,%1,%2,%3}, [%4];"
                 : "=r"(r0), "=r"(r1), "=r"(r2), "=r"(r3) : "r"(addr));
}

__device__ __forceinline__ void mma_bf16(float* c, uint32_t a0, uint32_t a1,
                                         uint32_t a2, uint32_t a3,
                                         uint32_t b0, uint32_t b1)
{
    asm volatile(
        "mma.sync.aligned.m16n8k16.row.col.f32.bf16.bf16.f32 "
        "{%0,%1,%2,%3}, {%4,%5,%6,%7}, {%8,%9}, {%0,%1,%2,%3};"
        : "+f"(c[0]), "+f"(c[1]), "+f"(c[2]), "+f"(c[3])
        : "r"(a0), "r"(a1), "r"(a2), "r"(a3), "r"(b0), "r"(b1));
}

__device__ __forceinline__ uint32_t pack_bf162(float x, float y)
{
    __nv_bfloat162 t = __floats2bfloat162_rn(x, y);
    return *reinterpret_cast<uint32_t*>(&t);
}

__device__ __forceinline__ void split_pair(float x, float y,
                                           uint32_t& hi, uint32_t& lo)
{
    __nv_bfloat16 hx = __float2bfloat16_rn(x);
    __nv_bfloat16 hy = __float2bfloat16_rn(y);
    __nv_bfloat162 th(hx, hy);
    hi = *reinterpret_cast<uint32_t*>(&th);
    __nv_bfloat162 tl(__float2bfloat16_rn(x - __bfloat162float(hx)),
                      __float2bfloat16_rn(y - __bfloat162float(hy)));
    lo = *reinterpret_cast<uint32_t*>(&tl);
}

// ---------------------------------------------------------------------------
// merged convert kernel: one block = one 1024-float row.
// ---------------------------------------------------------------------------
__global__ __launch_bounds__(256)
void convert_kernel(const float* __restrict__ hidden, __nv_bfloat16* __restrict__ hb,
                    const float* __restrict__ kv,     __nv_bfloat16* __restrict__ kvA,
                    const float* __restrict__ target, __nv_bfloat16* __restrict__ tb,
                    const float* __restrict__ Wq,  __nv_bfloat16* __restrict__ Wqb,
                    const float* __restrict__ Wk,  __nv_bfloat16* __restrict__ Wkb,
                    const float* __restrict__ Wwq, __nv_bfloat16* __restrict__ Wwqb,
                    const float* __restrict__ Wwk, __nv_bfloat16* __restrict__ Wwkb,
                    const float* __restrict__ Wv,  __nv_bfloat16* __restrict__ Wv2,
                    const float* __restrict__ Wo,  __nv_bfloat16* __restrict__ Wo2)
{
    const int x = blockIdx.x;
    const float* src;
    __nv_bfloat16* dst;
    int split, row;
    if (x < 4096)       { src = hidden; dst = hb;   split = 0; row = x; }
    else if (x < 12288) { src = kv;     dst = kvA;  split = 1; row = x - 4096; }
    else if (x < 12800) { src = target; dst = tb;   split = 0; row = x - 12288; }
    else if (x < 13824) { src = Wq;     dst = Wqb;  split = 0; row = x - 12800; }
    else if (x < 14848) { src = Wk;     dst = Wkb;  split = 0; row = x - 13824; }
    else if (x < 15872) { src = Wwq;    dst = Wwqb; split = 0; row = x - 14848; }
    else if (x < 16896) { src = Wwk;    dst = Wwkb; split = 0; row = x - 15872; }
    else if (x < 17920) { src = Wv;     dst = Wv2;  split = 1; row = x - 16896; }
    else                { src = Wo;     dst = Wo2;  split = 1; row = x - 17920; }

    const int c4 = threadIdx.x * 4;
    const float4 v = *reinterpret_cast<const float4*>(src + ((size_t)row << 10) + c4);

    uint32_t h0, l0, h1, l1;
    split_pair(v.x, v.y, h0, l0);
    split_pair(v.z, v.w, h1, l1);
    if (!split) {
        uint32_t* d = reinterpret_cast<uint32_t*>(dst + (size_t)row * D_ + c4);
        d[0] = h0; d[1] = h1;
    } else {
        uint32_t* dh = reinterpret_cast<uint32_t*>(dst + (size_t)row * K2_ + c4);
        dh[0] = h0; dh[1] = h1;
        uint32_t* dl = reinterpret_cast<uint32_t*>(dst + (size_t)row * K2_ + 1024 + c4);
        dl[0] = l0; dl[1] = l1;
    }
}

// ---------------------------------------------------------------------------
// GEMM core with per-operand strides.
// ---------------------------------------------------------------------------
#define BK 32
#define SROW 40
#define STAGES 4
#define STAGE_ELEMS (128 * SROW)
#define GEMM_SMEM_BYTES (STAGES * STAGE_ELEMS * 2 * 2)

__device__ __forceinline__
void gemm_core(const __nv_bfloat16* __restrict__ A, int astride,
               const __nv_bfloat16* __restrict__ W, int wstride,
               const float* __restrict__ bias,
               void* __restrict__ out, float scale, int mode, int nchunk,
               int bm, int bn, __nv_bfloat16* smem)
{
    __nv_bfloat16* sA = smem;
    __nv_bfloat16* sB = smem + STAGES * STAGE_ELEMS;
    __shared__ float biasS[128];

    const int tid = threadIdx.x;
    const int wid = tid >> 5, lane = tid & 31;
    const int wm = wid & 3;
    const int wn = wid >> 2;

    if (tid < 128) biasS[tid] = bias[bn + tid];

    const __nv_bfloat16* Ag = A + (size_t)bm * astride;
    const __nv_bfloat16* Wg = W + (size_t)bn * wstride;

    const int ldrow = tid >> 1;
    const int ldoff = (tid & 1) * 16;

    const uint32_t sAu = smem_u32(sA);
    const uint32_t sBu = smem_u32(sB);

    auto stage = [&](int c) {
        const int slot = c & (STAGES - 1);
        const int seg = c >> 5;
        const int col = (c & 31) * BK;
        const int aoff = (seg == 2) ? 1024 : 0;
        const int woff = (seg == 1) ? 1024 : 0;
        const size_t ga = (size_t)ldrow * astride + aoff + col + ldoff;
        const size_t gw = (size_t)ldrow * wstride + woff + col + ldoff;
        const uint32_t sa = sAu + (slot * STAGE_ELEMS + ldrow * SROW + ldoff) * 2;
        const uint32_t sb = sBu + (slot * STAGE_ELEMS + ldrow * SROW + ldoff) * 2;
        CP_ASYNC16(sa,      Ag + ga);
        CP_ASYNC16(sa + 16, Ag + ga + 8);
        CP_ASYNC16(sb,      Wg + gw);
        CP_ASYNC16(sb + 16, Wg + gw + 8);
    };

    float acc[2][8][4];
#pragma unroll
    for (int mt = 0; mt < 2; mt++)
#pragma unroll
        for (int nf = 0; nf < 8; nf++)
#pragma unroll
            for (int r = 0; r < 4; r++) acc[mt][nf][r] = 0.f;

    stage(0); CP_COMMIT();
    stage(1); CP_COMMIT();
    stage(2); CP_COMMIT();

    const int lrow = lane & 15;
    const int lcol = (lane >> 4) * 16;

    for (int c = 0; c < nchunk; ++c) {
        CP_WAIT2();
        __syncthreads();

        if (c + 3 < nchunk) { stage(c + 3); CP_COMMIT(); }
        else { CP_COMMIT(); }

        const int slot = c & (STAGES - 1);
        const uint32_t aBase = sAu + slot * STAGE_ELEMS * 2;
        const uint32_t bBase = sBu + slot * STAGE_ELEMS * 2;

#pragma unroll
        for (int kk = 0; kk < 2; kk++) {
            const int kbyte = kk * 32 + lcol;

            uint32_t a[2][4];
#pragma unroll
            for (int mt = 0; mt < 2; mt++) {
                const int row = wm * 32 + mt * 16 + lrow;
                ldmatrix_x4(a[mt][0], a[mt][1], a[mt][2], a[mt][3],
                            aBase + row * (SROW * 2) + kbyte);
            }
            uint32_t b[4][4];
#pragma unroll
            for (int nb = 0; nb < 4; nb++) {
                const int row = wn * 64 + nb * 16 + lrow;
                ldmatrix_x4(b[nb][0], b[nb][1], b[nb][2], b[nb][3],
                            bBase + row * (SROW * 2) + kbyte);
            }
#pragma unroll
            for (int mt = 0; mt < 2; mt++)
#pragma unroll
                for (int nf = 0; nf < 8; nf++) {
                    const int nb = nf >> 1;
                    const uint32_t b0 = (nf & 1) ? b[nb][1] : b[nb][0];
                    const uint32_t b1 = (nf & 1) ? b[nb][3] : b[nb][2];
                    mma_bf16(acc[mt][nf], a[mt][0], a[mt][1], a[mt][2], a[mt][3],
                             b0, b1);
                }
        }
    }

    const int g_  = lane >> 2;
    const int tig = lane & 3;
#pragma unroll
    for (int mt = 0; mt < 2; mt++) {
        const int row0 = bm + wm * 32 + mt * 16 + g_;
#pragma unroll
        for (int nf = 0; nf < 8; nf++) {
            const int lc  = wn * 64 + nf * 8 + tig * 2;
            const int col = bn + lc;
            const float b0 = biasS[lc], b1 = biasS[lc + 1];
            const float x0 = scale * (acc[mt][nf][0] + b0);
            const float x1 = scale * (acc[mt][nf][1] + b1);
            const float x2 = scale * (acc[mt][nf][2] + b0);
            const float x3 = scale * (acc[mt][nf][3] + b1);
            if (mode == MODE_F32) {
                float* C = (float*)out;
                *reinterpret_cast<float2*>(C + (size_t)row0 * 1024 + col)
                    = make_float2(x0, x1);
                *reinterpret_cast<float2*>(C + (size_t)(row0 + 8) * 1024 + col)
                    = make_float2(x2, x3);
            } else if (mode == MODE_BF16) {
                __nv_bfloat16* C = (__nv_bfloat16*)out;
                *reinterpret_cast<uint32_t*>(C + (size_t)row0 * 1024 + col)
                    = pack_bf162(x0, x1);
                *reinterpret_cast<uint32_t*>(C + (size_t)(row0 + 8) * 1024 + col)
                    = pack_bf162(x2, x3);
            } else {
                __nv_bfloat16* C = (__nv_bfloat16*)out;
                uint32_t h0, l0, h1, l1;
                split_pair(x0, x1, h0, l0);
                split_pair(x2, x3, h1, l1);
                *reinterpret_cast<uint32_t*>(C + (size_t)row0 * K2_ + col) = h0;
                *reinterpret_cast<uint32_t*>(C + (size_t)row0 * K2_ + 1024 + col) = l0;
                *reinterpret_cast<uint32_t*>(C + (size_t)(row0 + 8) * K2_ + col) = h1;
                *reinterpret_cast<uint32_t*>(C + (size_t)(row0 + 8) * K2_ + 1024 + col) = l1;
            }
        }
    }
}

// pre-attention GEMM mega-launch: v (512 heavy) first, then q/k/tq/tk light.
__global__ __launch_bounds__(256, 2)
void gemm_pre_kernel(const __nv_bfloat16* __restrict__ kvA,
                     const __nv_bfloat16* __restrict__ Wv2,
                     const float* __restrict__ bv,
                     __nv_bfloat16* __restrict__ v2,
                     const __nv_bfloat16* __restrict__ hb,
                     const __nv_bfloat16* __restrict__ Wqb,
                     const float* __restrict__ bq,
                     __nv_bfloat16* __restrict__ qb,
                     const __nv_bfloat16* __restrict__ Wkb,
                     const float* __restrict__ bk,
                     __nv_bfloat16* __restrict__ kb,
                     const __nv_bfloat16* __restrict__ Wwqb,
                     const float* __restrict__ bwq,
                     float* __restrict__ tq,
                     const __nv_bfloat16* __restrict__ tb,
                     const __nv_bfloat16* __restrict__ Wwkb,
                     const float* __restrict__ bwk,
                     float* __restrict__ tk)
{
    extern __shared__ __nv_bfloat16 smem[];
    const int x = blockIdx.x;
    if (x < 512) {
        gemm_core(kvA, K2_, Wv2, K2_, bv, v2, 1.0f, MODE_SPLIT, 96,
                  (x >> 3) * 128, (x & 7) * 128, smem);
    } else if (x < 768) {
        const int t = x - 512;
        gemm_core(hb, D_, Wqb, D_, bq, qb, SCALING_, MODE_BF16, 32,
                  (t >> 3) * 128, (t & 7) * 128, smem);
    } else if (x < 1280) {
        const int t = x - 768;
        gemm_core(kvA, K2_, Wkb, D_, bk, kb, 1.0f, MODE_BF16, 32,
                  (t >> 3) * 128, (t & 7) * 128, smem);
    } else if (x < 1792) {
        const int t = x - 1280;
        gemm_core(kvA, K2_, Wwqb, D_, bwq, tq, SCALING_, MODE_F32, 32,
                  (t >> 3) * 128, (t & 7) * 128, smem);
    } else {
        const int t = x - 1792;
        gemm_core(tb, D_, Wwkb, D_, bwk, tk, 1.0f, MODE_F32, 32,
                  (t >> 3) * 128, (t & 7) * 128, smem);
    }
}

// out projection: 3-term
__global__ __launch_bounds__(256, 2)
void gemm_out_kernel(const __nv_bfloat16* __restrict__ A,
                     const __nv_bfloat16* __restrict__ W,
                     const float* __restrict__ bias,
                     float* __restrict__ C)
{
    extern __shared__ __nv_bfloat16 smem[];
    gemm_core(A, K2_, W, K2_, bias, C, 1.0f, MODE_F32, 96,
              blockIdx.y * 128, blockIdx.x * 128, smem);
}

// ---------------------------------------------------------------------------
// weights[b,h,s] = (tq . (mask @ tk)) / sum(mask)
// ---------------------------------------------------------------------------
__global__ __launch_bounds__(256)
void weights_kernel(const float* __restrict__ tq, const float* __restrict__ tk,
                    const float* __restrict__ mask, float* __restrict__ wgt)
{
    const int bh = blockIdx.x;
    const int b = bh >> 4;
    const int h = bh & 15;

    __shared__ float tks[TL_][HD_];

    const int tid = threadIdx.x;
    for (int idx = tid; idx < TL_ * HD_; idx += 256) {
        const int t = idx >> 6, d = idx & 63;
        tks[t][d] = tk[((size_t)b * TL_ + t) * D_ + h * HD_ + d];
    }
    __syncthreads();

    const int warp = tid >> 5, lane = tid & 31;

    for (int s = warp; s < S_; s += 8) {
        const size_t tqo = ((size_t)b * S_ + s) * D_ + h * HD_;
        const float tq0 = __ldg(&tq[tqo + lane]);
        const float tq1 = __ldg(&tq[tqo + lane + 32]);
        const float* mrow = mask + ((size_t)b * S_ + s) * TL_;

        float mk0 = 0.f, mk1 = 0.f, cnt = 0.f;
#pragma unroll
        for (int t = 0; t < TL_; t++) {
            const float m = __ldg(&mrow[t]);
            cnt += m;
            mk0 = fmaf(m, tks[t][lane], mk0);
            mk1 = fmaf(m, tks[t][lane + 32], mk1);
        }
        float dotv = tq0 * mk0 + tq1 * mk1;
#pragma unroll
        for (int off = 16; off; off >>= 1)
            dotv += __shfl_xor_sync(0xffffffffu, dotv, off);

        if (lane == 0)
            wgt[(size_t)bh * S_ + s] = dotv / cnt;
    }
}

// ---------------------------------------------------------------------------
// fast exp on FMA pipe
// ---------------------------------------------------------------------------
__device__ __forceinline__ float fast_exp(float x)
{
    const float y = x * 1.44269504088896341f;
    const float n = rintf(y);
    const float t = (y - n) * 0.69314718055994531f;
    float p = 1.9841269841e-4f;
    p = fmaf(p, t, 1.38888888889e-3f);
    p = fmaf(p, t, 8.33333333333e-3f);
    p = fmaf(p, t, 4.16666666667e-2f);
    p = fmaf(p, t, 1.66666666667e-1f);
    p = fmaf(p, t, 0.5f);
    p = fmaf(p, t, 1.0f);
    p = fmaf(p, t, 1.0f);
    int e = (int)n;
    e = e < -126 ? -126 : e;
    const float s = __int_as_float((e + 127) << 23);
    return p * s;
}

// ---------------------------------------------------------------------------
// Tensor-core flash attention; bf16 operands; ctxA hi|lo out.
//   __launch_bounds__(256, 2): cap regs at 128 so 2 CTAs co-reside per SM
//   (R12 ncu: 135 regs -> 1 CTA/SM, occ 12.5%, tensor pipe 28% — latency-bound)
// ---------------------------------------------------------------------------
#define VPAD 72

__global__ __launch_bounds__(256, 2)
void attn_tc_kernel(const __nv_bfloat16* __restrict__ qb,
                    const __nv_bfloat16* __restrict__ kb,
                    const __nv_bfloat16* __restrict__ v2,
                    const float* __restrict__ wgt,
                    __nv_bfloat16* __restrict__ ctxA)
{
    __shared__ __nv_bfloat16 sQ [128 * VPAD];
    __shared__ __nv_bfloat16 sK [64 * VPAD];
    __shared__ __nv_bfloat16 sVh[64 * VPAD];
    __shared__ __nv_bfloat16 sVl[64 * VPAD];
    __shared__ float ws[64];

    const int qt = blockIdx.x, bh = blockIdx.y;
    const int b = bh >> 4, h = bh & 15;
    const int tid = threadIdx.x, wid = tid >> 5, lane = tid & 31;
    const int g = lane >> 2, tig = lane & 3;
    const int lrow = lane & 15, lcolb = (lane >> 4) * 16;

    const int trow = ((lane >> 3) & 1) * 8 + (lane & 7);
    const int tcol = (lane >> 4) * 8;

    const size_t qbase = ((size_t)b * T_ + qt * 128) * D_ + h * HD_;
#pragma unroll
    for (int it = 0; it < 4; ++it) {
        const int idx = it * 256 + tid;
        const int r = idx >> 3, c8 = (idx & 7) * 8;
        const uint4 t = *reinterpret_cast<const uint4*>(qb + qbase + (size_t)r * D_ + c8);
        *reinterpret_cast<uint4*>(&sQ[r * VPAD + c8]) = t;
    }

    float o[8][4];
#pragma unroll
    for (int nf = 0; nf < 8; nf++)
#pragma unroll
        for (int r = 0; r < 4; r++) o[nf][r] = 0.f;
    float m0 = -1e30f, m1 = -1e30f, l0 = 0.f, l1 = 0.f;

    const uint32_t sQb = smem_u32(sQ), sKb = smem_u32(sK);
    const uint32_t sVhb = smem_u32(sVh), sVlb = smem_u32(sVl);

    const float* wrow = wgt + (size_t)bh * S_;

    for (int sc = 0; sc < S_ / 64; ++sc) {
        __syncthreads();
        const size_t krow0 = (size_t)b * S_ + sc * 64;
#pragma unroll
        for (int it = 0; it < 2; ++it) {
            const int idx = it * 256 + tid;
            const int r = idx >> 3, c8 = (idx & 7) * 8;
            const uint4 tk4 = *reinterpret_cast<const uint4*>(
                kb + (krow0 + r) * D_ + h * HD_ + c8);
            *reinterpret_cast<uint4*>(&sK[r * VPAD + c8]) = tk4;
            const uint4 th4 = *reinterpret_cast<const uint4*>(
                v2 + (krow0 + r) * K2_ + h * HD_ + c8);
            *reinterpret_cast<uint4*>(&sVh[r * VPAD + c8]) = th4;
            const uint4 tl4 = *reinterpret_cast<const uint4*>(
                v2 + (krow0 + r) * K2_ + 1024 + h * HD_ + c8);
            *reinterpret_cast<uint4*>(&sVl[r * VPAD + c8]) = tl4;
        }
        if (tid < 64) ws[tid] = wrow[sc * 64 + tid];
        __syncthreads();

        float sv[8][4];
#pragma unroll
        for (int nf = 0; nf < 8; nf++)
#pragma unroll
            for (int r = 0; r < 4; r++) sv[nf][r] = 0.f;

#pragma unroll
        for (int kk = 0; kk < 4; kk++) {
            const int kb_ = kk * 32 + lcolb;
            uint32_t a0, a1, a2, a3;
            ldmatrix_x4(a0, a1, a2, a3,
                        sQb + (wid * 16 + lrow) * (VPAD * 2) + kb_);
#pragma unroll
            for (int nb = 0; nb < 4; nb++) {
                uint32_t b0, b1, b2, b3;
                ldmatrix_x4(b0, b1, b2, b3,
                            sKb + (nb * 16 + lrow) * (VPAD * 2) + kb_);
                mma_bf16(sv[2 * nb],     a0, a1, a2, a3, b0, b2);
                mma_bf16(sv[2 * nb + 1], a0, a1, a2, a3, b1, b3);
            }
        }

#pragma unroll
        for (int nf = 0; nf < 8; nf++) {
            const int col = nf * 8 + tig * 2;
            const float w0 = ws[col], w1 = ws[col + 1];
            sv[nf][0] *= w0; sv[nf][1] *= w1;
            sv[nf][2] *= w0; sv[nf][3] *= w1;
        }

        float mx0 = -1e30f, mx1 = -1e30f;
#pragma unroll
        for (int nf = 0; nf < 8; nf++) {
            mx0 = fmaxf(mx0, fmaxf(sv[nf][0], sv[nf][1]));
            mx1 = fmaxf(mx1, fmaxf(sv[nf][2], sv[nf][3]));
        }
        mx0 = fmaxf(mx0, __shfl_xor_sync(0xffffffffu, mx0, 1));
        mx0 = fmaxf(mx0, __shfl_xor_sync(0xffffffffu, mx0, 2));
        mx1 = fmaxf(mx1, __shfl_xor_sync(0xffffffffu, mx1, 1));
        mx1 = fmaxf(mx1, __shfl_xor_sync(0xffffffffu, mx1, 2));

        const float mn0 = fmaxf(m0, mx0), mn1 = fmaxf(m1, mx1);
        const float al0 = fast_exp(m0 - mn0), al1 = fast_exp(m1 - mn1);
        m0 = mn0; m1 = mn1;

        float s0 = 0.f, s1 = 0.f;
#pragma unroll
        for (int nf = 0; nf < 8; nf++) {
            sv[nf][0] = fast_exp(sv[nf][0] - mn0);
            sv[nf][1] = fast_exp(sv[nf][1] - mn0);
            sv[nf][2] = fast_exp(sv[nf][2] - mn1);
            sv[nf][3] = fast_exp(sv[nf][3] - mn1);
            s0 += sv[nf][0] + sv[nf][1];
            s1 += sv[nf][2] + sv[nf][3];
        }
        s0 += __shfl_xor_sync(0xffffffffu, s0, 1);
        s0 += __shfl_xor_sync(0xffffffffu, s0, 2);
        s1 += __shfl_xor_sync(0xffffffffu, s1, 1);
        s1 += __shfl_xor_sync(0xffffffffu, s1, 2);
        l0 = l0 * al0 + s0;
        l1 = l1 * al1 + s1;

#pragma unroll
        for (int nf = 0; nf < 8; nf++) {
            o[nf][0] *= al0; o[nf][1] *= al0;
            o[nf][2] *= al1; o[nf][3] *= al1;
        }

#pragma unroll
        for (int j = 0; j < 4; j++) {
            uint32_t ph[4], pl[4];
            split_pair(sv[2 * j][0],     sv[2 * j][1],     ph[0], pl[0]);
            split_pair(sv[2 * j][2],     sv[2 * j][3],     ph[1], pl[1]);
            split_pair(sv[2 * j + 1][0], sv[2 * j + 1][1], ph[2], pl[2]);
            split_pair(sv[2 * j + 1][2], sv[2 * j + 1][3], ph[3], pl[3]);

            const uint32_t vrow = (j * 16 + trow) * (VPAD * 2);
#pragma unroll
            for (int nb = 0; nb < 4; nb++) {
                const uint32_t vaddr = vrow + (nb * 16 + tcol) * 2;
                uint32_t h0, h1, h2, h3, q0, q1, q2, q3;
                ldmatrix_x4_trans(h0, h1, h2, h3, sVhb + vaddr);
                ldmatrix_x4_trans(q0, q1, q2, q3, sVlb + vaddr);
                mma_bf16(o[2 * nb],     ph[0], ph[1], ph[2], ph[3], h0, h1);
                mma_bf16(o[2 * nb + 1], ph[0], ph[1], ph[2], ph[3], h2, h3);
                mma_bf16(o[2 * nb],     ph[0], ph[1], ph[2], ph[3], q0, q1);
                mma_bf16(o[2 * nb + 1], ph[0], ph[1], ph[2], ph[3], q2, q3);
                mma_bf16(o[2 * nb],     pl[0], pl[1], pl[2], pl[3], h0, h1);
                mma_bf16(o[2 * nb + 1], pl[0], pl[1], pl[2], pl[3], h2, h3);
            }
        }
    }

    const float inv0 = 1.0f / l0, inv1 = 1.0f / l1;
    const int row0 = qt * 128 + wid * 16 + g;
#pragma unroll
    for (int nf = 0; nf < 8; nf++) {
        const int col = h * HD_ + nf * 8 + tig * 2;
        uint32_t h0, l0w, h1, l1w;
        split_pair(o[nf][0] * inv0, o[nf][1] * inv0, h0, l0w);
        split_pair(o[nf][2] * inv1, o[nf][3] * inv1, h1, l1w);
        const size_t r0 = ((size_t)b * T_ + row0) * K2_;
        const size_t r1 = ((size_t)b * T_ + row0 + 8) * K2_;
        *reinterpret_cast<uint32_t*>(ctxA + r0 + col)        = h0;
        *reinterpret_cast<uint32_t*>(ctxA + r0 + 1024 + col) = l0w;
        *reinterpret_cast<uint32_t*>(ctxA + r1 + col)        = h1;
        *reinterpret_cast<uint32_t*>(ctxA + r1 + 1024 + col) = l1w;
    }
}

// ---------------------------------------------------------------------------
// launch
// ---------------------------------------------------------------------------
extern "C" void kernel_launch(void* const* d_in, const int* in_sizes, int n_in,
                              void* d_out, int out_size)
{
    const float* hidden = (const float*)d_in[0];
    const float* kv     = (const float*)d_in[1];
    const float* target = (const float*)d_in[2];
    const float* mask   = (const float*)d_in[3];
    const float* Wq  = (const float*)d_in[4];
    const float* bq  = (const float*)d_in[5];
    const float* Wk  = (const float*)d_in[6];
    const float* bk  = (const float*)d_in[7];
    const float* Wv  = (const float*)d_in[8];
    const float* bv  = (const float*)d_in[9];
    const float* Wwq = (const float*)d_in[10];
    const float* bwq = (const float*)d_in[11];
    const float* Wwk = (const float*)d_in[12];
    const float* bwk = (const float*)d_in[13];
    const float* Wo  = (const float*)d_in[14];
    const float* bo  = (const float*)d_in[15];
    float* out = (float*)d_out;

    float *tq, *tk, *w;
    cudaGetSymbolAddress((void**)&tq,  g_tq);
    cudaGetSymbolAddress((void**)&tk,  g_tk);
    cudaGetSymbolAddress((void**)&w,   g_w);

    __nv_bfloat16 *qb, *kb, *v2, *hb, *tb, *Wqb, *Wkb, *Wwqb, *Wwkb;
    cudaGetSymbolAddress((void**)&qb,   g_qb);
    cudaGetSymbolAddress((void**)&kb,   g_kb);
    cudaGetSymbolAddress((void**)&v2,   g_v2);
    cudaGetSymbolAddress((void**)&hb,   g_hb);
    cudaGetSymbolAddress((void**)&tb,   g_tb);
    cudaGetSymbolAddress((void**)&Wqb,  g_Wqb);
    cudaGetSymbolAddress((void**)&Wkb,  g_Wkb);
    cudaGetSymbolAddress((void**)&Wwqb, g_Wwqb);
    cudaGetSymbolAddress((void**)&Wwkb, g_Wwkb);

    __nv_bfloat16 *kvA, *ctxA, *Wv2, *Wo2;
    cudaGetSymbolAddress((void**)&kvA,  g_kvA);
    cudaGetSymbolAddress((void**)&ctxA, g_ctxA);
    cudaGetSymbolAddress((void**)&Wv2,  g_Wv2);
    cudaGetSymbolAddress((void**)&Wo2,  g_Wo2);

    cudaFuncSetAttribute(gemm_pre_kernel,
                         cudaFuncAttributeMaxDynamicSharedMemorySize, GEMM_SMEM_BYTES);
    cudaFuncSetAttribute(gemm_out_kernel,
                         cudaFuncAttributeMaxDynamicSharedMemorySize, GEMM_SMEM_BYTES);

    // 1) all conversions (one launch)
    convert_kernel<<<18944, 256>>>(hidden, hb, kv, kvA, target, tb,
                                   Wq, Wqb, Wk, Wkb, Wwq, Wwqb, Wwk, Wwkb,
                                   Wv, Wv2, Wo, Wo2);

    // 2) all pre-attention projections (one launch, heavy-first)
    gemm_pre_kernel<<<1824, 256, GEMM_SMEM_BYTES>>>(
        kvA, Wv2, bv, v2,
        hb, Wqb, bq, qb,
        Wkb, bk, kb,
        Wwqb, bwq, tq,
        tb, Wwkb, bwk, tk);

    // 3) masked-mean weights
    weights_kernel<<<B_ * H_, 256>>>(tq, tk, mask, w);

    // 4) tensor-core flash attention -> ctxA (hi|lo), 2 CTA/SM
    attn_tc_kernel<<<dim3(T_ / 128, B_ * H_), 256>>>(qb, kb, v2, w, ctxA);

    // 5) output projection
    gemm_out_kernel<<<dim3(8, (B_ * T_) / 128), 256, GEMM_SMEM_BYTES>>>(
        ctxA, Wo2, bo, out);
}

// round 14
// speedup vs baseline: 2.8673x; 1.0062x over previous
#include <cuda_runtime.h>
#include <cuda_bf16.h>
#include <cstdint>

// ============================================================================
// KTMutualAttention — consolidated-launch pipeline:
//   1 convert launch, 1 pre-attention GEMM mega-launch, weights,
//   cp.async double-buffered flash attention (2 CTA/SM), out-projection.
//   B=8, T=512, S=1024, TL=64, D=1024, H=16, hd=64
// ============================================================================

#define B_   8
#define T_   512
#define S_   1024
#define TL_  64
#define D_   1024
#define H_   16
#define HD_  64
#define SCALING_ 0.125f
#define K2_  2048

#define MODE_F32   0
#define MODE_BF16  1
#define MODE_SPLIT 2

// ---------------------------------------------------------------------------
// scratch (device globals)
// ---------------------------------------------------------------------------
__device__ __align__(256) float g_tq [B_ * S_ * D_];
__device__ __align__(256) float g_tk [B_ * TL_ * D_];
__device__ __align__(256) float g_w  [B_ * H_ * S_];

__device__ __align__(256) __nv_bfloat16 g_qb  [(size_t)B_ * T_ * D_];
__device__ __align__(256) __nv_bfloat16 g_kb  [(size_t)B_ * S_ * D_];
__device__ __align__(256) __nv_bfloat16 g_v2  [(size_t)B_ * S_ * K2_];

// dense bf16 (1-term operands)
__device__ __align__(256) __nv_bfloat16 g_hb  [(size_t)B_ * T_  * D_];
__device__ __align__(256) __nv_bfloat16 g_tb  [(size_t)B_ * TL_ * D_];
__device__ __align__(256) __nv_bfloat16 g_Wqb [(size_t)D_ * D_];
__device__ __align__(256) __nv_bfloat16 g_Wkb [(size_t)D_ * D_];
__device__ __align__(256) __nv_bfloat16 g_Wwqb[(size_t)D_ * D_];
__device__ __align__(256) __nv_bfloat16 g_Wwkb[(size_t)D_ * D_];

// hi|lo split (3-term operands)
__device__ __align__(256) __nv_bfloat16 g_kvA [(size_t)B_ * S_ * K2_];
__device__ __align__(256) __nv_bfloat16 g_ctxA[(size_t)B_ * T_ * K2_];
__device__ __align__(256) __nv_bfloat16 g_Wv2 [(size_t)D_ * K2_];
__device__ __align__(256) __nv_bfloat16 g_Wo2 [(size_t)D_ * K2_];

// ---------------------------------------------------------------------------
// PTX helpers (portable sm_80+)
// ---------------------------------------------------------------------------
__device__ __forceinline__ uint32_t smem_u32(const void* p) {
    uint32_t a;
    asm("{ .reg .u64 t; cvta.to.shared.u64 t, %1; cvt.u32.u64 %0, t; }"
        : "=r"(a) : "l"(p));
    return a;
}

#define CP_ASYNC16(dst_u32, src_ptr) \
    asm volatile("cp.async.cg.shared.global [%0], [%1], 16;" \
                 :: "r"(dst_u32), "l"(src_ptr) : "memory")
#define CP_COMMIT() asm volatile("cp.async.commit_group;" ::: "memory")
#define CP_WAIT2()  asm volatile("cp.async.wait_group 2;" ::: "memory")
#define CP_WAIT0()  asm volatile("cp.async.wait_group 0;" ::: "memory")

__device__ __forceinline__ void ldmatrix_x4(uint32_t& r0, uint32_t& r1,
                                            uint32_t& r2, uint32_t& r3,
                                            uint32_t addr)
{
    asm volatile("ldmatrix.sync.aligned.m8n8.x4.shared.b16 {%0,%1,%2,%3}, [%4];"
                 : "=r"(r0), "=r"(r1), "=r"(r2), "=r"(r3) : "r"(addr));
}

__device__ __forceinline__ void ldmatrix_x4_trans(uint32_t& r0, uint32_t& r1,
                                                  uint32_t& r2, uint32_t& r3,
                                                  uint32_t addr)
{
    asm volatile("ldmatrix.sync.aligned.m8n8.x4.trans.shared.b16 {%0,%1,%2,%3}, [%4];"
                 : "=r"(r0), "=r"(r1), "=r"(r2), "=r"(r3) : "r"(addr));
}

__device__ __forceinline__ void mma_bf16(float* c, uint32_t a0, uint32_t a1,
                                         uint32_t a2, uint32_t a3,
                                         uint32_t b0, uint32_t b1)
{
    asm volatile(
        "mma.sync.aligned.m16n8k16.row.col.f32.bf16.bf16.f32 "
        "{%0,%1,%2,%3}, {%4,%5,%6,%7}, {%8,%9}, {%0,%1,%2,%3};"
        : "+f"(c[0]), "+f"(c[1]), "+f"(c[2]), "+f"(c[3])
        : "r"(a0), "r"(a1), "r"(a2), "r"(a3), "r"(b0), "r"(b1));
}

__device__ __forceinline__ uint32_t pack_bf162(float x, float y)
{
    __nv_bfloat162 t = __floats2bfloat162_rn(x, y);
    return *reinterpret_cast<uint32_t*>(&t);
}

__device__ __forceinline__ void split_pair(float x, float y,
                                           uint32_t& hi, uint32_t& lo)
{
    __nv_bfloat16 hx = __float2bfloat16_rn(x);
    __nv_bfloat16 hy = __float2bfloat16_rn(y);
    __nv_bfloat162 th(hx, hy);
    hi = *reinterpret_cast<uint32_t*>(&th);
    __nv_bfloat162 tl(__float2bfloat16_rn(x - __bfloat162float(hx)),
                      __float2bfloat16_rn(y - __bfloat162float(hy)));
    lo = *reinterpret_cast<uint32_t*>(&tl);
}

// ---------------------------------------------------------------------------
// merged convert kernel: one block = one 1024-float row.
// ---------------------------------------------------------------------------
__global__ __launch_bounds__(256)
void convert_kernel(const float* __restrict__ hidden, __nv_bfloat16* __restrict__ hb,
                    const float* __restrict__ kv,     __nv_bfloat16* __restrict__ kvA,
                    const float* __restrict__ target, __nv_bfloat16* __restrict__ tb,
                    const float* __restrict__ Wq,  __nv_bfloat16* __restrict__ Wqb,
                    const float* __restrict__ Wk,  __nv_bfloat16* __restrict__ Wkb,
                    const float* __restrict__ Wwq, __nv_bfloat16* __restrict__ Wwqb,
                    const float* __restrict__ Wwk, __nv_bfloat16* __restrict__ Wwkb,
                    const float* __restrict__ Wv,  __nv_bfloat16* __restrict__ Wv2,
                    const float* __restrict__ Wo,  __nv_bfloat16* __restrict__ Wo2)
{
    const int x = blockIdx.x;
    const float* src;
    __nv_bfloat16* dst;
    int split, row;
    if (x < 4096)       { src = hidden; dst = hb;   split = 0; row = x; }
    else if (x < 12288) { src = kv;     dst = kvA;  split = 1; row = x - 4096; }
    else if (x < 12800) { src = target; dst = tb;   split = 0; row = x - 12288; }
    else if (x < 13824) { src = Wq;     dst = Wqb;  split = 0; row = x - 12800; }
    else if (x < 14848) { src = Wk;     dst = Wkb;  split = 0; row = x - 13824; }
    else if (x < 15872) { src = Wwq;    dst = Wwqb; split = 0; row = x - 14848; }
    else if (x < 16896) { src = Wwk;    dst = Wwkb; split = 0; row = x - 15872; }
    else if (x < 17920) { src = Wv;     dst = Wv2;  split = 1; row = x - 16896; }
    else                { src = Wo;     dst = Wo2;  split = 1; row = x - 17920; }

    const int c4 = threadIdx.x * 4;
    const float4 v = *reinterpret_cast<const float4*>(src + ((size_t)row << 10) + c4);

    uint32_t h0, l0, h1, l1;
    split_pair(v.x, v.y, h0, l0);
    split_pair(v.z, v.w, h1, l1);
    if (!split) {
        uint32_t* d = reinterpret_cast<uint32_t*>(dst + (size_t)row * D_ + c4);
        d[0] = h0; d[1] = h1;
    } else {
        uint32_t* dh = reinterpret_cast<uint32_t*>(dst + (size_t)row * K2_ + c4);
        dh[0] = h0; dh[1] = h1;
        uint32_t* dl = reinterpret_cast<uint32_t*>(dst + (size_t)row * K2_ + 1024 + c4);
        dl[0] = l0; dl[1] = l1;
    }
}

// ---------------------------------------------------------------------------
// GEMM core with per-operand strides (unchanged, validated)
// ---------------------------------------------------------------------------
#define BK 32
#define SROW 40
#define STAGES 4
#define STAGE_ELEMS (128 * SROW)
#define GEMM_SMEM_BYTES (STAGES * STAGE_ELEMS * 2 * 2)

__device__ __forceinline__
void gemm_core(const __nv_bfloat16* __restrict__ A, int astride,
               const __nv_bfloat16* __restrict__ W, int wstride,
               const float* __restrict__ bias,
               void* __restrict__ out, float scale, int mode, int nchunk,
               int bm, int bn, __nv_bfloat16* smem)
{
    __nv_bfloat16* sA = smem;
    __nv_bfloat16* sB = smem + STAGES * STAGE_ELEMS;
    __shared__ float biasS[128];

    const int tid = threadIdx.x;
    const int wid = tid >> 5, lane = tid & 31;
    const int wm = wid & 3;
    const int wn = wid >> 2;

    if (tid < 128) biasS[tid] = bias[bn + tid];

    const __nv_bfloat16* Ag = A + (size_t)bm * astride;
    const __nv_bfloat16* Wg = W + (size_t)bn * wstride;

    const int ldrow = tid >> 1;
    const int ldoff = (tid & 1) * 16;

    const uint32_t sAu = smem_u32(sA);
    const uint32_t sBu = smem_u32(sB);

    auto stage = [&](int c) {
        const int slot = c & (STAGES - 1);
        const int seg = c >> 5;
        const int col = (c & 31) * BK;
        const int aoff = (seg == 2) ? 1024 : 0;
        const int woff = (seg == 1) ? 1024 : 0;
        const size_t ga = (size_t)ldrow * astride + aoff + col + ldoff;
        const size_t gw = (size_t)ldrow * wstride + woff + col + ldoff;
        const uint32_t sa = sAu + (slot * STAGE_ELEMS + ldrow * SROW + ldoff) * 2;
        const uint32_t sb = sBu + (slot * STAGE_ELEMS + ldrow * SROW + ldoff) * 2;
        CP_ASYNC16(sa,      Ag + ga);
        CP_ASYNC16(sa + 16, Ag + ga + 8);
        CP_ASYNC16(sb,      Wg + gw);
        CP_ASYNC16(sb + 16, Wg + gw + 8);
    };

    float acc[2][8][4];
#pragma unroll
    for (int mt = 0; mt < 2; mt++)
#pragma unroll
        for (int nf = 0; nf < 8; nf++)
#pragma unroll
            for (int r = 0; r < 4; r++) acc[mt][nf][r] = 0.f;

    stage(0); CP_COMMIT();
    stage(1); CP_COMMIT();
    stage(2); CP_COMMIT();

    const int lrow = lane & 15;
    const int lcol = (lane >> 4) * 16;

    for (int c = 0; c < nchunk; ++c) {
        CP_WAIT2();
        __syncthreads();

        if (c + 3 < nchunk) { stage(c + 3); CP_COMMIT(); }
        else { CP_COMMIT(); }

        const int slot = c & (STAGES - 1);
        const uint32_t aBase = sAu + slot * STAGE_ELEMS * 2;
        const uint32_t bBase = sBu + slot * STAGE_ELEMS * 2;

#pragma unroll
        for (int kk = 0; kk < 2; kk++) {
            const int kbyte = kk * 32 + lcol;

            uint32_t a[2][4];
#pragma unroll
            for (int mt = 0; mt < 2; mt++) {
                const int row = wm * 32 + mt * 16 + lrow;
                ldmatrix_x4(a[mt][0], a[mt][1], a[mt][2], a[mt][3],
                            aBase + row * (SROW * 2) + kbyte);
            }
            uint32_t b[4][4];
#pragma unroll
            for (int nb = 0; nb < 4; nb++) {
                const int row = wn * 64 + nb * 16 + lrow;
                ldmatrix_x4(b[nb][0], b[nb][1], b[nb][2], b[nb][3],
                            bBase + row * (SROW * 2) + kbyte);
            }
#pragma unroll
            for (int mt = 0; mt < 2; mt++)
#pragma unroll
                for (int nf = 0; nf < 8; nf++) {
                    const int nb = nf >> 1;
                    const uint32_t b0 = (nf & 1) ? b[nb][1] : b[nb][0];
                    const uint32_t b1 = (nf & 1) ? b[nb][3] : b[nb][2];
                    mma_bf16(acc[mt][nf], a[mt][0], a[mt][1], a[mt][2], a[mt][3],
                             b0, b1);
                }
        }
    }

    const int g_  = lane >> 2;
    const int tig = lane & 3;
#pragma unroll
    for (int mt = 0; mt < 2; mt++) {
        const int row0 = bm + wm * 32 + mt * 16 + g_;
#pragma unroll
        for (int nf = 0; nf < 8; nf++) {
            const int lc  = wn * 64 + nf * 8 + tig * 2;
            const int col = bn + lc;
            const float b0 = biasS[lc], b1 = biasS[lc + 1];
            const float x0 = scale * (acc[mt][nf][0] + b0);
            const float x1 = scale * (acc[mt][nf][1] + b1);
            const float x2 = scale * (acc[mt][nf][2] + b0);
            const float x3 = scale * (acc[mt][nf][3] + b1);
            if (mode == MODE_F32) {
                float* C = (float*)out;
                *reinterpret_cast<float2*>(C + (size_t)row0 * 1024 + col)
                    = make_float2(x0, x1);
                *reinterpret_cast<float2*>(C + (size_t)(row0 + 8) * 1024 + col)
                    = make_float2(x2, x3);
            } else if (mode == MODE_BF16) {
                __nv_bfloat16* C = (__nv_bfloat16*)out;
                *reinterpret_cast<uint32_t*>(C + (size_t)row0 * 1024 + col)
                    = pack_bf162(x0, x1);
                *reinterpret_cast<uint32_t*>(C + (size_t)(row0 + 8) * 1024 + col)
                    = pack_bf162(x2, x3);
            } else {
                __nv_bfloat16* C = (__nv_bfloat16*)out;
                uint32_t h0, l0, h1, l1;
                split_pair(x0, x1, h0, l0);
                split_pair(x2, x3, h1, l1);
                *reinterpret_cast<uint32_t*>(C + (size_t)row0 * K2_ + col) = h0;
                *reinterpret_cast<uint32_t*>(C + (size_t)row0 * K2_ + 1024 + col) = l0;
                *reinterpret_cast<uint32_t*>(C + (size_t)(row0 + 8) * K2_ + col) = h1;
                *reinterpret_cast<uint32_t*>(C + (size_t)(row0 + 8) * K2_ + 1024 + col) = l1;
            }
        }
    }
}

// pre-attention GEMM mega-launch: v (512 heavy) first, then q/k/tq/tk light.
__global__ __launch_bounds__(256, 2)
void gemm_pre_kernel(const __nv_bfloat16* __restrict__ kvA,
                     const __nv_bfloat16* __restrict__ Wv2,
                     const float* __restrict__ bv,
                     __nv_bfloat16* __restrict__ v2,
                     const __nv_bfloat16* __restrict__ hb,
                     const __nv_bfloat16* __restrict__ Wqb,
                     const float* __restrict__ bq,
                     __nv_bfloat16* __restrict__ qb,
                     const __nv_bfloat16* __restrict__ Wkb,
                     const float* __restrict__ bk,
                     __nv_bfloat16* __restrict__ kb,
                     const __nv_bfloat16* __restrict__ Wwqb,
                     const float* __restrict__ bwq,
                     float* __restrict__ tq,
                     const __nv_bfloat16* __restrict__ tb,
                     const __nv_bfloat16* __restrict__ Wwkb,
                     const float* __restrict__ bwk,
                     float* __restrict__ tk)
{
    extern __shared__ __nv_bfloat16 smem[];
    const int x = blockIdx.x;
    if (x < 512) {
        gemm_core(kvA, K2_, Wv2, K2_, bv, v2, 1.0f, MODE_SPLIT, 96,
                  (x >> 3) * 128, (x & 7) * 128, smem);
    } else if (x < 768) {
        const int t = x - 512;
        gemm_core(hb, D_, Wqb, D_, bq, qb, SCALING_, MODE_BF16, 32,
                  (t >> 3) * 128, (t & 7) * 128, smem);
    } else if (x < 1280) {
        const int t = x - 768;
        gemm_core(kvA, K2_, Wkb, D_, bk, kb, 1.0f, MODE_BF16, 32,
                  (t >> 3) * 128, (t & 7) * 128, smem);
    } else if (x < 1792) {
        const int t = x - 1280;
        gemm_core(kvA, K2_, Wwqb, D_, bwq, tq, SCALING_, MODE_F32, 32,
                  (t >> 3) * 128, (t & 7) * 128, smem);
    } else {
        const int t = x - 1792;
        gemm_core(tb, D_, Wwkb, D_, bwk, tk, 1.0f, MODE_F32, 32,
                  (t >> 3) * 128, (t & 7) * 128, smem);
    }
}

// out projection: 3-term
__global__ __launch_bounds__(256, 2)
void gemm_out_kernel(const __nv_bfloat16* __restrict__ A,
                     const __nv_bfloat16* __restrict__ W,
                     const float* __restrict__ bias,
                     float* __restrict__ C)
{
    extern __shared__ __nv_bfloat16 smem[];
    gemm_core(A, K2_, W, K2_, bias, C, 1.0f, MODE_F32, 96,
              blockIdx.y * 128, blockIdx.x * 128, smem);
}

// ---------------------------------------------------------------------------
// weights[b,h,s] = (tq . (mask @ tk)) / sum(mask)
// ---------------------------------------------------------------------------
__global__ __launch_bounds__(256)
void weights_kernel(const float* __restrict__ tq, const float* __restrict__ tk,
                    const float* __restrict__ mask, float* __restrict__ wgt)
{
    const int bh = blockIdx.x;
    const int b = bh >> 4;
    const int h = bh & 15;

    __shared__ float tks[TL_][HD_];

    const int tid = threadIdx.x;
    for (int idx = tid; idx < TL_ * HD_; idx += 256) {
        const int t = idx >> 6, d = idx & 63;
        tks[t][d] = tk[((size_t)b * TL_ + t) * D_ + h * HD_ + d];
    }
    __syncthreads();

    const int warp = tid >> 5, lane = tid & 31;

    for (int s = warp; s < S_; s += 8) {
        const size_t tqo = ((size_t)b * S_ + s) * D_ + h * HD_;
        const float tq0 = __ldg(&tq[tqo + lane]);
        const float tq1 = __ldg(&tq[tqo + lane + 32]);
        const float* mrow = mask + ((size_t)b * S_ + s) * TL_;

        float mk0 = 0.f, mk1 = 0.f, cnt = 0.f;
#pragma unroll
        for (int t = 0; t < TL_; t++) {
            const float m = __ldg(&mrow[t]);
            cnt += m;
            mk0 = fmaf(m, tks[t][lane], mk0);
            mk1 = fmaf(m, tks[t][lane + 32], mk1);
        }
        float dotv = tq0 * mk0 + tq1 * mk1;
#pragma unroll
        for (int off = 16; off; off >>= 1)
            dotv += __shfl_xor_sync(0xffffffffu, dotv, off);

        if (lane == 0)
            wgt[(size_t)bh * S_ + s] = dotv / cnt;
    }
}

// ---------------------------------------------------------------------------
// fast exp on FMA pipe
// ---------------------------------------------------------------------------
__device__ __forceinline__ float fast_exp(float x)
{
    const float y = x * 1.44269504088896341f;
    const float n = rintf(y);
    const float t = (y - n) * 0.69314718055994531f;
    float p = 1.9841269841e-4f;
    p = fmaf(p, t, 1.38888888889e-3f);
    p = fmaf(p, t, 8.33333333333e-3f);
    p = fmaf(p, t, 4.16666666667e-2f);
    p = fmaf(p, t, 1.66666666667e-1f);
    p = fmaf(p, t, 0.5f);
    p = fmaf(p, t, 1.0f);
    p = fmaf(p, t, 1.0f);
    int e = (int)n;
    e = e < -126 ? -126 : e;
    const float s = __int_as_float((e + 127) << 23);
    return p * s;
}

// ---------------------------------------------------------------------------
// Tensor-core flash attention, cp.async double-buffered K/Vh/Vl.
//   Dynamic smem: sQ[128x72] | sK[2][64x72] | sVh[2] | sVl[2] | ws[1024]f
//   One __syncthreads per chunk; prefetch chunk c+1 overlaps compute of c.
// ---------------------------------------------------------------------------
#define VPAD 72
#define ATT_QELEMS   (128 * VPAD)
#define ATT_BUFELEMS (64 * VPAD)
#define ATT_SMEM_BYTES ((ATT_QELEMS + 6 * ATT_BUFELEMS) * 2 + 1024 * 4)

__global__ __launch_bounds__(256, 2)
void attn_tc_kernel(const __nv_bfloat16* __restrict__ qb,
                    const __nv_bfloat16* __restrict__ kb,
                    const __nv_bfloat16* __restrict__ v2,
                    const float* __restrict__ wgt,
                    __nv_bfloat16* __restrict__ ctxA)
{
    extern __shared__ __nv_bfloat16 asmem[];
    __nv_bfloat16* sQ  = asmem;
    __nv_bfloat16* sK  = asmem + ATT_QELEMS;                      // [2][...]
    __nv_bfloat16* sVh = sK  + 2 * ATT_BUFELEMS;
    __nv_bfloat16* sVl = sVh + 2 * ATT_BUFELEMS;
    float* wsAll = reinterpret_cast<float*>(sVl + 2 * ATT_BUFELEMS);

    const int qt = blockIdx.x, bh = blockIdx.y;
    const int bb = bh >> 4, h = bh & 15;
    const int tid = threadIdx.x, wid = tid >> 5, lane = tid & 31;
    const int g = lane >> 2, tig = lane & 3;
    const int lrow = lane & 15, lcolb = (lane >> 4) * 16;

    const int trow = ((lane >> 3) & 1) * 8 + (lane & 7);
    const int tcol = (lane >> 4) * 8;

    const uint32_t sQu  = smem_u32(sQ);
    const uint32_t sKu  = smem_u32(sK);
    const uint32_t sVhu = smem_u32(sVh);
    const uint32_t sVlu = smem_u32(sVl);
    const uint32_t wsu  = smem_u32(wsAll);
    const uint32_t BUFB = ATT_BUFELEMS * 2;   // bytes per buffer

    const float* wrow = wgt + (size_t)bh * S_;

    // prefetch chunk sc of K/Vh/Vl into buffer bsel (cp.async, 6 per thread)
    auto prefetch = [&](int sc, int bsel) {
        const size_t krow0 = (size_t)bb * S_ + sc * 64;
#pragma unroll
        for (int it = 0; it < 2; ++it) {
            const int idx = it * 256 + tid;
            const int r = idx >> 3, c8 = (idx & 7) * 8;
            const uint32_t soff = (uint32_t)(r * VPAD + c8) * 2 + bsel * BUFB;
            CP_ASYNC16(sKu  + soff, kb + (krow0 + r) * D_  + h * HD_ + c8);
            CP_ASYNC16(sVhu + soff, v2 + (krow0 + r) * K2_ + h * HD_ + c8);
            CP_ASYNC16(sVlu + soff, v2 + (krow0 + r) * K2_ + 1024 + h * HD_ + c8);
        }
    };

    // Q tile (128x64) + all 1024 weights + chunk 0, one cp.async group
    {
        const size_t qbase = ((size_t)bb * T_ + qt * 128) * D_ + h * HD_;
#pragma unroll
        for (int it = 0; it < 4; ++it) {
            const int idx = it * 256 + tid;
            const int r = idx >> 3, c8 = (idx & 7) * 8;
            CP_ASYNC16(sQu + (uint32_t)(r * VPAD + c8) * 2,
                       qb + qbase + (size_t)r * D_ + c8);
        }
        CP_ASYNC16(wsu + tid * 16, wrow + tid * 4);
        prefetch(0, 0);
        CP_COMMIT();
    }

    float o[8][4];
#pragma unroll
    for (int nf = 0; nf < 8; nf++)
#pragma unroll
        for (int r = 0; r < 4; r++) o[nf][r] = 0.f;
    float m0 = -1e30f, m1 = -1e30f, l0 = 0.f, l1 = 0.f;

    for (int sc = 0; sc < S_ / 64; ++sc) {
        CP_WAIT0();
        __syncthreads();   // chunk sc visible; all warps done reading buf (sc+1)&1

        if (sc + 1 < S_ / 64) { prefetch(sc + 1, (sc + 1) & 1); CP_COMMIT(); }

        const uint32_t kBase  = sKu  + (sc & 1) * BUFB;
        const uint32_t vhBase = sVhu + (sc & 1) * BUFB;
        const uint32_t vlBase = sVlu + (sc & 1) * BUFB;

        // ---- S = Q @ K^T
        float sv[8][4];
#pragma unroll
        for (int nf = 0; nf < 8; nf++)
#pragma unroll
            for (int r = 0; r < 4; r++) sv[nf][r] = 0.f;

#pragma unroll
        for (int kk = 0; kk < 4; kk++) {
            const int kb_ = kk * 32 + lcolb;
            uint32_t a0, a1, a2, a3;
            ldmatrix_x4(a0, a1, a2, a3,
                        sQu + (wid * 16 + lrow) * (VPAD * 2) + kb_);
#pragma unroll
            for (int nb = 0; nb < 4; nb++) {
                uint32_t b0, b1, b2, b3;
                ldmatrix_x4(b0, b1, b2, b3,
                            kBase + (nb * 16 + lrow) * (VPAD * 2) + kb_);
                mma_bf16(sv[2 * nb],     a0, a1, a2, a3, b0, b2);
                mma_bf16(sv[2 * nb + 1], a0, a1, a2, a3, b1, b3);
            }
        }

        // ---- per-key-column weight scaling (from persistent table)
#pragma unroll
        for (int nf = 0; nf < 8; nf++) {
            const int col = sc * 64 + nf * 8 + tig * 2;
            const float w0 = wsAll[col], w1 = wsAll[col + 1];
            sv[nf][0] *= w0; sv[nf][1] *= w1;
            sv[nf][2] *= w0; sv[nf][3] *= w1;
        }

        // ---- online softmax
        float mx0 = -1e30f, mx1 = -1e30f;
#pragma unroll
        for (int nf = 0; nf < 8; nf++) {
            mx0 = fmaxf(mx0, fmaxf(sv[nf][0], sv[nf][1]));
            mx1 = fmaxf(mx1, fmaxf(sv[nf][2], sv[nf][3]));
        }
        mx0 = fmaxf(mx0, __shfl_xor_sync(0xffffffffu, mx0, 1));
        mx0 = fmaxf(mx0, __shfl_xor_sync(0xffffffffu, mx0, 2));
        mx1 = fmaxf(mx1, __shfl_xor_sync(0xffffffffu, mx1, 1));
        mx1 = fmaxf(mx1, __shfl_xor_sync(0xffffffffu, mx1, 2));

        const float mn0 = fmaxf(m0, mx0), mn1 = fmaxf(m1, mx1);
        const float al0 = fast_exp(m0 - mn0), al1 = fast_exp(m1 - mn1);
        m0 = mn0; m1 = mn1;

        float s0 = 0.f, s1 = 0.f;
#pragma unroll
        for (int nf = 0; nf < 8; nf++) {
            sv[nf][0] = fast_exp(sv[nf][0] - mn0);
            sv[nf][1] = fast_exp(sv[nf][1] - mn0);
            sv[nf][2] = fast_exp(sv[nf][2] - mn1);
            sv[nf][3] = fast_exp(sv[nf][3] - mn1);
            s0 += sv[nf][0] + sv[nf][1];
            s1 += sv[nf][2] + sv[nf][3];
        }
        s0 += __shfl_xor_sync(0xffffffffu, s0, 1);
        s0 += __shfl_xor_sync(0xffffffffu, s0, 2);
        s1 += __shfl_xor_sync(0xffffffffu, s1, 1);
        s1 += __shfl_xor_sync(0xffffffffu, s1, 2);
        l0 = l0 * al0 + s0;
        l1 = l1 * al1 + s1;

#pragma unroll
        for (int nf = 0; nf < 8; nf++) {
            o[nf][0] *= al0; o[nf][1] *= al0;
            o[nf][2] *= al1; o[nf][3] *= al1;
        }

        // ---- O += P @ V  (3-term hi/lo; V row-major + ldmatrix.trans)
#pragma unroll
        for (int j = 0; j < 4; j++) {
            uint32_t ph[4], pl[4];
            split_pair(sv[2 * j][0],     sv[2 * j][1],     ph[0], pl[0]);
            split_pair(sv[2 * j][2],     sv[2 * j][3],     ph[1], pl[1]);
            split_pair(sv[2 * j + 1][0], sv[2 * j + 1][1], ph[2], pl[2]);
            split_pair(sv[2 * j + 1][2], sv[2 * j + 1][3], ph[3], pl[3]);

            const uint32_t vrow = (j * 16 + trow) * (VPAD * 2);
#pragma unroll
            for (int nb = 0; nb < 4; nb++) {
                const uint32_t vaddr = vrow + (nb * 16 + tcol) * 2;
                uint32_t h0, h1, h2, h3, q0, q1, q2, q3;
                ldmatrix_x4_trans(h0, h1, h2, h3, vhBase + vaddr);
                ldmatrix_x4_trans(q0, q1, q2, q3, vlBase + vaddr);
                mma_bf16(o[2 * nb],     ph[0], ph[1], ph[2], ph[3], h0, h1);
                mma_bf16(o[2 * nb + 1], ph[0], ph[1], ph[2], ph[3], h2, h3);
                mma_bf16(o[2 * nb],     ph[0], ph[1], ph[2], ph[3], q0, q1);
                mma_bf16(o[2 * nb + 1], ph[0], ph[1], ph[2], ph[3], q2, q3);
                mma_bf16(o[2 * nb],     pl[0], pl[1], pl[2], pl[3], h0, h1);
                mma_bf16(o[2 * nb + 1], pl[0], pl[1], pl[2], pl[3], h2, h3);
            }
        }
    }

    const float inv0 = 1.0f / l0, inv1 = 1.0f / l1;
    const int row0 = qt * 128 + wid * 16 + g;
#pragma unroll
    for (int nf = 0; nf < 8; nf++) {
        const int col = h * HD_ + nf * 8 + tig * 2;
        uint32_t h0, l0w, h1, l1w;
        split_pair(o[nf][0] * inv0, o[nf][1] * inv0, h0, l0w);
        split_pair(o[nf][2] * inv1, o[nf][3] * inv1, h1, l1w);
        const size_t r0 = ((size_t)bb * T_ + row0) * K2_;
        const size_t r1 = ((size_t)bb * T_ + row0 + 8) * K2_;
        *reinterpret_cast<uint32_t*>(ctxA + r0 + col)        = h0;
        *reinterpret_cast<uint32_t*>(ctxA + r0 + 1024 + col) = l0w;
        *reinterpret_cast<uint32_t*>(ctxA + r1 + col)        = h1;
        *reinterpret_cast<uint32_t*>(ctxA + r1 + 1024 + col) = l1w;
    }
}

// ---------------------------------------------------------------------------
// launch
// ---------------------------------------------------------------------------
extern "C" void kernel_launch(void* const* d_in, const int* in_sizes, int n_in,
                              void* d_out, int out_size)
{
    const float* hidden = (const float*)d_in[0];
    const float* kv     = (const float*)d_in[1];
    const float* target = (const float*)d_in[2];
    const float* mask   = (const float*)d_in[3];
    const float* Wq  = (const float*)d_in[4];
    const float* bq  = (const float*)d_in[5];
    const float* Wk  = (const float*)d_in[6];
    const float* bk  = (const float*)d_in[7];
    const float* Wv  = (const float*)d_in[8];
    const float* bv  = (const float*)d_in[9];
    const float* Wwq = (const float*)d_in[10];
    const float* bwq = (const float*)d_in[11];
    const float* Wwk = (const float*)d_in[12];
    const float* bwk = (const float*)d_in[13];
    const float* Wo  = (const float*)d_in[14];
    const float* bo  = (const float*)d_in[15];
    float* out = (float*)d_out;

    float *tq, *tk, *w;
    cudaGetSymbolAddress((void**)&tq,  g_tq);
    cudaGetSymbolAddress((void**)&tk,  g_tk);
    cudaGetSymbolAddress((void**)&w,   g_w);

    __nv_bfloat16 *qb, *kb, *v2, *hb, *tb, *Wqb, *Wkb, *Wwqb, *Wwkb;
    cudaGetSymbolAddress((void**)&qb,   g_qb);
    cudaGetSymbolAddress((void**)&kb,   g_kb);
    cudaGetSymbolAddress((void**)&v2,   g_v2);
    cudaGetSymbolAddress((void**)&hb,   g_hb);
    cudaGetSymbolAddress((void**)&tb,   g_tb);
    cudaGetSymbolAddress((void**)&Wqb,  g_Wqb);
    cudaGetSymbolAddress((void**)&Wkb,  g_Wkb);
    cudaGetSymbolAddress((void**)&Wwqb, g_Wwqb);
    cudaGetSymbolAddress((void**)&Wwkb, g_Wwkb);

    __nv_bfloat16 *kvA, *ctxA, *Wv2, *Wo2;
    cudaGetSymbolAddress((void**)&kvA,  g_kvA);
    cudaGetSymbolAddress((void**)&ctxA, g_ctxA);
    cudaGetSymbolAddress((void**)&Wv2,  g_Wv2);
    cudaGetSymbolAddress((void**)&Wo2,  g_Wo2);

    cudaFuncSetAttribute(gemm_pre_kernel,
                         cudaFuncAttributeMaxDynamicSharedMemorySize, GEMM_SMEM_BYTES);
    cudaFuncSetAttribute(gemm_out_kernel,
                         cudaFuncAttributeMaxDynamicSharedMemorySize, GEMM_SMEM_BYTES);
    cudaFuncSetAttribute(attn_tc_kernel,
                         cudaFuncAttributeMaxDynamicSharedMemorySize, ATT_SMEM_BYTES);

    // 1) all conversions (one launch)
    convert_kernel<<<18944, 256>>>(hidden, hb, kv, kvA, target, tb,
                                   Wq, Wqb, Wk, Wkb, Wwq, Wwqb, Wwk, Wwkb,
                                   Wv, Wv2, Wo, Wo2);

    // 2) all pre-attention projections (one launch, heavy-first)
    gemm_pre_kernel<<<1824, 256, GEMM_SMEM_BYTES>>>(
        kvA, Wv2, bv, v2,
        hb, Wqb, bq, qb,
        Wkb, bk, kb,
        Wwqb, bwq, tq,
        tb, Wwkb, bwk, tk);

    // 3) masked-mean weights
    weights_kernel<<<B_ * H_, 256>>>(tq, tk, mask, w);

    // 4) cp.async double-buffered flash attention -> ctxA (hi|lo)
    attn_tc_kernel<<<dim3(T_ / 128, B_ * H_), 256, ATT_SMEM_BYTES>>>(
        qb, kb, v2, w, ctxA);

    // 5) output projection
    gemm_out_kernel<<<dim3(8, (B_ * T_) / 128), 256, GEMM_SMEM_BYTES>>>(
        ctxA, Wo2, bo, out);
}